// round 2
// baseline (speedup 1.0000x reference)
#include <cuda_runtime.h>
#include <mma.h>
#include <math.h>

using namespace nvcuda;

#define TSTEPS 31

// ---------------- scratch ----------------
__device__ float g_W0[768 * 2048];           // [k][n'] gate-interleaved: n' = d*4+g
__device__ float g_W1[1024 * 2048];
__device__ float g_b0[2048];
__device__ float g_b1[2048];
__device__ float g_convWT[512 * 9 * 256];    // [c][tap][attn]
__device__ float g_elwT[512 * 256];          // [k][attn]
__device__ float g_fcT[1024 * 98];           // [k][class]
__device__ float g_fmapT[64 * 256 * 512];    // [b][hw][c]
__device__ float g_efmap[64 * 256 * 256];    // [b][attn][hw]  (no bias)
__device__ float g_xh0[2][64 * 768];         // [b][emb|h0prev]
__device__ float g_xh1[2][64 * 1024];        // [b][h0cur|h1prev]
__device__ float g_c0s[64 * 512];
__device__ float g_c1s[64 * 512];

__device__ __forceinline__ float tanh_fast(float x) {
    float y; asm("tanh.approx.f32 %0, %1;" : "=f"(y) : "f"(x)); return y;
}
__device__ __forceinline__ float sig_acc(float x) { return 1.0f / (1.0f + expf(-x)); }

template <class F>
__device__ __forceinline__ void frag_tf32(F& f) {
#pragma unroll
    for (int i = 0; i < f.num_elements; i++) f.x[i] = wmma::__float_to_tf32(f.x[i]);
}

// ---------------- setup ----------------
__global__ void k_transpose(const float* __restrict__ Wih0, const float* __restrict__ Whh0,
                            const float* __restrict__ Wih1, const float* __restrict__ Whh1,
                            const float* __restrict__ efw, const float* __restrict__ elw,
                            const float* __restrict__ fcw, const float* __restrict__ fmap,
                            const float* __restrict__ bih0, const float* __restrict__ bhh0,
                            const float* __restrict__ bih1, const float* __restrict__ bhh1) {
    const int y = blockIdx.y;
    const int stride = gridDim.x * blockDim.x;
    const int i0 = blockIdx.x * blockDim.x + threadIdx.x;
    if (y == 0) {
        for (int i = i0; i < 768 * 2048; i += stride) {
            int k = i >> 11, n = i & 2047;
            int col = (n & 3) * 512 + (n >> 2);
            g_W0[i] = (k < 256) ? Wih0[col * 256 + k] : Whh0[col * 512 + (k - 256)];
        }
    } else if (y == 1) {
        for (int i = i0; i < 1024 * 2048; i += stride) {
            int k = i >> 11, n = i & 2047;
            int col = (n & 3) * 512 + (n >> 2);
            g_W1[i] = (k < 512) ? Wih1[col * 512 + k] : Whh1[col * 512 + (k - 512)];
        }
    } else if (y == 2) {
        for (int i = i0; i < 4608 * 256; i += stride) {
            int ck = i >> 8, a = i & 255;
            g_convWT[i] = efw[a * 4608 + ck];
        }
    } else if (y == 3) {
        for (int i = i0; i < 512 * 256; i += stride) {
            int k = i >> 8, a = i & 255;
            g_elwT[i] = elw[a * 512 + k];
        }
    } else if (y == 4) {
        for (int i = i0; i < 1024 * 98; i += stride) {
            int k = i / 98, j = i % 98;
            g_fcT[i] = fcw[j * 1024 + k];
        }
        for (int i = i0; i < 2048; i += stride) {
            int col = (i & 3) * 512 + (i >> 2);
            g_b0[i] = bih0[col] + bhh0[col];
            g_b1[i] = bih1[col] + bhh1[col];
        }
    } else {
        for (int i = i0; i < 64 * 256 * 512; i += stride) {
            int b = i >> 17, rem = i & 131071;
            int hw = rem >> 9, c = rem & 511;
            g_fmapT[i] = fmap[b * 131072 + c * 256 + hw];
        }
    }
}

__global__ void k_init(const float* __restrict__ h0, const float* __restrict__ c0,
                       const float* __restrict__ emb) {
    int idx = blockIdx.x * blockDim.x + threadIdx.x;
    const int S0 = 64 * 768, S1 = S0 + 64 * 512, S2 = S1 + 64 * 512, S3 = S2 + 64 * 512;
    if (idx < S0) {
        int b = idx / 768, k = idx % 768;
        g_xh0[0][idx] = (k < 256) ? emb[k] : h0[b * 512 + (k - 256)];
    } else if (idx < S1) {
        int r = idx - S0; int b = r >> 9, d = r & 511;
        g_xh1[0][b * 1024 + 512 + d] = h0[32768 + b * 512 + d];
    } else if (idx < S2) {
        g_c0s[idx - S1] = c0[idx - S1];
    } else if (idx < S3) {
        g_c1s[idx - S2] = c0[32768 + (idx - S2)];
    }
}

// ---------------- conv: tf32 implicit GEMM ----------------
// block: b = blockIdx.y, N-tile 128 attn (blockIdx.x), M = 256 spatial. 512 threads.
__global__ __launch_bounds__(512) void k_conv(const float* __restrict__ fmap) {
    __shared__ float xs[10 * 34 * 8];     // rows -1..8, cols -1..32, 8 ch (ch minor)
    __shared__ float ws[9 * 8 * 128];     // [tap][c][n]
    const int b = blockIdx.y;
    const int n0 = blockIdx.x * 128;
    const int tid = threadIdx.x;
    const int warp = tid >> 5;
    const int wm = warp >> 1;             // 0..7 -> m-tiles {2wm, 2wm+1}
    const int wn = warp & 1;              // 0..1 -> n range wn*64, 4 frags

    wmma::fragment<wmma::accumulator, 16, 16, 8, float> acc[2][4];
#pragma unroll
    for (int i = 0; i < 2; i++)
#pragma unroll
        for (int j = 0; j < 4; j++) wmma::fill_fragment(acc[i][j], 0.0f);

    const float* fb = fmap + b * 131072;
    for (int cc = 0; cc < 512; cc += 8) {
        for (int i = tid; i < 2720; i += 512) {
            int c = i / 340, rem = i % 340, r = rem / 34, w = rem % 34;
            int ir = r - 1, iw = w - 1;
            float v = (ir >= 0 && ir < 8 && iw >= 0 && iw < 32)
                          ? fb[(cc + c) * 256 + ir * 32 + iw] : 0.0f;
            xs[(r * 34 + w) * 8 + c] = v;
        }
        for (int i = tid; i < 9216; i += 512) {
            int n = i & 127, rc = i >> 7;
            int c = rc & 7, tap = rc >> 3;
            ws[i] = g_convWT[((cc + c) * 9 + tap) * 256 + n0 + n];
        }
        __syncthreads();
#pragma unroll
        for (int tap = 0; tap < 9; tap++) {
            const int dy = tap / 3, dx = tap % 3;
            wmma::fragment<wmma::matrix_a, 16, 16, 8, wmma::precision::tf32, wmma::row_major> af[2];
#pragma unroll
            for (int i = 0; i < 2; i++) {
                int mt = wm * 2 + i;
                int row = mt >> 1, wseg = (mt & 1) * 16;
                wmma::load_matrix_sync(af[i], &xs[((row + dy) * 34 + wseg + dx) * 8], 8);
                frag_tf32(af[i]);
            }
#pragma unroll
            for (int j = 0; j < 4; j++) {
                wmma::fragment<wmma::matrix_b, 16, 16, 8, wmma::precision::tf32, wmma::row_major> bf;
                wmma::load_matrix_sync(bf, &ws[(tap * 8) * 128 + wn * 64 + j * 16], 128);
                frag_tf32(bf);
#pragma unroll
                for (int i = 0; i < 2; i++)
                    wmma::mma_sync(acc[i][j], af[i], bf, acc[i][j]);
            }
        }
        __syncthreads();
    }
    float* eb = g_efmap + b * 65536;
#pragma unroll
    for (int i = 0; i < 2; i++) {
        int mt = wm * 2 + i, m0 = mt * 16;
#pragma unroll
        for (int j = 0; j < 4; j++) {
            int n = n0 + wn * 64 + j * 16;
            wmma::store_matrix_sync(eb + n * 256 + m0, acc[i][j], 256, wmma::mem_col_major);
        }
    }
}

// ---------------- step GEMM (tf32) + fused LSTM pointwise ----------------
// M=64 batch, N=128 gate-interleaved cols per block (16 blocks), K=768/1024.
__global__ __launch_bounds__(256) void k_gemm(int which, int t) {
    __shared__ float smem[8192];          // union: As[64][36]+Bs[32][128] | Cs[64][128]
    float* As = smem;
    float* Bs = smem + 2304;
    const int tid = threadIdx.x;
    const int warp = tid >> 5;
    const int wm = warp >> 2, wn = warp & 3;
    const int n0 = blockIdx.x * 128;
    const int tc = t & 1, tp = (t + 1) & 1;

    const float* A; const float* W; const float* bias; float* cs; int K;
    if (which == 0) { A = g_xh0[tc]; W = g_W0; bias = g_b0; cs = g_c0s; K = 768; }
    else            { A = g_xh1[tc]; W = g_W1; bias = g_b1; cs = g_c1s; K = 1024; }

    wmma::fragment<wmma::accumulator, 16, 16, 8, float> acc[2][2];
#pragma unroll
    for (int i = 0; i < 2; i++)
#pragma unroll
        for (int j = 0; j < 2; j++) wmma::fill_fragment(acc[i][j], 0.0f);

    for (int kt = 0; kt < K; kt += 32) {
        for (int i = tid; i < 2048; i += 256) {
            int m = i >> 5, k = i & 31;
            As[m * 36 + k] = A[m * K + kt + k];
        }
        for (int i = tid; i < 4096; i += 256) {
            int k = i >> 7, n = i & 127;
            Bs[k * 128 + n] = W[(kt + k) * 2048 + n0 + n];
        }
        __syncthreads();
#pragma unroll
        for (int kf = 0; kf < 4; kf++) {
            wmma::fragment<wmma::matrix_a, 16, 16, 8, wmma::precision::tf32, wmma::row_major> af[2];
            wmma::fragment<wmma::matrix_b, 16, 16, 8, wmma::precision::tf32, wmma::row_major> bf[2];
#pragma unroll
            for (int i = 0; i < 2; i++) {
                wmma::load_matrix_sync(af[i], &As[(wm * 32 + i * 16) * 36 + kf * 8], 36);
                frag_tf32(af[i]);
            }
#pragma unroll
            for (int j = 0; j < 2; j++) {
                wmma::load_matrix_sync(bf[j], &Bs[kf * 8 * 128 + wn * 32 + j * 16], 128);
                frag_tf32(bf[j]);
            }
#pragma unroll
            for (int i = 0; i < 2; i++)
#pragma unroll
                for (int j = 0; j < 2; j++)
                    wmma::mma_sync(acc[i][j], af[i], bf[j], acc[i][j]);
        }
        __syncthreads();
    }
    float* Cs = smem;
#pragma unroll
    for (int i = 0; i < 2; i++)
#pragma unroll
        for (int j = 0; j < 2; j++)
            wmma::store_matrix_sync(&Cs[(wm * 32 + i * 16) * 128 + wn * 32 + j * 16],
                                    acc[i][j], 128, wmma::mem_row_major);
    __syncthreads();

    const int d0 = blockIdx.x * 32;
#pragma unroll
    for (int it = 0; it < 8; it++) {
        int p = it * 256 + tid;
        int b = p >> 5, dl = p & 31;
        int d = d0 + dl;
        int nb = n0 + dl * 4;
        float gi = Cs[b * 128 + dl * 4 + 0] + bias[nb + 0];
        float gf = Cs[b * 128 + dl * 4 + 1] + bias[nb + 1];
        float gg = Cs[b * 128 + dl * 4 + 2] + bias[nb + 2];
        float go = Cs[b * 128 + dl * 4 + 3] + bias[nb + 3];
        float c = cs[b * 512 + d];
        c = sig_acc(gf) * c + sig_acc(gi) * tanhf(gg);
        float h = sig_acc(go) * tanhf(c);
        cs[b * 512 + d] = c;
        if (which == 0) {
            g_xh1[tc][b * 1024 + d] = h;           // LSTM1 input this step
            g_xh0[tp][b * 768 + 256 + d] = h;      // recurrent input next step
        } else {
            g_xh1[tp][b * 1024 + 512 + d] = h;     // h1 for next step + attn
        }
    }
}

// ---------------- fused attention + glimpse + fc ----------------
__global__ __launch_bounds__(256) void k_attn(const float* __restrict__ elb, const float* __restrict__ efb,
                                              const float* __restrict__ aw, const float* __restrict__ ab,
                                              const float* __restrict__ fcb, const int* __restrict__ target,
                                              const float* __restrict__ emb, float* __restrict__ out, int t) {
    const int b = blockIdx.x;
    const int tid = threadIdx.x;
    __shared__ float hs[512], ehs[256], aws[256], ps[256], gs[512];
    __shared__ float red[8], red2[8], fin[2];
    __shared__ float facc[2][98];

    const float* h1 = g_xh1[(t + 1) & 1] + b * 1024 + 512;
    hs[tid] = h1[tid];
    hs[tid + 256] = h1[tid + 256];
    aws[tid] = aw[tid];
    __syncthreads();

    // e_h = h1 @ elw^T + elb + efb (conv bias folded here)
    {
        float acc = elb[tid] + efb[tid];
        const float* w = g_elwT + tid;
#pragma unroll 8
        for (int k = 0; k < 512; k++) acc += hs[k] * w[k * 256];
        ehs[tid] = acc;
    }
    __syncthreads();

    float sc = ab[0];
    {
        const float* ef = g_efmap + b * 65536 + tid;
#pragma unroll 4
        for (int a = 0; a < 256; a++) sc += aws[a] * tanh_fast(ehs[a] + ef[a * 256]);
    }
    const int warp = tid >> 5, lane = tid & 31;
    float m = sc;
#pragma unroll
    for (int o = 16; o; o >>= 1) m = fmaxf(m, __shfl_xor_sync(0xffffffffu, m, o));
    if (lane == 0) red[warp] = m;
    __syncthreads();
    if (tid == 0) {
        float v = red[0];
#pragma unroll
        for (int i = 1; i < 8; i++) v = fmaxf(v, red[i]);
        fin[0] = v;
    }
    __syncthreads();
    float e = expf(sc - fin[0]);
    float s = e;
#pragma unroll
    for (int o = 16; o; o >>= 1) s += __shfl_xor_sync(0xffffffffu, s, o);
    if (lane == 0) red2[warp] = s;
    __syncthreads();
    if (tid == 0) {
        float v = 0;
#pragma unroll
        for (int i = 0; i < 8; i++) v += red2[i];
        fin[1] = v;
    }
    __syncthreads();
    float p = e / fin[1];
    ps[tid] = p;
    out[194432 + (b * 31 + t) * 256 + tid] = p;    // masks
    __syncthreads();

#pragma unroll
    for (int r = 0; r < 2; r++) {
        int c = tid + r * 256;
        float g = 0;
        const float* ft = g_fmapT + b * 131072 + c;
#pragma unroll 8
        for (int hw = 0; hw < 256; hw++) g += ft[hw * 512] * ps[hw];
        gs[c] = g;
        out[702336 + (b * 31 + t) * 512 + c] = g;  // glimpses
    }
    __syncthreads();

    if (tid < 196) {
        int half = (tid >= 98) ? 1 : 0;
        int j = tid - half * 98;
        const float* src = half ? gs : hs;
        const float* w = g_fcT + half * (512 * 98) + j;
        float acc = 0;
#pragma unroll 8
        for (int k = 0; k < 512; k++) acc += src[k] * w[k * 98];
        facc[half][j] = acc;
    }
    // next-step embedding
    if (t < 30) {
        int lab = target[b * 30 + t];
        g_xh0[(t + 1) & 1][b * 768 + tid] = emb[lab * 256 + tid];
    }
    __syncthreads();
    if (tid < 98)
        out[(b * 31 + t) * 98 + tid] = facc[0][tid] + facc[1][tid] + fcb[tid];  // logits
}

// ---------------- launch ----------------
extern "C" void kernel_launch(void* const* d_in, const int* in_sizes, int n_in,
                              void* d_out, int out_size) {
    const float* fmap   = (const float*)d_in[0];
    const float* h0     = (const float*)d_in[1];
    const float* c0     = (const float*)d_in[2];
    const int*   target = (const int*)d_in[3];
    const float* emb    = (const float*)d_in[5];
    const float* Wih0   = (const float*)d_in[6];
    const float* Whh0   = (const float*)d_in[7];
    const float* bih0   = (const float*)d_in[8];
    const float* bhh0   = (const float*)d_in[9];
    const float* Wih1   = (const float*)d_in[10];
    const float* Whh1   = (const float*)d_in[11];
    const float* bih1   = (const float*)d_in[12];
    const float* bhh1   = (const float*)d_in[13];
    const float* elw    = (const float*)d_in[14];
    const float* elb    = (const float*)d_in[15];
    const float* efw    = (const float*)d_in[16];
    const float* efb    = (const float*)d_in[17];
    const float* aw     = (const float*)d_in[18];
    const float* ab     = (const float*)d_in[19];
    const float* fcw    = (const float*)d_in[20];
    const float* fcb    = (const float*)d_in[21];
    float* out = (float*)d_out;

    k_transpose<<<dim3(512, 6), 256>>>(Wih0, Whh0, Wih1, Whh1, efw, elw, fcw, fmap,
                                       bih0, bhh0, bih1, bhh1);
    k_conv<<<dim3(2, 64), 512>>>(fmap);
    k_init<<<(64 * 2304 + 255) / 256, 256>>>(h0, c0, emb);
    for (int t = 0; t < TSTEPS; t++) {
        k_gemm<<<16, 256>>>(0, t);
        k_gemm<<<16, 256>>>(1, t);
        k_attn<<<64, 256>>>(elb, efb, aw, ab, fcb, target, emb, out, t);
    }
}

// round 3
// speedup vs baseline: 2.2277x; 2.2277x over previous
#include <cuda_runtime.h>
#include <mma.h>
#include <math.h>

using namespace nvcuda;

#define TSTEPS 31
#define GBLK 128

// ---------------- scratch ----------------
__device__ float g_W0[768 * 2048];           // [k][n]  n = gate*512+d (PyTorch row)
__device__ float g_W1[1024 * 2048];
__device__ float g_b0[2048];
__device__ float g_b1[2048];
__device__ float g_convWT[512 * 9 * 256];    // [c][tap][attn]
__device__ float g_elwT[512 * 256];          // [k][attn]
__device__ float g_fcT[1024 * 98];           // [k][class]
__device__ float g_fmapT[64 * 256 * 512];    // [b][hw][c]
__device__ float g_efmap[64 * 256 * 256];    // [b][attn][hw]  (no bias)
__device__ float g_xh0[2][64 * 768];         // [b][emb|h0prev]
__device__ float g_xh1[2][64 * 1024];        // [b][h0cur|h1prev]
__device__ float g_c0s[64 * 512];
__device__ float g_c1s[64 * 512];
__device__ float g_part[8 * 64 * 2048];      // K-split partials
__device__ unsigned g_barc = 0;
__device__ volatile unsigned g_barg = 0;

__device__ __forceinline__ float tanh_fast(float x) {
    float y; asm("tanh.approx.f32 %0, %1;" : "=f"(y) : "f"(x)); return y;
}
__device__ __forceinline__ float sig_acc(float x) { return 1.0f / (1.0f + expf(-x)); }

template <class F>
__device__ __forceinline__ void frag_tf32(F& f) {
#pragma unroll
    for (int i = 0; i < f.num_elements; i++) f.x[i] = wmma::__float_to_tf32(f.x[i]);
}

// grid-wide barrier (all GBLK blocks resident: 1 block/SM by smem)
__device__ __forceinline__ void gsync() {
    __syncthreads();
    if (threadIdx.x == 0) {
        __threadfence();
        unsigned gen = g_barg;
        if (atomicAdd(&g_barc, 1u) == GBLK - 1u) {
            g_barc = 0;
            __threadfence();
            g_barg = gen + 1u;
        } else {
            while (g_barg == gen) { }
            __threadfence();
        }
    }
    __syncthreads();
}

// ---------------- setup ----------------
__global__ void k_transpose(const float* __restrict__ Wih0, const float* __restrict__ Whh0,
                            const float* __restrict__ Wih1, const float* __restrict__ Whh1,
                            const float* __restrict__ efw, const float* __restrict__ elw,
                            const float* __restrict__ fcw, const float* __restrict__ fmap,
                            const float* __restrict__ bih0, const float* __restrict__ bhh0,
                            const float* __restrict__ bih1, const float* __restrict__ bhh1) {
    const int y = blockIdx.y;
    const int stride = gridDim.x * blockDim.x;
    const int i0 = blockIdx.x * blockDim.x + threadIdx.x;
    if (y == 0) {
        for (int i = i0; i < 768 * 2048; i += stride) {
            int k = i >> 11, n = i & 2047;
            g_W0[i] = (k < 256) ? Wih0[n * 256 + k] : Whh0[n * 512 + (k - 256)];
        }
    } else if (y == 1) {
        for (int i = i0; i < 1024 * 2048; i += stride) {
            int k = i >> 11, n = i & 2047;
            g_W1[i] = (k < 512) ? Wih1[n * 512 + k] : Whh1[n * 512 + (k - 512)];
        }
    } else if (y == 2) {
        for (int i = i0; i < 4608 * 256; i += stride) {
            int ck = i >> 8, a = i & 255;
            g_convWT[i] = efw[a * 4608 + ck];
        }
    } else if (y == 3) {
        for (int i = i0; i < 512 * 256; i += stride) {
            int k = i >> 8, a = i & 255;
            g_elwT[i] = elw[a * 512 + k];
        }
    } else if (y == 4) {
        for (int i = i0; i < 1024 * 98; i += stride) {
            int k = i / 98, j = i % 98;
            g_fcT[i] = fcw[j * 1024 + k];
        }
        for (int i = i0; i < 2048; i += stride) {
            g_b0[i] = bih0[i] + bhh0[i];
            g_b1[i] = bih1[i] + bhh1[i];
        }
    } else {
        for (int i = i0; i < 64 * 256 * 512; i += stride) {
            int b = i >> 17, rem = i & 131071;
            int hw = rem >> 9, c = rem & 511;
            g_fmapT[i] = fmap[b * 131072 + c * 256 + hw];
        }
    }
}

__global__ void k_init(const float* __restrict__ h0, const float* __restrict__ c0,
                       const float* __restrict__ emb) {
    int idx = blockIdx.x * blockDim.x + threadIdx.x;
    const int S0 = 64 * 768, S1 = S0 + 64 * 512, S2 = S1 + 64 * 512, S3 = S2 + 64 * 512;
    if (idx < S0) {
        int b = idx / 768, k = idx % 768;
        g_xh0[0][idx] = (k < 256) ? emb[k] : h0[b * 512 + (k - 256)];
    } else if (idx < S1) {
        int r = idx - S0; int b = r >> 9, d = r & 511;
        g_xh1[0][b * 1024 + 512 + d] = h0[32768 + b * 512 + d];
    } else if (idx < S2) {
        g_c0s[idx - S1] = c0[idx - S1];
    } else if (idx < S3) {
        g_c1s[idx - S2] = c0[32768 + (idx - S2)];
    }
}

// ---------------- conv: tf32 implicit GEMM (proven round 2) ----------------
__global__ __launch_bounds__(512) void k_conv(const float* __restrict__ fmap) {
    __shared__ float xs[10 * 34 * 8];
    __shared__ float ws[9 * 8 * 128];
    const int b = blockIdx.y;
    const int n0 = blockIdx.x * 128;
    const int tid = threadIdx.x;
    const int warp = tid >> 5;
    const int wm = warp >> 1;
    const int wn = warp & 1;

    wmma::fragment<wmma::accumulator, 16, 16, 8, float> acc[2][4];
#pragma unroll
    for (int i = 0; i < 2; i++)
#pragma unroll
        for (int j = 0; j < 4; j++) wmma::fill_fragment(acc[i][j], 0.0f);

    const float* fb = fmap + b * 131072;
    for (int cc = 0; cc < 512; cc += 8) {
        for (int i = tid; i < 2720; i += 512) {
            int c = i / 340, rem = i % 340, r = rem / 34, w = rem % 34;
            int ir = r - 1, iw = w - 1;
            float v = (ir >= 0 && ir < 8 && iw >= 0 && iw < 32)
                          ? fb[(cc + c) * 256 + ir * 32 + iw] : 0.0f;
            xs[(r * 34 + w) * 8 + c] = v;
        }
        for (int i = tid; i < 9216; i += 512) {
            int n = i & 127, rc = i >> 7;
            int c = rc & 7, tap = rc >> 3;
            ws[i] = g_convWT[((cc + c) * 9 + tap) * 256 + n0 + n];
        }
        __syncthreads();
#pragma unroll
        for (int tap = 0; tap < 9; tap++) {
            const int dy = tap / 3, dx = tap % 3;
            wmma::fragment<wmma::matrix_a, 16, 16, 8, wmma::precision::tf32, wmma::row_major> af[2];
#pragma unroll
            for (int i = 0; i < 2; i++) {
                int mt = wm * 2 + i;
                int row = mt >> 1, wseg = (mt & 1) * 16;
                wmma::load_matrix_sync(af[i], &xs[((row + dy) * 34 + wseg + dx) * 8], 8);
                frag_tf32(af[i]);
            }
#pragma unroll
            for (int j = 0; j < 4; j++) {
                wmma::fragment<wmma::matrix_b, 16, 16, 8, wmma::precision::tf32, wmma::row_major> bf;
                wmma::load_matrix_sync(bf, &ws[(tap * 8) * 128 + wn * 64 + j * 16], 128);
                frag_tf32(bf);
#pragma unroll
                for (int i = 0; i < 2; i++)
                    wmma::mma_sync(acc[i][j], af[i], bf, acc[i][j]);
            }
        }
        __syncthreads();
    }
    float* eb = g_efmap + b * 65536;
#pragma unroll
    for (int i = 0; i < 2; i++) {
        int mt = wm * 2 + i, m0 = mt * 16;
#pragma unroll
        for (int j = 0; j < 4; j++) {
            int n = n0 + wn * 64 + j * 16;
            wmma::store_matrix_sync(eb + n * 256 + m0, acc[i][j], 256, wmma::mem_col_major);
        }
    }
}

// ---------------- persistent step kernel ----------------
// 128 blocks x 256 threads. block: ks = bid&7 (K-split), nt = bid>>3 (128-col N tile).
// smem: W0 slice [96][128] + W1 slice [128][128] persistent; As transient / attn scratch.
__global__ __launch_bounds__(256)
void k_steps(const int* __restrict__ target, const float* __restrict__ emb,
             const float* __restrict__ elb, const float* __restrict__ efb,
             const float* __restrict__ aw, const float* __restrict__ ab,
             const float* __restrict__ fcb, float* __restrict__ out) {
    extern __shared__ float sm[];
    float* W0s = sm;                 // 12288
    float* W1s = sm + 12288;         // 16384
    float* As  = sm + 28672;         // 8448 (max)
    const int tid = threadIdx.x;
    const int bid = blockIdx.x;
    const int warp = tid >> 5;
    const int wm = warp >> 2, wn = warp & 3;
    const int ks = bid & 7, nt = bid >> 3;

    // one-time weight staging (reused all 31 steps)
    {
        const float* s0 = g_W0 + (ks * 96) * 2048 + nt * 128;
        for (int i = tid; i < 96 * 32; i += 256) {
            int k = i >> 5, s = i & 31;
            *(float4*)&W0s[k * 128 + s * 4] = *(const float4*)&s0[k * 2048 + s * 4];
        }
        const float* s1 = g_W1 + (ks * 128) * 2048 + nt * 128;
        for (int i = tid; i < 128 * 32; i += 256) {
            int k = i >> 5, s = i & 31;
            *(float4*)&W1s[k * 128 + s * 4] = *(const float4*)&s1[k * 2048 + s * 4];
        }
    }
    __syncthreads();

    for (int t = 0; t < TSTEPS; t++) {
        const int tc = t & 1, tp = tc ^ 1;

        // ---- phase A: GEMM0 partial (M64 x N128 x K96) ----
        {
            const float* A = g_xh0[tc];
            for (int i = tid; i < 64 * 24; i += 256) {
                int m = i / 24, s = i % 24;
                float4 v = __ldcg((const float4*)(A + m * 768 + ks * 96 + s * 4));
                *(float4*)&As[m * 100 + s * 4] = v;
            }
            __syncthreads();
            wmma::fragment<wmma::accumulator, 16, 16, 8, float> acc[2][2];
#pragma unroll
            for (int i = 0; i < 2; i++)
#pragma unroll
                for (int j = 0; j < 2; j++) wmma::fill_fragment(acc[i][j], 0.0f);
#pragma unroll
            for (int kf = 0; kf < 12; kf++) {
                wmma::fragment<wmma::matrix_a, 16, 16, 8, wmma::precision::tf32, wmma::row_major> af[2];
                wmma::fragment<wmma::matrix_b, 16, 16, 8, wmma::precision::tf32, wmma::row_major> bf[2];
#pragma unroll
                for (int i = 0; i < 2; i++) {
                    wmma::load_matrix_sync(af[i], &As[(wm * 32 + i * 16) * 100 + kf * 8], 100);
                    frag_tf32(af[i]);
                }
#pragma unroll
                for (int j = 0; j < 2; j++) {
                    wmma::load_matrix_sync(bf[j], &W0s[kf * 8 * 128 + wn * 32 + j * 16], 128);
                    frag_tf32(bf[j]);
                }
#pragma unroll
                for (int i = 0; i < 2; i++)
#pragma unroll
                    for (int j = 0; j < 2; j++)
                        wmma::mma_sync(acc[i][j], af[i], bf[j], acc[i][j]);
            }
            float* P = g_part + ks * 131072;
#pragma unroll
            for (int i = 0; i < 2; i++)
#pragma unroll
                for (int j = 0; j < 2; j++)
                    wmma::store_matrix_sync(P + (wm * 32 + i * 16) * 2048 + nt * 128 + wn * 32 + j * 16,
                                            acc[i][j], 2048, wmma::mem_row_major);
        }
        gsync();

        // ---- phase B: LSTM0 pointwise (1 elem/thread) ----
        {
            int idx = bid * 256 + tid;          // 32768 = 64*512
            int b = idx >> 9, d = idx & 511;
            float gi = 0, gf = 0, gg = 0, go = 0;
#pragma unroll
            for (int s = 0; s < 8; s++) {
                const float* p = g_part + s * 131072 + b * 2048;
                gi += __ldcg(p + d); gf += __ldcg(p + 512 + d);
                gg += __ldcg(p + 1024 + d); go += __ldcg(p + 1536 + d);
            }
            gi += g_b0[d]; gf += g_b0[512 + d]; gg += g_b0[1024 + d]; go += g_b0[1536 + d];
            float c = g_c0s[idx];
            c = sig_acc(gf) * c + sig_acc(gi) * tanhf(gg);
            float h = sig_acc(go) * tanhf(c);
            g_c0s[idx] = c;
            g_xh1[tc][b * 1024 + d] = h;
            g_xh0[tp][b * 768 + 256 + d] = h;
        }
        gsync();

        // ---- phase C: GEMM1 partial (M64 x N128 x K128) ----
        {
            const float* A = g_xh1[tc];
            for (int i = tid; i < 64 * 32; i += 256) {
                int m = i >> 5, s = i & 31;
                float4 v = __ldcg((const float4*)(A + m * 1024 + ks * 128 + s * 4));
                *(float4*)&As[m * 132 + s * 4] = v;
            }
            __syncthreads();
            wmma::fragment<wmma::accumulator, 16, 16, 8, float> acc[2][2];
#pragma unroll
            for (int i = 0; i < 2; i++)
#pragma unroll
                for (int j = 0; j < 2; j++) wmma::fill_fragment(acc[i][j], 0.0f);
#pragma unroll
            for (int kf = 0; kf < 16; kf++) {
                wmma::fragment<wmma::matrix_a, 16, 16, 8, wmma::precision::tf32, wmma::row_major> af[2];
                wmma::fragment<wmma::matrix_b, 16, 16, 8, wmma::precision::tf32, wmma::row_major> bf[2];
#pragma unroll
                for (int i = 0; i < 2; i++) {
                    wmma::load_matrix_sync(af[i], &As[(wm * 32 + i * 16) * 132 + kf * 8], 132);
                    frag_tf32(af[i]);
                }
#pragma unroll
                for (int j = 0; j < 2; j++) {
                    wmma::load_matrix_sync(bf[j], &W1s[kf * 8 * 128 + wn * 32 + j * 16], 128);
                    frag_tf32(bf[j]);
                }
#pragma unroll
                for (int i = 0; i < 2; i++)
#pragma unroll
                    for (int j = 0; j < 2; j++)
                        wmma::mma_sync(acc[i][j], af[i], bf[j], acc[i][j]);
            }
            float* P = g_part + ks * 131072;
#pragma unroll
            for (int i = 0; i < 2; i++)
#pragma unroll
                for (int j = 0; j < 2; j++)
                    wmma::store_matrix_sync(P + (wm * 32 + i * 16) * 2048 + nt * 128 + wn * 32 + j * 16,
                                            acc[i][j], 2048, wmma::mem_row_major);
        }
        gsync();

        // ---- phase D: LSTM1 pointwise + attention + glimpse + fc (blocks 0..63) ----
        if (bid < 64) {
            const int b = bid;
            float* hs  = As;            // 512
            float* ehs = As + 512;      // 256
            float* aws = As + 768;      // 256
            float* ps  = As + 1024;     // 256
            float* gs  = As + 1280;     // 512
            float* red = As + 1792;     // 8
            float* red2= As + 1800;     // 8
            float* fin = As + 1808;     // 2
            float* facc= As + 1812;     // 196

#pragma unroll
            for (int r = 0; r < 2; r++) {
                int d = tid + r * 256;
                float gi = 0, gf = 0, gg = 0, go = 0;
#pragma unroll
                for (int s = 0; s < 8; s++) {
                    const float* p = g_part + s * 131072 + b * 2048;
                    gi += __ldcg(p + d); gf += __ldcg(p + 512 + d);
                    gg += __ldcg(p + 1024 + d); go += __ldcg(p + 1536 + d);
                }
                gi += g_b1[d]; gf += g_b1[512 + d]; gg += g_b1[1024 + d]; go += g_b1[1536 + d];
                float c = g_c1s[b * 512 + d];
                c = sig_acc(gf) * c + sig_acc(gi) * tanhf(gg);
                float h = sig_acc(go) * tanhf(c);
                g_c1s[b * 512 + d] = c;
                g_xh1[tp][b * 1024 + 512 + d] = h;
                hs[d] = h;
            }
            aws[tid] = aw[tid];
            __syncthreads();

            {
                float acc = elb[tid] + efb[tid];
                const float* w = g_elwT + tid;
#pragma unroll 8
                for (int k = 0; k < 512; k++) acc += hs[k] * w[k * 256];
                ehs[tid] = acc;
            }
            __syncthreads();

            float sc = ab[0];
            {
                const float* ef = g_efmap + b * 65536 + tid;
#pragma unroll 4
                for (int a = 0; a < 256; a++) sc += aws[a] * tanh_fast(ehs[a] + ef[a * 256]);
            }
            const int wp = tid >> 5, lane = tid & 31;
            float m = sc;
#pragma unroll
            for (int o = 16; o; o >>= 1) m = fmaxf(m, __shfl_xor_sync(0xffffffffu, m, o));
            if (lane == 0) red[wp] = m;
            __syncthreads();
            if (tid == 0) {
                float v = red[0];
#pragma unroll
                for (int i = 1; i < 8; i++) v = fmaxf(v, red[i]);
                fin[0] = v;
            }
            __syncthreads();
            float e = expf(sc - fin[0]);
            float s = e;
#pragma unroll
            for (int o = 16; o; o >>= 1) s += __shfl_xor_sync(0xffffffffu, s, o);
            if (lane == 0) red2[wp] = s;
            __syncthreads();
            if (tid == 0) {
                float v = 0;
#pragma unroll
                for (int i = 0; i < 8; i++) v += red2[i];
                fin[1] = v;
            }
            __syncthreads();
            float p = e / fin[1];
            ps[tid] = p;
            out[194432 + (b * 31 + t) * 256 + tid] = p;         // masks
            __syncthreads();

#pragma unroll
            for (int r = 0; r < 2; r++) {
                int c = tid + r * 256;
                float g = 0;
                const float* ft = g_fmapT + b * 131072 + c;
#pragma unroll 8
                for (int hw = 0; hw < 256; hw++) g += ft[hw * 512] * ps[hw];
                gs[c] = g;
                out[702336 + (b * 31 + t) * 512 + c] = g;        // glimpses
            }
            __syncthreads();

            if (tid < 196) {
                int half = (tid >= 98) ? 1 : 0;
                int j = tid - half * 98;
                const float* src = half ? gs : hs;
                const float* w = g_fcT + half * (512 * 98) + j;
                float acc = 0;
#pragma unroll 8
                for (int k = 0; k < 512; k++) acc += src[k] * w[k * 98];
                facc[half * 98 + j] = acc;
            }
            if (t < 30) {
                int lab = target[b * 30 + t];
                g_xh0[tp][b * 768 + tid] = emb[lab * 256 + tid]; // next-step embedding
            }
            __syncthreads();
            if (tid < 98)
                out[(b * 31 + t) * 98 + tid] = facc[tid] + facc[98 + tid] + fcb[tid]; // logits
        }
        gsync();
    }
}

// ---------------- launch ----------------
extern "C" void kernel_launch(void* const* d_in, const int* in_sizes, int n_in,
                              void* d_out, int out_size) {
    const float* fmap   = (const float*)d_in[0];
    const float* h0     = (const float*)d_in[1];
    const float* c0     = (const float*)d_in[2];
    const int*   target = (const int*)d_in[3];
    const float* emb    = (const float*)d_in[5];
    const float* Wih0   = (const float*)d_in[6];
    const float* Whh0   = (const float*)d_in[7];
    const float* bih0   = (const float*)d_in[8];
    const float* bhh0   = (const float*)d_in[9];
    const float* Wih1   = (const float*)d_in[10];
    const float* Whh1   = (const float*)d_in[11];
    const float* bih1   = (const float*)d_in[12];
    const float* bhh1   = (const float*)d_in[13];
    const float* elw    = (const float*)d_in[14];
    const float* elb    = (const float*)d_in[15];
    const float* efw    = (const float*)d_in[16];
    const float* efb    = (const float*)d_in[17];
    const float* aw     = (const float*)d_in[18];
    const float* ab     = (const float*)d_in[19];
    const float* fcw    = (const float*)d_in[20];
    const float* fcb    = (const float*)d_in[21];
    float* out = (float*)d_out;

    const int SMEM_BYTES = (12288 + 16384 + 8448) * 4;   // 148480
    static int configured = 0;
    if (!configured) {
        cudaFuncSetAttribute(k_steps, cudaFuncAttributeMaxDynamicSharedMemorySize, SMEM_BYTES);
        configured = 1;
    }

    k_transpose<<<dim3(512, 6), 256>>>(Wih0, Whh0, Wih1, Whh1, efw, elw, fcw, fmap,
                                       bih0, bhh0, bih1, bhh1);
    k_conv<<<dim3(2, 64), 512>>>(fmap);
    k_init<<<(64 * 2304 + 255) / 256, 256>>>(h0, c0, emb);
    k_steps<<<GBLK, 256, SMEM_BYTES>>>(target, emb, elb, efb, aw, ab, fcb, out);
}

// round 4
// speedup vs baseline: 2.7746x; 1.2455x over previous
#include <cuda_runtime.h>
#include <mma.h>
#include <math.h>

using namespace nvcuda;

#define TSTEPS 31
#define GBLK 128

// ---------------- scratch ----------------
__device__ float g_Wh0[512 * 2048];          // [k][n] n = d*4+g interleaved (Whh0)
__device__ float g_W1cat[1024 * 2048];       // [k][n] k: [h0_new|h1_prev]
__device__ float g_Wemb[256 * 2048];         // [k][n] (Wih0)
__device__ float g_b0i[2048];
__device__ float g_b1i[2048];
__device__ float g_convWT[512 * 9 * 256];    // [c][tap][attn]
__device__ float g_elwT[512 * 256];          // [k][attn]
__device__ float g_fcTp[1024 * 128];         // [k][class padded]
__device__ float g_efmap[64 * 256 * 256];    // [b][attn][hw] (no bias)
__device__ float g_E[1984 * 256];            // emb_seq rows (t*64+b)
__device__ float g_pre[1984 * 2048];         // emb @ Wih0^T, interleaved cols
__device__ float g_h0buf[2][64 * 512];
__device__ float g_x1buf[2][64 * 1024];      // [h0_new | h1_prev]
__device__ float g_c0s[64 * 512];
__device__ float g_c1s[64 * 512];
__device__ float g_h1all[1984 * 512];        // rows (t*64+b)
__device__ float g_eh[1984 * 256];
__device__ unsigned g_barc = 0;
__device__ volatile unsigned g_barg = 0;

__device__ __forceinline__ float tanh_fast(float x) {
    float y; asm("tanh.approx.f32 %0, %1;" : "=f"(y) : "f"(x)); return y;
}
__device__ __forceinline__ float sig_acc(float x) { return 1.0f / (1.0f + expf(-x)); }

template <class F>
__device__ __forceinline__ void frag_tf32(F& f) {
#pragma unroll
    for (int i = 0; i < f.num_elements; i++) f.x[i] = wmma::__float_to_tf32(f.x[i]);
}

__device__ __forceinline__ void gsync() {
    __syncthreads();
    if (threadIdx.x == 0) {
        __threadfence();
        unsigned gen = g_barg;
        if (atomicAdd(&g_barc, 1u) == GBLK - 1u) {
            g_barc = 0;
            __threadfence();
            g_barg = gen + 1u;
        } else {
            while (g_barg == gen) { }
            __threadfence();
        }
    }
    __syncthreads();
}

// ---------------- setup: repacks ----------------
__global__ void k_transpose(const float* __restrict__ Wih0, const float* __restrict__ Whh0,
                            const float* __restrict__ Wih1, const float* __restrict__ Whh1,
                            const float* __restrict__ efw, const float* __restrict__ elw,
                            const float* __restrict__ fcw,
                            const float* __restrict__ bih0, const float* __restrict__ bhh0,
                            const float* __restrict__ bih1, const float* __restrict__ bhh1) {
    const int y = blockIdx.y;
    const int stride = gridDim.x * blockDim.x;
    const int i0 = blockIdx.x * blockDim.x + threadIdx.x;
    if (y == 0) {
        for (int i = i0; i < 512 * 2048; i += stride) {
            int k = i >> 11, n = i & 2047;
            int col = (n & 3) * 512 + (n >> 2);
            g_Wh0[i] = Whh0[col * 512 + k];
        }
        for (int i = i0; i < 2048; i += stride) {
            int col = (i & 3) * 512 + (i >> 2);
            g_b0i[i] = bih0[col] + bhh0[col];
            g_b1i[i] = bih1[col] + bhh1[col];
        }
    } else if (y == 1) {
        for (int i = i0; i < 1024 * 2048; i += stride) {
            int k = i >> 11, n = i & 2047;
            int col = (n & 3) * 512 + (n >> 2);
            g_W1cat[i] = (k < 512) ? Wih1[col * 512 + k] : Whh1[col * 512 + (k - 512)];
        }
    } else if (y == 2) {
        for (int i = i0; i < 256 * 2048; i += stride) {
            int k = i >> 11, n = i & 2047;
            int col = (n & 3) * 512 + (n >> 2);
            g_Wemb[i] = Wih0[col * 256 + k];
        }
    } else if (y == 3) {
        for (int i = i0; i < 4608 * 256; i += stride) {
            int ck = i >> 8, a = i & 255;
            g_convWT[i] = efw[a * 4608 + ck];
        }
    } else {
        for (int i = i0; i < 512 * 256; i += stride) {
            int k = i >> 8, a = i & 255;
            g_elwT[i] = elw[a * 512 + k];
        }
        for (int i = i0; i < 1024 * 128; i += stride) {
            int k = i >> 7, j = i & 127;
            g_fcTp[i] = (j < 98) ? fcw[j * 1024 + k] : 0.0f;
        }
    }
}

__global__ void k_init2(const float* __restrict__ h0, const float* __restrict__ c0,
                        const float* __restrict__ emb, const int* __restrict__ target) {
    int idx = blockIdx.x * blockDim.x + threadIdx.x;
    const int SE = 1984 * 256;
    if (idx < SE) {
        int t = idx >> 14, rem = idx & 16383;
        int b = rem >> 8, k = rem & 255;
        int lab = (t == 0) ? 0 : target[b * 30 + t - 1];
        g_E[idx] = emb[lab * 256 + k];
    } else {
        int r = idx - SE;
        if (r < 32768) {
            g_h0buf[0][r] = h0[r];                       // layer0 h
        } else if (r < 65536) {
            int q = r - 32768; int b = q >> 9, d = q & 511;
            g_x1buf[0][b * 1024 + 512 + d] = h0[32768 + q];  // layer1 h
        } else if (r < 98304) {
            g_c0s[r - 65536] = c0[r - 65536];
        } else if (r < 131072) {
            g_c1s[r - 98304] = c0[32768 + (r - 98304)];
        }
    }
}

// ---------------- pre-embedding GEMM: g_pre = E @ Wemb ----------------
__global__ __launch_bounds__(256) void k_preemb() {
    __shared__ float As[64 * 36];
    __shared__ float Bs[32 * 128];
    const int tid = threadIdx.x;
    const int warp = tid >> 5;
    const int wm = warp >> 2, wn = warp & 3;
    const int n0 = blockIdx.x * 128, m0 = blockIdx.y * 64;
    wmma::fragment<wmma::accumulator, 16, 16, 8, float> acc[2][2];
#pragma unroll
    for (int i = 0; i < 2; i++)
#pragma unroll
        for (int j = 0; j < 2; j++) wmma::fill_fragment(acc[i][j], 0.0f);
    for (int kt = 0; kt < 256; kt += 32) {
        for (int i = tid; i < 2048; i += 256) {
            int m = i >> 5, k = i & 31;
            As[m * 36 + k] = g_E[(m0 + m) * 256 + kt + k];
        }
        for (int i = tid; i < 4096; i += 256) {
            int k = i >> 7, n = i & 127;
            Bs[i] = g_Wemb[(kt + k) * 2048 + n0 + n];
        }
        __syncthreads();
#pragma unroll
        for (int kf = 0; kf < 4; kf++) {
            wmma::fragment<wmma::matrix_a, 16, 16, 8, wmma::precision::tf32, wmma::row_major> af[2];
            wmma::fragment<wmma::matrix_b, 16, 16, 8, wmma::precision::tf32, wmma::row_major> bf[2];
#pragma unroll
            for (int i = 0; i < 2; i++) {
                wmma::load_matrix_sync(af[i], &As[(wm * 32 + i * 16) * 36 + kf * 8], 36);
                frag_tf32(af[i]);
            }
#pragma unroll
            for (int j = 0; j < 2; j++) {
                wmma::load_matrix_sync(bf[j], &Bs[kf * 8 * 128 + wn * 32 + j * 16], 128);
                frag_tf32(bf[j]);
            }
#pragma unroll
            for (int i = 0; i < 2; i++)
#pragma unroll
                for (int j = 0; j < 2; j++)
                    wmma::mma_sync(acc[i][j], af[i], bf[j], acc[i][j]);
        }
        __syncthreads();
    }
#pragma unroll
    for (int i = 0; i < 2; i++)
#pragma unroll
        for (int j = 0; j < 2; j++)
            wmma::store_matrix_sync(g_pre + (m0 + wm * 32 + i * 16) * 2048 + n0 + wn * 32 + j * 16,
                                    acc[i][j], 2048, wmma::mem_row_major);
}

// ---------------- conv: tf32 implicit GEMM (proven) ----------------
__global__ __launch_bounds__(512) void k_conv(const float* __restrict__ fmap) {
    __shared__ float xs[10 * 34 * 8];
    __shared__ float ws[9 * 8 * 128];
    const int b = blockIdx.y;
    const int n0 = blockIdx.x * 128;
    const int tid = threadIdx.x;
    const int warp = tid >> 5;
    const int wm = warp >> 1;
    const int wn = warp & 1;
    wmma::fragment<wmma::accumulator, 16, 16, 8, float> acc[2][4];
#pragma unroll
    for (int i = 0; i < 2; i++)
#pragma unroll
        for (int j = 0; j < 4; j++) wmma::fill_fragment(acc[i][j], 0.0f);
    const float* fb = fmap + b * 131072;
    for (int cc = 0; cc < 512; cc += 8) {
        for (int i = tid; i < 2720; i += 512) {
            int c = i / 340, rem = i % 340, r = rem / 34, w = rem % 34;
            int ir = r - 1, iw = w - 1;
            float v = (ir >= 0 && ir < 8 && iw >= 0 && iw < 32)
                          ? fb[(cc + c) * 256 + ir * 32 + iw] : 0.0f;
            xs[(r * 34 + w) * 8 + c] = v;
        }
        for (int i = tid; i < 9216; i += 512) {
            int n = i & 127, rc = i >> 7;
            int c = rc & 7, tap = rc >> 3;
            ws[i] = g_convWT[((cc + c) * 9 + tap) * 256 + n0 + n];
        }
        __syncthreads();
#pragma unroll
        for (int tap = 0; tap < 9; tap++) {
            const int dy = tap / 3, dx = tap % 3;
            wmma::fragment<wmma::matrix_a, 16, 16, 8, wmma::precision::tf32, wmma::row_major> af[2];
#pragma unroll
            for (int i = 0; i < 2; i++) {
                int mt = wm * 2 + i;
                int row = mt >> 1, wseg = (mt & 1) * 16;
                wmma::load_matrix_sync(af[i], &xs[((row + dy) * 34 + wseg + dx) * 8], 8);
                frag_tf32(af[i]);
            }
#pragma unroll
            for (int j = 0; j < 4; j++) {
                wmma::fragment<wmma::matrix_b, 16, 16, 8, wmma::precision::tf32, wmma::row_major> bf;
                wmma::load_matrix_sync(bf, &ws[(tap * 8) * 128 + wn * 64 + j * 16], 128);
                frag_tf32(bf);
#pragma unroll
                for (int i = 0; i < 2; i++)
                    wmma::mma_sync(acc[i][j], af[i], bf, acc[i][j]);
            }
        }
        __syncthreads();
    }
    float* eb = g_efmap + b * 65536;
#pragma unroll
    for (int i = 0; i < 2; i++) {
        int mt = wm * 2 + i, m0 = mt * 16;
#pragma unroll
        for (int j = 0; j < 4; j++) {
            int n = n0 + wn * 64 + j * 16;
            wmma::store_matrix_sync(eb + n * 256 + m0, acc[i][j], 256, wmma::mem_col_major);
        }
    }
}

// ---------------- persistent recurrence: 31 steps x 2 phases ----------------
// 128 blocks; block bid owns 16 interleaved gate-cols (= 4 d units, d=bid*4..+3).
__global__ __launch_bounds__(256)
void k_steps() {
    extern __shared__ float sm[];
    float* W0s = sm;                 // 512*16  = 8192
    float* W1s = sm + 8192;          // 1024*16 = 16384
    float* As  = sm + 24576;         // 64*68   = 4352
    float* Cs  = sm + 28928;         // 8*256   = 2048
    const int tid = threadIdx.x;
    const int bid = blockIdx.x;
    const int warp = tid >> 5;
    const int mt = warp & 3, kh = warp >> 2;
    const int n0 = bid * 16;

    for (int i = tid; i < 8192; i += 256) {
        int k = i >> 4, n = i & 15;
        W0s[i] = g_Wh0[k * 2048 + n0 + n];
    }
    for (int i = tid; i < 16384; i += 256) {
        int k = i >> 4, n = i & 15;
        W1s[i] = g_W1cat[k * 2048 + n0 + n];
    }
    __syncthreads();

    const int pb = tid >> 2, pdl = tid & 3;       // pointwise mapping
    const int pr = pb & 15, pmt = pb >> 4;
    const int pd = bid * 4 + pdl;

    for (int t = 0; t < TSTEPS; t++) {
        const int tc = t & 1, tp = tc ^ 1;

        // ---- phase 1: gates0 = h0_prev @ Whh0slice (+pre) -> LSTM0 ----
        {
            const float* Ap = g_h0buf[tc];
            wmma::fragment<wmma::accumulator, 16, 16, 8, float> acc;
            wmma::fill_fragment(acc, 0.0f);
            for (int ch = 0; ch < 8; ch++) {
                for (int i = tid; i < 1024; i += 256) {
                    int m = i >> 4, k4 = i & 15;
                    float4 v = __ldcg((const float4*)(Ap + m * 512 + ch * 64 + k4 * 4));
                    *(float4*)&As[m * 68 + k4 * 4] = v;
                }
                __syncthreads();
#pragma unroll
                for (int q = 0; q < 4; q++) {
                    int kf = kh * 4 + q;
                    wmma::fragment<wmma::matrix_a, 16, 16, 8, wmma::precision::tf32, wmma::row_major> af;
                    wmma::fragment<wmma::matrix_b, 16, 16, 8, wmma::precision::tf32, wmma::row_major> bf;
                    wmma::load_matrix_sync(af, &As[(mt * 16) * 68 + kf * 8], 68);
                    frag_tf32(af);
                    wmma::load_matrix_sync(bf, &W0s[(ch * 64 + kf * 8) * 16], 16);
                    frag_tf32(bf);
                    wmma::mma_sync(acc, af, bf, acc);
                }
                __syncthreads();
            }
            wmma::store_matrix_sync(&Cs[warp * 256], acc, 16, wmma::mem_row_major);
            __syncthreads();

            float4 pe = *(const float4*)&g_pre[(t * 64 + pb) * 2048 + n0 + pdl * 4];
            float4 bi = *(const float4*)&g_b0i[n0 + pdl * 4];
            int base = pmt * 256 + pr * 16 + pdl * 4;
            float gi = Cs[base + 0] + Cs[1024 + base + 0] + pe.x + bi.x;
            float gf = Cs[base + 1] + Cs[1024 + base + 1] + pe.y + bi.y;
            float gg = Cs[base + 2] + Cs[1024 + base + 2] + pe.z + bi.z;
            float go = Cs[base + 3] + Cs[1024 + base + 3] + pe.w + bi.w;
            float c = g_c0s[pb * 512 + pd];
            c = sig_acc(gf) * c + sig_acc(gi) * tanhf(gg);
            float h = sig_acc(go) * tanhf(c);
            g_c0s[pb * 512 + pd] = c;
            g_x1buf[tc][pb * 1024 + pd] = h;
            g_h0buf[tp][pb * 512 + pd] = h;
        }
        gsync();

        // ---- phase 2: gates1 = [h0_new|h1_prev] @ W1slice -> LSTM1 ----
        {
            const float* Ap = g_x1buf[tc];
            wmma::fragment<wmma::accumulator, 16, 16, 8, float> acc;
            wmma::fill_fragment(acc, 0.0f);
            for (int ch = 0; ch < 16; ch++) {
                for (int i = tid; i < 1024; i += 256) {
                    int m = i >> 4, k4 = i & 15;
                    float4 v = __ldcg((const float4*)(Ap + m * 1024 + ch * 64 + k4 * 4));
                    *(float4*)&As[m * 68 + k4 * 4] = v;
                }
                __syncthreads();
#pragma unroll
                for (int q = 0; q < 4; q++) {
                    int kf = kh * 4 + q;
                    wmma::fragment<wmma::matrix_a, 16, 16, 8, wmma::precision::tf32, wmma::row_major> af;
                    wmma::fragment<wmma::matrix_b, 16, 16, 8, wmma::precision::tf32, wmma::row_major> bf;
                    wmma::load_matrix_sync(af, &As[(mt * 16) * 68 + kf * 8], 68);
                    frag_tf32(af);
                    wmma::load_matrix_sync(bf, &W1s[(ch * 64 + kf * 8) * 16], 16);
                    frag_tf32(bf);
                    wmma::mma_sync(acc, af, bf, acc);
                }
                __syncthreads();
            }
            wmma::store_matrix_sync(&Cs[warp * 256], acc, 16, wmma::mem_row_major);
            __syncthreads();

            float4 bi = *(const float4*)&g_b1i[n0 + pdl * 4];
            int base = pmt * 256 + pr * 16 + pdl * 4;
            float gi = Cs[base + 0] + Cs[1024 + base + 0] + bi.x;
            float gf = Cs[base + 1] + Cs[1024 + base + 1] + bi.y;
            float gg = Cs[base + 2] + Cs[1024 + base + 2] + bi.z;
            float go = Cs[base + 3] + Cs[1024 + base + 3] + bi.w;
            float c = g_c1s[pb * 512 + pd];
            c = sig_acc(gf) * c + sig_acc(gi) * tanhf(gg);
            float h = sig_acc(go) * tanhf(c);
            g_c1s[pb * 512 + pd] = c;
            g_x1buf[tp][pb * 1024 + 512 + pd] = h;
            g_h1all[(t * 64 + pb) * 512 + pd] = h;
        }
        gsync();
    }
}

// ---------------- epilogue: e_h = h1all @ elwT ----------------
__global__ __launch_bounds__(256) void k_eh() {
    __shared__ float As[64 * 36];
    __shared__ float Bs[32 * 128];
    const int tid = threadIdx.x;
    const int warp = tid >> 5;
    const int wm = warp >> 2, wn = warp & 3;
    const int n0 = blockIdx.x * 128, m0 = blockIdx.y * 64;
    wmma::fragment<wmma::accumulator, 16, 16, 8, float> acc[2][2];
#pragma unroll
    for (int i = 0; i < 2; i++)
#pragma unroll
        for (int j = 0; j < 2; j++) wmma::fill_fragment(acc[i][j], 0.0f);
    for (int kt = 0; kt < 512; kt += 32) {
        for (int i = tid; i < 2048; i += 256) {
            int m = i >> 5, k = i & 31;
            As[m * 36 + k] = g_h1all[(m0 + m) * 512 + kt + k];
        }
        for (int i = tid; i < 4096; i += 256) {
            int k = i >> 7, n = i & 127;
            Bs[i] = g_elwT[(kt + k) * 256 + n0 + n];
        }
        __syncthreads();
#pragma unroll
        for (int kf = 0; kf < 4; kf++) {
            wmma::fragment<wmma::matrix_a, 16, 16, 8, wmma::precision::tf32, wmma::row_major> af[2];
            wmma::fragment<wmma::matrix_b, 16, 16, 8, wmma::precision::tf32, wmma::row_major> bf[2];
#pragma unroll
            for (int i = 0; i < 2; i++) {
                wmma::load_matrix_sync(af[i], &As[(wm * 32 + i * 16) * 36 + kf * 8], 36);
                frag_tf32(af[i]);
            }
#pragma unroll
            for (int j = 0; j < 2; j++) {
                wmma::load_matrix_sync(bf[j], &Bs[kf * 8 * 128 + wn * 32 + j * 16], 128);
                frag_tf32(bf[j]);
            }
#pragma unroll
            for (int i = 0; i < 2; i++)
#pragma unroll
                for (int j = 0; j < 2; j++)
                    wmma::mma_sync(acc[i][j], af[i], bf[j], acc[i][j]);
        }
        __syncthreads();
    }
#pragma unroll
    for (int i = 0; i < 2; i++)
#pragma unroll
        for (int j = 0; j < 2; j++)
            wmma::store_matrix_sync(g_eh + (m0 + wm * 32 + i * 16) * 256 + n0 + wn * 32 + j * 16,
                                    acc[i][j], 256, wmma::mem_row_major);
}

// ---------------- epilogue: scores + softmax + masks ----------------
__global__ __launch_bounds__(256) void k_scores(const float* __restrict__ elb,
                                                const float* __restrict__ efb,
                                                const float* __restrict__ aw,
                                                const float* __restrict__ ab,
                                                float* __restrict__ out) {
    const int t = blockIdx.x, b = blockIdx.y;
    const int tid = threadIdx.x;
    __shared__ float ehs[256], aws[256];
    __shared__ float red[8], red2[8], fin[2];
    ehs[tid] = g_eh[(t * 64 + b) * 256 + tid] + elb[tid] + efb[tid];
    aws[tid] = aw[tid];
    __syncthreads();
    float sc = ab[0];
    {
        const float* ef = g_efmap + b * 65536 + tid;
#pragma unroll 8
        for (int a = 0; a < 256; a++) sc += aws[a] * tanh_fast(ehs[a] + ef[a * 256]);
    }
    const int wp = tid >> 5, lane = tid & 31;
    float m = sc;
#pragma unroll
    for (int o = 16; o; o >>= 1) m = fmaxf(m, __shfl_xor_sync(0xffffffffu, m, o));
    if (lane == 0) red[wp] = m;
    __syncthreads();
    if (tid == 0) {
        float v = red[0];
#pragma unroll
        for (int i = 1; i < 8; i++) v = fmaxf(v, red[i]);
        fin[0] = v;
    }
    __syncthreads();
    float e = expf(sc - fin[0]);
    float s = e;
#pragma unroll
    for (int o = 16; o; o >>= 1) s += __shfl_xor_sync(0xffffffffu, s, o);
    if (lane == 0) red2[wp] = s;
    __syncthreads();
    if (tid == 0) {
        float v = 0;
#pragma unroll
        for (int i = 0; i < 8; i++) v += red2[i];
        fin[1] = v;
    }
    __syncthreads();
    out[194432 + (b * 31 + t) * 256 + tid] = e / fin[1];
}

// ---------------- epilogue: glimpse (exact fp32, fmap read once per b) ----------------
__global__ __launch_bounds__(256) void k_glimpse(const float* __restrict__ fmap,
                                                 float* __restrict__ out) {
    __shared__ float ms[31 * 256];
    const int b = blockIdx.y;
    const int c = blockIdx.x * 256 + threadIdx.x;
    const int tid = threadIdx.x;
    for (int i = tid; i < 7936; i += 256) ms[i] = out[194432 + b * 7936 + i];
    __syncthreads();
    float acc[31];
#pragma unroll
    for (int tt = 0; tt < 31; tt++) acc[tt] = 0.0f;
    const float* fp = fmap + b * 131072 + c * 256;
    for (int h4 = 0; h4 < 64; h4++) {
        float4 f = __ldg((const float4*)(fp + h4 * 4));
#pragma unroll
        for (int tt = 0; tt < 31; tt++) {
            float4 m4 = *(const float4*)&ms[tt * 256 + h4 * 4];
            acc[tt] += f.x * m4.x + f.y * m4.y + f.z * m4.z + f.w * m4.w;
        }
    }
#pragma unroll
    for (int tt = 0; tt < 31; tt++)
        out[702336 + (b * 31 + tt) * 512 + c] = acc[tt];
}

// ---------------- epilogue: fc logits ----------------
__global__ __launch_bounds__(256) void k_fc(const float* __restrict__ fcb,
                                            float* __restrict__ out) {
    __shared__ float smem[8192];          // As(2304) + Bs(4096) during loop; Cs(8192) after
    float* As = smem;
    float* Bs = smem + 2304;
    const int t = blockIdx.x;
    const int tid = threadIdx.x;
    const int warp = tid >> 5;
    const int wm = warp >> 2, wn = warp & 3;
    wmma::fragment<wmma::accumulator, 16, 16, 8, float> acc[2][2];
#pragma unroll
    for (int i = 0; i < 2; i++)
#pragma unroll
        for (int j = 0; j < 2; j++) wmma::fill_fragment(acc[i][j], 0.0f);
    for (int kt = 0; kt < 1024; kt += 32) {
        for (int i = tid; i < 2048; i += 256) {
            int m = i >> 5, k = i & 31;
            int kk = kt + k;
            As[m * 36 + k] = (kk < 512) ? g_h1all[(t * 64 + m) * 512 + kk]
                                        : out[702336 + (m * 31 + t) * 512 + kk - 512];
        }
        for (int i = tid; i < 4096; i += 256) {
            int k = i >> 7, n = i & 127;
            Bs[i] = g_fcTp[(kt + k) * 128 + n];
        }
        __syncthreads();
#pragma unroll
        for (int kf = 0; kf < 4; kf++) {
            wmma::fragment<wmma::matrix_a, 16, 16, 8, wmma::precision::tf32, wmma::row_major> af[2];
            wmma::fragment<wmma::matrix_b, 16, 16, 8, wmma::precision::tf32, wmma::row_major> bf[2];
#pragma unroll
            for (int i = 0; i < 2; i++) {
                wmma::load_matrix_sync(af[i], &As[(wm * 32 + i * 16) * 36 + kf * 8], 36);
                frag_tf32(af[i]);
            }
#pragma unroll
            for (int j = 0; j < 2; j++) {
                wmma::load_matrix_sync(bf[j], &Bs[kf * 8 * 128 + wn * 32 + j * 16], 128);
                frag_tf32(bf[j]);
            }
#pragma unroll
            for (int i = 0; i < 2; i++)
#pragma unroll
                for (int j = 0; j < 2; j++)
                    wmma::mma_sync(acc[i][j], af[i], bf[j], acc[i][j]);
        }
        __syncthreads();
    }
    float* Cs = smem;
#pragma unroll
    for (int i = 0; i < 2; i++)
#pragma unroll
        for (int j = 0; j < 2; j++)
            wmma::store_matrix_sync(&Cs[(wm * 32 + i * 16) * 128 + wn * 32 + j * 16],
                                    acc[i][j], 128, wmma::mem_row_major);
    __syncthreads();
    for (int i = tid; i < 64 * 98; i += 256) {
        int m = i / 98, j = i % 98;
        out[(m * 31 + t) * 98 + j] = Cs[m * 128 + j] + fcb[j];
    }
}

// ---------------- launch ----------------
extern "C" void kernel_launch(void* const* d_in, const int* in_sizes, int n_in,
                              void* d_out, int out_size) {
    const float* fmap   = (const float*)d_in[0];
    const float* h0     = (const float*)d_in[1];
    const float* c0     = (const float*)d_in[2];
    const int*   target = (const int*)d_in[3];
    const float* emb    = (const float*)d_in[5];
    const float* Wih0   = (const float*)d_in[6];
    const float* Whh0   = (const float*)d_in[7];
    const float* bih0   = (const float*)d_in[8];
    const float* bhh0   = (const float*)d_in[9];
    const float* Wih1   = (const float*)d_in[10];
    const float* Whh1   = (const float*)d_in[11];
    const float* bih1   = (const float*)d_in[12];
    const float* bhh1   = (const float*)d_in[13];
    const float* elw    = (const float*)d_in[14];
    const float* elb    = (const float*)d_in[15];
    const float* efw    = (const float*)d_in[16];
    const float* efb    = (const float*)d_in[17];
    const float* aw     = (const float*)d_in[18];
    const float* ab     = (const float*)d_in[19];
    const float* fcw    = (const float*)d_in[20];
    const float* fcb    = (const float*)d_in[21];
    float* out = (float*)d_out;

    const int SMEM_BYTES = (8192 + 16384 + 4352 + 2048) * 4;   // 123904
    static int configured = 0;
    if (!configured) {
        cudaFuncSetAttribute(k_steps, cudaFuncAttributeMaxDynamicSharedMemorySize, SMEM_BYTES);
        configured = 1;
    }

    k_transpose<<<dim3(512, 5), 256>>>(Wih0, Whh0, Wih1, Whh1, efw, elw, fcw,
                                       bih0, bhh0, bih1, bhh1);
    k_init2<<<(1984 * 256 + 131072 + 255) / 256, 256>>>(h0, c0, emb, target);
    k_preemb<<<dim3(16, 31), 256>>>();
    k_conv<<<dim3(2, 64), 512>>>(fmap);
    k_steps<<<GBLK, 256, SMEM_BYTES>>>();
    k_eh<<<dim3(2, 31), 256>>>();
    k_scores<<<dim3(31, 64), 256>>>(elb, efb, aw, ab, out);
    k_glimpse<<<dim3(2, 64), 256>>>(fmap, out);
    k_fc<<<31, 256>>>(fcb, out);
}

// round 5
// speedup vs baseline: 3.6299x; 1.3083x over previous
#include <cuda_runtime.h>
#include <mma.h>
#include <math.h>

using namespace nvcuda;

#define TSTEPS 31
#define GBLK 128

// ---------------- scratch ----------------
__device__ float g_Wh0[512 * 2048];          // [k][n] n = d*4+g interleaved (Whh0)
__device__ float g_W1cat[1024 * 2048];       // [k][n] k: [h0_new|h1_prev]
__device__ float g_Wemb[256 * 2048];         // [k][n] (Wih0)
__device__ float g_b0i[2048];
__device__ float g_b1i[2048];
__device__ float g_convWB[9 * 512 * 256];    // [tap][c][attn]
__device__ float g_elwT[512 * 256];          // [k][attn]
__device__ float g_fcTp[1024 * 128];         // [k][class padded]
__device__ float g_fmapT[64 * 256 * 512];    // [b][hw][c]
__device__ float g_efmap[64 * 256 * 256];    // [b][attn][hw] (no bias)
__device__ float g_E[1984 * 256];            // emb_seq rows (t*64+b)
__device__ float g_pre[1984 * 2048];         // emb @ Wih0^T, interleaved cols
__device__ float g_h0buf[2][64 * 512];
__device__ float g_x1buf[2][64 * 1024];      // [h0_new | h1_prev]
__device__ float g_c0s[64 * 512];
__device__ float g_c1s[64 * 512];
__device__ float g_h1all[1984 * 512];        // rows (t*64+b)
__device__ float g_eh[1984 * 256];
__device__ unsigned g_barc = 0;
__device__ volatile unsigned g_barg = 0;

__device__ __forceinline__ float tanh_fast(float x) {
    float y; asm("tanh.approx.f32 %0, %1;" : "=f"(y) : "f"(x)); return y;
}
__device__ __forceinline__ float sig_acc(float x) { return 1.0f / (1.0f + expf(-x)); }

template <class F>
__device__ __forceinline__ void frag_tf32(F& f) {
#pragma unroll
    for (int i = 0; i < f.num_elements; i++) f.x[i] = wmma::__float_to_tf32(f.x[i]);
}

__device__ __forceinline__ void gsync() {
    __syncthreads();
    if (threadIdx.x == 0) {
        __threadfence();
        unsigned gen = g_barg;
        if (atomicAdd(&g_barc, 1u) == GBLK - 1u) {
            g_barc = 0;
            __threadfence();
            g_barg = gen + 1u;
        } else {
            while (g_barg == gen) { }
            __threadfence();
        }
    }
    __syncthreads();
}

// ---------------- setup: repacks ----------------
__global__ void k_transpose(const float* __restrict__ Wih0, const float* __restrict__ Whh0,
                            const float* __restrict__ Wih1, const float* __restrict__ Whh1,
                            const float* __restrict__ efw, const float* __restrict__ elw,
                            const float* __restrict__ fcw, const float* __restrict__ fmap,
                            const float* __restrict__ bih0, const float* __restrict__ bhh0,
                            const float* __restrict__ bih1, const float* __restrict__ bhh1) {
    const int y = blockIdx.y;
    const int stride = gridDim.x * blockDim.x;
    const int i0 = blockIdx.x * blockDim.x + threadIdx.x;
    if (y == 0) {
        for (int i = i0; i < 512 * 2048; i += stride) {
            int k = i >> 11, n = i & 2047;
            int col = (n & 3) * 512 + (n >> 2);
            g_Wh0[i] = Whh0[col * 512 + k];
        }
        for (int i = i0; i < 2048; i += stride) {
            int col = (i & 3) * 512 + (i >> 2);
            g_b0i[i] = bih0[col] + bhh0[col];
            g_b1i[i] = bih1[col] + bhh1[col];
        }
    } else if (y == 1) {
        for (int i = i0; i < 1024 * 2048; i += stride) {
            int k = i >> 11, n = i & 2047;
            int col = (n & 3) * 512 + (n >> 2);
            g_W1cat[i] = (k < 512) ? Wih1[col * 512 + k] : Whh1[col * 512 + (k - 512)];
        }
    } else if (y == 2) {
        for (int i = i0; i < 256 * 2048; i += stride) {
            int k = i >> 11, n = i & 2047;
            int col = (n & 3) * 512 + (n >> 2);
            g_Wemb[i] = Wih0[col * 256 + k];
        }
    } else if (y == 3) {
        for (int i = i0; i < 9 * 512 * 256; i += stride) {
            int tap = i >> 17, rem = i & 131071;
            int c = rem >> 8, a = rem & 255;
            g_convWB[i] = efw[a * 4608 + c * 9 + tap];
        }
    } else if (y == 4) {
        for (int i = i0; i < 512 * 256; i += stride) {
            int k = i >> 8, a = i & 255;
            g_elwT[i] = elw[a * 512 + k];
        }
        for (int i = i0; i < 1024 * 128; i += stride) {
            int k = i >> 7, j = i & 127;
            g_fcTp[i] = (j < 98) ? fcw[j * 1024 + k] : 0.0f;
        }
    } else {
        for (int i = i0; i < 64 * 256 * 512; i += stride) {
            int b = i >> 17, rem = i & 131071;
            int hw = rem >> 9, c = rem & 511;
            g_fmapT[i] = fmap[b * 131072 + c * 256 + hw];
        }
    }
}

__global__ void k_init2(const float* __restrict__ h0, const float* __restrict__ c0,
                        const float* __restrict__ emb, const int* __restrict__ target) {
    int idx = blockIdx.x * blockDim.x + threadIdx.x;
    const int SE = 1984 * 256;
    if (idx < SE) {
        int t = idx >> 14, rem = idx & 16383;
        int b = rem >> 8, k = rem & 255;
        int lab = (t == 0) ? 0 : target[b * 30 + t - 1];
        g_E[idx] = emb[lab * 256 + k];
    } else {
        int r = idx - SE;
        if (r < 32768) {
            g_h0buf[0][r] = h0[r];
        } else if (r < 65536) {
            int q = r - 32768; int b = q >> 9, d = q & 511;
            g_x1buf[0][b * 1024 + 512 + d] = h0[32768 + q];
        } else if (r < 98304) {
            g_c0s[r - 65536] = c0[r - 65536];
        } else if (r < 131072) {
            g_c1s[r - 98304] = c0[32768 + (r - 98304)];
        }
    }
}

// ---------------- pre-embedding GEMM: g_pre = E @ Wemb ----------------
__global__ __launch_bounds__(256) void k_preemb() {
    __shared__ float As[64 * 36];
    __shared__ float Bs[32 * 128];
    const int tid = threadIdx.x;
    const int warp = tid >> 5;
    const int wm = warp >> 2, wn = warp & 3;
    const int n0 = blockIdx.x * 128, m0 = blockIdx.y * 64;
    wmma::fragment<wmma::accumulator, 16, 16, 8, float> acc[2][2];
#pragma unroll
    for (int i = 0; i < 2; i++)
#pragma unroll
        for (int j = 0; j < 2; j++) wmma::fill_fragment(acc[i][j], 0.0f);
    for (int kt = 0; kt < 256; kt += 32) {
        for (int i = tid; i < 2048; i += 256) {
            int m = i >> 5, k = i & 31;
            As[m * 36 + k] = g_E[(m0 + m) * 256 + kt + k];
        }
        for (int i = tid; i < 4096; i += 256) {
            int k = i >> 7, n = i & 127;
            Bs[i] = g_Wemb[(kt + k) * 2048 + n0 + n];
        }
        __syncthreads();
#pragma unroll
        for (int kf = 0; kf < 4; kf++) {
            wmma::fragment<wmma::matrix_a, 16, 16, 8, wmma::precision::tf32, wmma::row_major> af[2];
            wmma::fragment<wmma::matrix_b, 16, 16, 8, wmma::precision::tf32, wmma::row_major> bf[2];
#pragma unroll
            for (int i = 0; i < 2; i++) {
                wmma::load_matrix_sync(af[i], &As[(wm * 32 + i * 16) * 36 + kf * 8], 36);
                frag_tf32(af[i]);
            }
#pragma unroll
            for (int j = 0; j < 2; j++) {
                wmma::load_matrix_sync(bf[j], &Bs[kf * 8 * 128 + wn * 32 + j * 16], 128);
                frag_tf32(bf[j]);
            }
#pragma unroll
            for (int i = 0; i < 2; i++)
#pragma unroll
                for (int j = 0; j < 2; j++)
                    wmma::mma_sync(acc[i][j], af[i], bf[j], acc[i][j]);
        }
        __syncthreads();
    }
#pragma unroll
    for (int i = 0; i < 2; i++)
#pragma unroll
        for (int j = 0; j < 2; j++)
            wmma::store_matrix_sync(g_pre + (m0 + wm * 32 + i * 16) * 2048 + n0 + wn * 32 + j * 16,
                                    acc[i][j], 2048, wmma::mem_row_major);
}

// ---------------- conv v2: tap-major implicit GEMM from fmapT ----------------
// grid (2 ntile, 4 mtile, 64 b), 256 thr. Block tile M64 x N128, K=4608 in 72 chunks of 64.
__global__ __launch_bounds__(256) void k_conv() {
    extern __shared__ float csm[];
    float* As = csm;             // 64*68 = 4352
    float* Bs = csm + 4352;      // 64*128 = 8192
    const int tid = threadIdx.x;
    const int warp = tid >> 5;
    const int wm = warp >> 2, wn = warp & 3;
    const int n0 = blockIdx.x * 128;
    const int s0 = blockIdx.y * 64;
    const int b = blockIdx.z;
    const float* fT = g_fmapT + b * 131072;

    wmma::fragment<wmma::accumulator, 16, 16, 8, float> acc[2][2];
#pragma unroll
    for (int i = 0; i < 2; i++)
#pragma unroll
        for (int j = 0; j < 2; j++) wmma::fill_fragment(acc[i][j], 0.0f);

    float4 rA[4], rB[8];
    const float4 z4 = make_float4(0.f, 0.f, 0.f, 0.f);

    // per-thread A geometry (row fixed per j)
    int arow[4], aseg[4];
#pragma unroll
    for (int j = 0; j < 4; j++) {
        int f = tid + j * 256;
        arow[j] = f >> 4; aseg[j] = f & 15;
    }

    auto loadA = [&](int q) {
        int tap = q >> 3, cch = q & 7;
        int dy = tap / 3 - 1, dx = tap % 3 - 1;
#pragma unroll
        for (int j = 0; j < 4; j++) {
            int s = s0 + arow[j];
            int yy = (s >> 5) + dy, xx = (s & 31) + dx;
            bool ok = (yy >= 0) && (yy < 8) && (xx >= 0) && (xx < 32);
            rA[j] = ok ? *(const float4*)(fT + (yy * 32 + xx) * 512 + cch * 64 + aseg[j] * 4) : z4;
        }
    };
    auto loadB = [&](int q) {
        int tap = q >> 3, cch = q & 7;
        const float* src = g_convWB + (tap * 512 + cch * 64) * 256 + n0;
#pragma unroll
        for (int j = 0; j < 8; j++) {
            int f = tid + j * 256;
            rB[j] = *(const float4*)(src + (f >> 5) * 256 + (f & 31) * 4);
        }
    };

    loadA(0); loadB(0);
#pragma unroll 1
    for (int q = 0; q < 72; q++) {
#pragma unroll
        for (int j = 0; j < 4; j++)
            *(float4*)&As[arow[j] * 68 + aseg[j] * 4] = rA[j];
#pragma unroll
        for (int j = 0; j < 8; j++) {
            int f = tid + j * 256;
            *(float4*)&Bs[(f >> 5) * 128 + (f & 31) * 4] = rB[j];
        }
        __syncthreads();
        if (q < 71) { loadA(q + 1); loadB(q + 1); }
#pragma unroll
        for (int kf = 0; kf < 8; kf++) {
            wmma::fragment<wmma::matrix_a, 16, 16, 8, wmma::precision::tf32, wmma::row_major> af[2];
            wmma::fragment<wmma::matrix_b, 16, 16, 8, wmma::precision::tf32, wmma::row_major> bf[2];
#pragma unroll
            for (int i = 0; i < 2; i++) {
                wmma::load_matrix_sync(af[i], &As[(wm * 32 + i * 16) * 68 + kf * 8], 68);
                frag_tf32(af[i]);
            }
#pragma unroll
            for (int j = 0; j < 2; j++) {
                wmma::load_matrix_sync(bf[j], &Bs[kf * 8 * 128 + wn * 32 + j * 16], 128);
                frag_tf32(bf[j]);
            }
#pragma unroll
            for (int i = 0; i < 2; i++)
#pragma unroll
                for (int j = 0; j < 2; j++)
                    wmma::mma_sync(acc[i][j], af[i], bf[j], acc[i][j]);
        }
        __syncthreads();
    }
    float* eb = g_efmap + b * 65536;
#pragma unroll
    for (int i = 0; i < 2; i++)
#pragma unroll
        for (int j = 0; j < 2; j++)
            wmma::store_matrix_sync(eb + (n0 + wn * 32 + j * 16) * 256 + s0 + wm * 32 + i * 16,
                                    acc[i][j], 256, wmma::mem_col_major);
}

// ---------------- persistent recurrence: 31 steps x 2 phases ----------------
__global__ __launch_bounds__(256)
void k_steps() {
    extern __shared__ float sm[];
    float* W0s = sm;                 // 512*16  = 8192
    float* W1s = sm + 8192;          // 1024*16 = 16384
    float* As  = sm + 24576;         // 64*68   = 4352
    float* Cs  = sm + 28928;         // 8*256   = 2048
    const int tid = threadIdx.x;
    const int bid = blockIdx.x;
    const int warp = tid >> 5;
    const int mt = warp & 3, kh = warp >> 2;
    const int n0 = bid * 16;

    for (int i = tid; i < 8192; i += 256) {
        int k = i >> 4, n = i & 15;
        W0s[i] = g_Wh0[k * 2048 + n0 + n];
    }
    for (int i = tid; i < 16384; i += 256) {
        int k = i >> 4, n = i & 15;
        W1s[i] = g_W1cat[k * 2048 + n0 + n];
    }
    __syncthreads();

    const int pb = tid >> 2, pdl = tid & 3;
    const int pr = pb & 15, pmt = pb >> 4;
    const int pd = bid * 4 + pdl;
    const int am = tid >> 4, ak4 = tid & 15;   // A-load mapping (4 float4/thread)

    for (int t = 0; t < TSTEPS; t++) {
        const int tc = t & 1, tp = tc ^ 1;

        // ---- phase 1: gates0 = h0_prev @ Whh0slice (+pre) -> LSTM0 ----
        {
            const float* Ap = g_h0buf[tc];
            float4 r[4];
#pragma unroll
            for (int j = 0; j < 4; j++)
                r[j] = __ldcg((const float4*)(Ap + (am + j * 16) * 512 + ak4 * 4));
            wmma::fragment<wmma::accumulator, 16, 16, 8, float> acc;
            wmma::fill_fragment(acc, 0.0f);
#pragma unroll 1
            for (int ch = 0; ch < 8; ch++) {
#pragma unroll
                for (int j = 0; j < 4; j++)
                    *(float4*)&As[(am + j * 16) * 68 + ak4 * 4] = r[j];
                __syncthreads();
                if (ch < 7) {
#pragma unroll
                    for (int j = 0; j < 4; j++)
                        r[j] = __ldcg((const float4*)(Ap + (am + j * 16) * 512 + (ch + 1) * 64 + ak4 * 4));
                }
#pragma unroll
                for (int q = 0; q < 4; q++) {
                    int kf = kh * 4 + q;
                    wmma::fragment<wmma::matrix_a, 16, 16, 8, wmma::precision::tf32, wmma::row_major> af;
                    wmma::fragment<wmma::matrix_b, 16, 16, 8, wmma::precision::tf32, wmma::row_major> bf;
                    wmma::load_matrix_sync(af, &As[(mt * 16) * 68 + kf * 8], 68);
                    frag_tf32(af);
                    wmma::load_matrix_sync(bf, &W0s[(ch * 64 + kf * 8) * 16], 16);
                    frag_tf32(bf);
                    wmma::mma_sync(acc, af, bf, acc);
                }
                __syncthreads();
            }
            wmma::store_matrix_sync(&Cs[warp * 256], acc, 16, wmma::mem_row_major);
            __syncthreads();

            float4 pe = *(const float4*)&g_pre[(t * 64 + pb) * 2048 + n0 + pdl * 4];
            float4 bi = *(const float4*)&g_b0i[n0 + pdl * 4];
            int base = pmt * 256 + pr * 16 + pdl * 4;
            float gi = Cs[base + 0] + Cs[1024 + base + 0] + pe.x + bi.x;
            float gf = Cs[base + 1] + Cs[1024 + base + 1] + pe.y + bi.y;
            float gg = Cs[base + 2] + Cs[1024 + base + 2] + pe.z + bi.z;
            float go = Cs[base + 3] + Cs[1024 + base + 3] + pe.w + bi.w;
            float c = g_c0s[pb * 512 + pd];
            c = sig_acc(gf) * c + sig_acc(gi) * tanhf(gg);
            float h = sig_acc(go) * tanhf(c);
            g_c0s[pb * 512 + pd] = c;
            g_x1buf[tc][pb * 1024 + pd] = h;
            g_h0buf[tp][pb * 512 + pd] = h;
        }
        gsync();

        // ---- phase 2: gates1 = [h0_new|h1_prev] @ W1slice -> LSTM1 ----
        {
            const float* Ap = g_x1buf[tc];
            float4 r[4];
#pragma unroll
            for (int j = 0; j < 4; j++)
                r[j] = __ldcg((const float4*)(Ap + (am + j * 16) * 1024 + ak4 * 4));
            wmma::fragment<wmma::accumulator, 16, 16, 8, float> acc;
            wmma::fill_fragment(acc, 0.0f);
#pragma unroll 1
            for (int ch = 0; ch < 16; ch++) {
#pragma unroll
                for (int j = 0; j < 4; j++)
                    *(float4*)&As[(am + j * 16) * 68 + ak4 * 4] = r[j];
                __syncthreads();
                if (ch < 15) {
#pragma unroll
                    for (int j = 0; j < 4; j++)
                        r[j] = __ldcg((const float4*)(Ap + (am + j * 16) * 1024 + (ch + 1) * 64 + ak4 * 4));
                }
#pragma unroll
                for (int q = 0; q < 4; q++) {
                    int kf = kh * 4 + q;
                    wmma::fragment<wmma::matrix_a, 16, 16, 8, wmma::precision::tf32, wmma::row_major> af;
                    wmma::fragment<wmma::matrix_b, 16, 16, 8, wmma::precision::tf32, wmma::row_major> bf;
                    wmma::load_matrix_sync(af, &As[(mt * 16) * 68 + kf * 8], 68);
                    frag_tf32(af);
                    wmma::load_matrix_sync(bf, &W1s[(ch * 64 + kf * 8) * 16], 16);
                    frag_tf32(bf);
                    wmma::mma_sync(acc, af, bf, acc);
                }
                __syncthreads();
            }
            wmma::store_matrix_sync(&Cs[warp * 256], acc, 16, wmma::mem_row_major);
            __syncthreads();

            float4 bi = *(const float4*)&g_b1i[n0 + pdl * 4];
            int base = pmt * 256 + pr * 16 + pdl * 4;
            float gi = Cs[base + 0] + Cs[1024 + base + 0] + bi.x;
            float gf = Cs[base + 1] + Cs[1024 + base + 1] + bi.y;
            float gg = Cs[base + 2] + Cs[1024 + base + 2] + bi.z;
            float go = Cs[base + 3] + Cs[1024 + base + 3] + bi.w;
            float c = g_c1s[pb * 512 + pd];
            c = sig_acc(gf) * c + sig_acc(gi) * tanhf(gg);
            float h = sig_acc(go) * tanhf(c);
            g_c1s[pb * 512 + pd] = c;
            g_x1buf[tp][pb * 1024 + 512 + pd] = h;
            g_h1all[(t * 64 + pb) * 512 + pd] = h;
        }
        gsync();
    }
}

// ---------------- epilogue: e_h = h1all @ elwT ----------------
__global__ __launch_bounds__(256) void k_eh() {
    __shared__ float As[64 * 36];
    __shared__ float Bs[32 * 128];
    const int tid = threadIdx.x;
    const int warp = tid >> 5;
    const int wm = warp >> 2, wn = warp & 3;
    const int n0 = blockIdx.x * 128, m0 = blockIdx.y * 64;
    wmma::fragment<wmma::accumulator, 16, 16, 8, float> acc[2][2];
#pragma unroll
    for (int i = 0; i < 2; i++)
#pragma unroll
        for (int j = 0; j < 2; j++) wmma::fill_fragment(acc[i][j], 0.0f);
    for (int kt = 0; kt < 512; kt += 32) {
        for (int i = tid; i < 2048; i += 256) {
            int m = i >> 5, k = i & 31;
            As[m * 36 + k] = g_h1all[(m0 + m) * 512 + kt + k];
        }
        for (int i = tid; i < 4096; i += 256) {
            int k = i >> 7, n = i & 127;
            Bs[i] = g_elwT[(kt + k) * 256 + n0 + n];
        }
        __syncthreads();
#pragma unroll
        for (int kf = 0; kf < 4; kf++) {
            wmma::fragment<wmma::matrix_a, 16, 16, 8, wmma::precision::tf32, wmma::row_major> af[2];
            wmma::fragment<wmma::matrix_b, 16, 16, 8, wmma::precision::tf32, wmma::row_major> bf[2];
#pragma unroll
            for (int i = 0; i < 2; i++) {
                wmma::load_matrix_sync(af[i], &As[(wm * 32 + i * 16) * 36 + kf * 8], 36);
                frag_tf32(af[i]);
            }
#pragma unroll
            for (int j = 0; j < 2; j++) {
                wmma::load_matrix_sync(bf[j], &Bs[kf * 8 * 128 + wn * 32 + j * 16], 128);
                frag_tf32(bf[j]);
            }
#pragma unroll
            for (int i = 0; i < 2; i++)
#pragma unroll
                for (int j = 0; j < 2; j++)
                    wmma::mma_sync(acc[i][j], af[i], bf[j], acc[i][j]);
        }
        __syncthreads();
    }
#pragma unroll
    for (int i = 0; i < 2; i++)
#pragma unroll
        for (int j = 0; j < 2; j++)
            wmma::store_matrix_sync(g_eh + (m0 + wm * 32 + i * 16) * 256 + n0 + wn * 32 + j * 16,
                                    acc[i][j], 256, wmma::mem_row_major);
}

// ---------------- epilogue: scores + softmax + masks ----------------
__global__ __launch_bounds__(256) void k_scores(const float* __restrict__ elb,
                                                const float* __restrict__ efb,
                                                const float* __restrict__ aw,
                                                const float* __restrict__ ab,
                                                float* __restrict__ out) {
    const int t = blockIdx.x, b = blockIdx.y;
    const int tid = threadIdx.x;
    __shared__ float ehs[256], aws[256];
    __shared__ float red[8], red2[8], fin[2];
    ehs[tid] = g_eh[(t * 64 + b) * 256 + tid] + elb[tid] + efb[tid];
    aws[tid] = aw[tid];
    __syncthreads();
    float sc = ab[0];
    {
        const float* ef = g_efmap + b * 65536 + tid;
#pragma unroll 8
        for (int a = 0; a < 256; a++) sc += aws[a] * tanh_fast(ehs[a] + ef[a * 256]);
    }
    const int wp = tid >> 5, lane = tid & 31;
    float m = sc;
#pragma unroll
    for (int o = 16; o; o >>= 1) m = fmaxf(m, __shfl_xor_sync(0xffffffffu, m, o));
    if (lane == 0) red[wp] = m;
    __syncthreads();
    if (tid == 0) {
        float v = red[0];
#pragma unroll
        for (int i = 1; i < 8; i++) v = fmaxf(v, red[i]);
        fin[0] = v;
    }
    __syncthreads();
    float e = expf(sc - fin[0]);
    float s = e;
#pragma unroll
    for (int o = 16; o; o >>= 1) s += __shfl_xor_sync(0xffffffffu, s, o);
    if (lane == 0) red2[wp] = s;
    __syncthreads();
    if (tid == 0) {
        float v = 0;
#pragma unroll
        for (int i = 0; i < 8; i++) v += red2[i];
        fin[1] = v;
    }
    __syncthreads();
    out[194432 + (b * 31 + t) * 256 + tid] = e / fin[1];
}

// ---------------- epilogue: glimpse v2 (exact fp32, broadcast masks) ----------------
// grid (2 t-half, 64 b), 128 threads; thread owns 4 contiguous channels.
__global__ __launch_bounds__(128) void k_glimpse(float* __restrict__ out) {
    __shared__ float ms[16 * 256];
    const int th = blockIdx.x, b = blockIdx.y;
    const int tid = threadIdx.x;
    const int nt = (th == 0) ? 16 : 15;
    for (int i = tid; i < 16 * 256; i += 128) {
        int tt = i >> 8;
        ms[i] = (tt < nt) ? out[194432 + (b * 31 + th * 16 + tt) * 256 + (i & 255)] : 0.0f;
    }
    __syncthreads();
    const int c = tid * 4;
    float4 acc[16];
#pragma unroll
    for (int tt = 0; tt < 16; tt++) acc[tt] = make_float4(0.f, 0.f, 0.f, 0.f);
    const float* fp = g_fmapT + b * 131072 + c;
#pragma unroll 4
    for (int hw = 0; hw < 256; hw++) {
        float4 f = *(const float4*)(fp + hw * 512);
#pragma unroll
        for (int tt = 0; tt < 16; tt++) {
            float m = ms[tt * 256 + hw];
            acc[tt].x += f.x * m; acc[tt].y += f.y * m;
            acc[tt].z += f.z * m; acc[tt].w += f.w * m;
        }
    }
#pragma unroll
    for (int tt = 0; tt < 16; tt++)
        if (tt < nt)
            *(float4*)&out[702336 + (b * 31 + th * 16 + tt) * 512 + c] = acc[tt];
}

// ---------------- epilogue: fc logits ----------------
__global__ __launch_bounds__(256) void k_fc(const float* __restrict__ fcb,
                                            float* __restrict__ out) {
    __shared__ float smem[8192];
    float* As = smem;
    float* Bs = smem + 2304;
    const int t = blockIdx.x;
    const int tid = threadIdx.x;
    const int warp = tid >> 5;
    const int wm = warp >> 2, wn = warp & 3;
    wmma::fragment<wmma::accumulator, 16, 16, 8, float> acc[2][2];
#pragma unroll
    for (int i = 0; i < 2; i++)
#pragma unroll
        for (int j = 0; j < 2; j++) wmma::fill_fragment(acc[i][j], 0.0f);
    for (int kt = 0; kt < 1024; kt += 32) {
        for (int i = tid; i < 2048; i += 256) {
            int m = i >> 5, k = i & 31;
            int kk = kt + k;
            As[m * 36 + k] = (kk < 512) ? g_h1all[(t * 64 + m) * 512 + kk]
                                        : out[702336 + (m * 31 + t) * 512 + kk - 512];
        }
        for (int i = tid; i < 4096; i += 256) {
            int k = i >> 7, n = i & 127;
            Bs[i] = g_fcTp[(kt + k) * 128 + n];
        }
        __syncthreads();
#pragma unroll
        for (int kf = 0; kf < 4; kf++) {
            wmma::fragment<wmma::matrix_a, 16, 16, 8, wmma::precision::tf32, wmma::row_major> af[2];
            wmma::fragment<wmma::matrix_b, 16, 16, 8, wmma::precision::tf32, wmma::row_major> bf[2];
#pragma unroll
            for (int i = 0; i < 2; i++) {
                wmma::load_matrix_sync(af[i], &As[(wm * 32 + i * 16) * 36 + kf * 8], 36);
                frag_tf32(af[i]);
            }
#pragma unroll
            for (int j = 0; j < 2; j++) {
                wmma::load_matrix_sync(bf[j], &Bs[kf * 8 * 128 + wn * 32 + j * 16], 128);
                frag_tf32(bf[j]);
            }
#pragma unroll
            for (int i = 0; i < 2; i++)
#pragma unroll
                for (int j = 0; j < 2; j++)
                    wmma::mma_sync(acc[i][j], af[i], bf[j], acc[i][j]);
        }
        __syncthreads();
    }
    float* Cs = smem;
#pragma unroll
    for (int i = 0; i < 2; i++)
#pragma unroll
        for (int j = 0; j < 2; j++)
            wmma::store_matrix_sync(&Cs[(wm * 32 + i * 16) * 128 + wn * 32 + j * 16],
                                    acc[i][j], 128, wmma::mem_row_major);
    __syncthreads();
    for (int i = tid; i < 64 * 98; i += 256) {
        int m = i / 98, j = i % 98;
        out[(m * 31 + t) * 98 + j] = Cs[m * 128 + j] + fcb[j];
    }
}

// ---------------- launch ----------------
extern "C" void kernel_launch(void* const* d_in, const int* in_sizes, int n_in,
                              void* d_out, int out_size) {
    const float* fmap   = (const float*)d_in[0];
    const float* h0     = (const float*)d_in[1];
    const float* c0     = (const float*)d_in[2];
    const int*   target = (const int*)d_in[3];
    const float* emb    = (const float*)d_in[5];
    const float* Wih0   = (const float*)d_in[6];
    const float* Whh0   = (const float*)d_in[7];
    const float* bih0   = (const float*)d_in[8];
    const float* bhh0   = (const float*)d_in[9];
    const float* Wih1   = (const float*)d_in[10];
    const float* Whh1   = (const float*)d_in[11];
    const float* bih1   = (const float*)d_in[12];
    const float* bhh1   = (const float*)d_in[13];
    const float* elw    = (const float*)d_in[14];
    const float* elb    = (const float*)d_in[15];
    const float* efw    = (const float*)d_in[16];
    const float* efb    = (const float*)d_in[17];
    const float* aw     = (const float*)d_in[18];
    const float* ab     = (const float*)d_in[19];
    const float* fcw    = (const float*)d_in[20];
    const float* fcb    = (const float*)d_in[21];
    float* out = (float*)d_out;

    const int SMEM_STEPS = (8192 + 16384 + 4352 + 2048) * 4;   // 123904
    const int SMEM_CONV  = (4352 + 8192) * 4;                  // 50176
    static int configured = 0;
    if (!configured) {
        cudaFuncSetAttribute(k_steps, cudaFuncAttributeMaxDynamicSharedMemorySize, SMEM_STEPS);
        cudaFuncSetAttribute(k_conv, cudaFuncAttributeMaxDynamicSharedMemorySize, SMEM_CONV);
        configured = 1;
    }

    k_transpose<<<dim3(512, 6), 256>>>(Wih0, Whh0, Wih1, Whh1, efw, elw, fcw, fmap,
                                       bih0, bhh0, bih1, bhh1);
    k_init2<<<(1984 * 256 + 131072 + 255) / 256, 256>>>(h0, c0, emb, target);
    k_preemb<<<dim3(16, 31), 256>>>();
    k_conv<<<dim3(2, 4, 64), 256, SMEM_CONV>>>();
    k_steps<<<GBLK, 256, SMEM_STEPS>>>();
    k_eh<<<dim3(2, 31), 256>>>();
    k_scores<<<dim3(31, 64), 256>>>(elb, efb, aw, ab, out);
    k_glimpse<<<dim3(2, 64), 128>>>(out);
    k_fc<<<31, 256>>>(fcb, out);
}

// round 6
// speedup vs baseline: 4.4360x; 1.2221x over previous
#include <cuda_runtime.h>
#include <cuda_fp16.h>
#include <mma.h>
#include <math.h>

using namespace nvcuda;

#define TSTEPS 31
#define GBLK 128

// ---------------- scratch ----------------
__device__ __half g_W0h[512 * 2048];         // [k][n] n = d*4+g interleaved (Whh0)
__device__ __half g_W1h[1024 * 2048];        // [k][n] k: [h0_new|h1_prev]
__device__ float g_Wemb[256 * 2048];         // [k][n] (Wih0) fp32/tf32
__device__ float g_b0i[2048];
__device__ float g_b1i[2048];
__device__ __half g_convWH[9 * 512 * 256];   // [tap][c][attn]
__device__ float g_elwT[512 * 256];          // [k][attn]
__device__ float g_fcTp[1024 * 128];         // [k][class padded]
__device__ float g_fmapT[64 * 256 * 512];    // [b][hw][c] fp32 (glimpse)
__device__ __half g_fmapTh[64 * 256 * 512];  // half copy (conv)
__device__ float g_efmap[64 * 256 * 256];    // [b][attn][hw] (no bias)
__device__ float g_E[1984 * 256];            // emb_seq rows (t*64+b)
__device__ float g_pre[1984 * 2048];         // emb @ Wih0^T, interleaved cols
__device__ __half g_h0h[2][64 * 512];
__device__ __half g_x1h[2][64 * 1024];       // [h0_new | h1_prev]
__device__ float g_c0s[64 * 512];
__device__ float g_c1s[64 * 512];
__device__ float g_h1all[1984 * 512];        // rows (t*64+b)
__device__ float g_eh[1984 * 256];
__device__ unsigned g_barc = 0;
__device__ volatile unsigned g_barg = 0;

__device__ __forceinline__ float tanh_fast(float x) {
    float y; asm("tanh.approx.f32 %0, %1;" : "=f"(y) : "f"(x)); return y;
}
__device__ __forceinline__ float sig_acc(float x) { return 1.0f / (1.0f + expf(-x)); }

template <class F>
__device__ __forceinline__ void frag_tf32(F& f) {
#pragma unroll
    for (int i = 0; i < f.num_elements; i++) f.x[i] = wmma::__float_to_tf32(f.x[i]);
}

__device__ __forceinline__ void gsync() {
    __syncthreads();
    if (threadIdx.x == 0) {
        __threadfence();
        unsigned gen = g_barg;
        if (atomicAdd(&g_barc, 1u) == GBLK - 1u) {
            g_barc = 0;
            __threadfence();
            g_barg = gen + 1u;
        } else {
            while (g_barg == gen) { }
            __threadfence();
        }
    }
    __syncthreads();
}

// ---------------- setup: repacks ----------------
__global__ void k_transpose(const float* __restrict__ Wih0, const float* __restrict__ Whh0,
                            const float* __restrict__ Wih1, const float* __restrict__ Whh1,
                            const float* __restrict__ efw, const float* __restrict__ elw,
                            const float* __restrict__ fcw, const float* __restrict__ fmap,
                            const float* __restrict__ bih0, const float* __restrict__ bhh0,
                            const float* __restrict__ bih1, const float* __restrict__ bhh1) {
    const int y = blockIdx.y;
    const int stride = gridDim.x * blockDim.x;
    const int i0 = blockIdx.x * blockDim.x + threadIdx.x;
    if (y == 0) {
        for (int i = i0; i < 512 * 2048; i += stride) {
            int k = i >> 11, n = i & 2047;
            int col = (n & 3) * 512 + (n >> 2);
            g_W0h[i] = __float2half(Whh0[col * 512 + k]);
        }
        for (int i = i0; i < 2048; i += stride) {
            int col = (i & 3) * 512 + (i >> 2);
            g_b0i[i] = bih0[col] + bhh0[col];
            g_b1i[i] = bih1[col] + bhh1[col];
        }
    } else if (y == 1) {
        for (int i = i0; i < 1024 * 2048; i += stride) {
            int k = i >> 11, n = i & 2047;
            int col = (n & 3) * 512 + (n >> 2);
            g_W1h[i] = __float2half((k < 512) ? Wih1[col * 512 + k] : Whh1[col * 512 + (k - 512)]);
        }
    } else if (y == 2) {
        for (int i = i0; i < 256 * 2048; i += stride) {
            int k = i >> 11, n = i & 2047;
            int col = (n & 3) * 512 + (n >> 2);
            g_Wemb[i] = Wih0[col * 256 + k];
        }
    } else if (y == 3) {
        for (int i = i0; i < 9 * 512 * 256; i += stride) {
            int tap = i >> 17, rem = i & 131071;
            int c = rem >> 8, a = rem & 255;
            g_convWH[i] = __float2half(efw[a * 4608 + c * 9 + tap]);
        }
    } else if (y == 4) {
        for (int i = i0; i < 512 * 256; i += stride) {
            int k = i >> 8, a = i & 255;
            g_elwT[i] = elw[a * 512 + k];
        }
        for (int i = i0; i < 1024 * 128; i += stride) {
            int k = i >> 7, j = i & 127;
            g_fcTp[i] = (j < 98) ? fcw[j * 1024 + k] : 0.0f;
        }
    } else {
        for (int i = i0; i < 64 * 256 * 512; i += stride) {
            int b = i >> 17, rem = i & 131071;
            int hw = rem >> 9, c = rem & 511;
            float v = fmap[b * 131072 + c * 256 + hw];
            g_fmapT[i] = v;
            g_fmapTh[i] = __float2half(v);
        }
    }
}

__global__ void k_init2(const float* __restrict__ h0, const float* __restrict__ c0,
                        const float* __restrict__ emb, const int* __restrict__ target) {
    int idx = blockIdx.x * blockDim.x + threadIdx.x;
    const int SE = 1984 * 256;
    if (idx < SE) {
        int t = idx >> 14, rem = idx & 16383;
        int b = rem >> 8, k = rem & 255;
        int lab = (t == 0) ? 0 : target[b * 30 + t - 1];
        g_E[idx] = emb[lab * 256 + k];
    } else {
        int r = idx - SE;
        if (r < 32768) {
            g_h0h[0][r] = __float2half(h0[r]);
        } else if (r < 65536) {
            int q = r - 32768; int b = q >> 9, d = q & 511;
            g_x1h[0][b * 1024 + 512 + d] = __float2half(h0[32768 + q]);
        } else if (r < 98304) {
            g_c0s[r - 65536] = c0[r - 65536];
        } else if (r < 131072) {
            g_c1s[r - 98304] = c0[32768 + (r - 98304)];
        }
    }
}

// ---------------- pre-embedding GEMM: g_pre = E @ Wemb (tf32) ----------------
__global__ __launch_bounds__(256) void k_preemb() {
    __shared__ float As[64 * 36];
    __shared__ float Bs[32 * 128];
    const int tid = threadIdx.x;
    const int warp = tid >> 5;
    const int wm = warp >> 2, wn = warp & 3;
    const int n0 = blockIdx.x * 128, m0 = blockIdx.y * 64;
    wmma::fragment<wmma::accumulator, 16, 16, 8, float> acc[2][2];
#pragma unroll
    for (int i = 0; i < 2; i++)
#pragma unroll
        for (int j = 0; j < 2; j++) wmma::fill_fragment(acc[i][j], 0.0f);
    for (int kt = 0; kt < 256; kt += 32) {
        for (int i = tid; i < 2048; i += 256) {
            int m = i >> 5, k = i & 31;
            As[m * 36 + k] = g_E[(m0 + m) * 256 + kt + k];
        }
        for (int i = tid; i < 4096; i += 256) {
            int k = i >> 7, n = i & 127;
            Bs[i] = g_Wemb[(kt + k) * 2048 + n0 + n];
        }
        __syncthreads();
#pragma unroll
        for (int kf = 0; kf < 4; kf++) {
            wmma::fragment<wmma::matrix_a, 16, 16, 8, wmma::precision::tf32, wmma::row_major> af[2];
            wmma::fragment<wmma::matrix_b, 16, 16, 8, wmma::precision::tf32, wmma::row_major> bf[2];
#pragma unroll
            for (int i = 0; i < 2; i++) {
                wmma::load_matrix_sync(af[i], &As[(wm * 32 + i * 16) * 36 + kf * 8], 36);
                frag_tf32(af[i]);
            }
#pragma unroll
            for (int j = 0; j < 2; j++) {
                wmma::load_matrix_sync(bf[j], &Bs[kf * 8 * 128 + wn * 32 + j * 16], 128);
                frag_tf32(bf[j]);
            }
#pragma unroll
            for (int i = 0; i < 2; i++)
#pragma unroll
                for (int j = 0; j < 2; j++)
                    wmma::mma_sync(acc[i][j], af[i], bf[j], acc[i][j]);
        }
        __syncthreads();
    }
#pragma unroll
    for (int i = 0; i < 2; i++)
#pragma unroll
        for (int j = 0; j < 2; j++)
            wmma::store_matrix_sync(g_pre + (m0 + wm * 32 + i * 16) * 2048 + n0 + wn * 32 + j * 16,
                                    acc[i][j], 2048, wmma::mem_row_major);
}

// ---------------- conv v3: fp16 tap-major implicit GEMM ----------------
// grid (2 ntile, 4 mtile, 64 b), 256 thr. Tile M64 x N128, K=4608 in 72 chunks of 64.
__global__ __launch_bounds__(256) void k_conv() {
    extern __shared__ __half csm[];
    __half* As = csm;            // 64*72 = 4608 halves (9216 B)
    __half* Bs = csm + 4608;     // 64*128 = 8192 halves (16384 B)
    const int tid = threadIdx.x;
    const int warp = tid >> 5;
    const int wm = warp >> 2, wn = warp & 3;
    const int n0 = blockIdx.x * 128;
    const int s0 = blockIdx.y * 64;
    const int b = blockIdx.z;
    const __half* fTh = g_fmapTh + b * 131072;

    wmma::fragment<wmma::accumulator, 16, 16, 16, float> acc[2][2];
#pragma unroll
    for (int i = 0; i < 2; i++)
#pragma unroll
        for (int j = 0; j < 2; j++) wmma::fill_fragment(acc[i][j], 0.0f);

    uint4 rA[2], rB[4];
    const uint4 z4 = make_uint4(0u, 0u, 0u, 0u);

    auto loadA = [&](int q) {
        int tap = q >> 3, cch = q & 7;
        int dy = tap / 3 - 1, dx = tap % 3 - 1;
#pragma unroll
        for (int j = 0; j < 2; j++) {
            int u = tid + j * 256;
            int row = u >> 3, seg = u & 7;
            int s = s0 + row;
            int yy = (s >> 5) + dy, xx = (s & 31) + dx;
            bool ok = (yy >= 0) && (yy < 8) && (xx >= 0) && (xx < 32);
            rA[j] = ok ? *(const uint4*)(fTh + (yy * 32 + xx) * 512 + cch * 64 + seg * 8) : z4;
        }
    };
    auto loadB = [&](int q) {
        int tap = q >> 3, cch = q & 7;
        const __half* src = g_convWH + (tap * 512 + cch * 64) * 256 + n0;
#pragma unroll
        for (int j = 0; j < 4; j++) {
            int u = tid + j * 256;
            rB[j] = *(const uint4*)(src + (u >> 4) * 256 + (u & 15) * 8);
        }
    };

    loadA(0); loadB(0);
#pragma unroll 1
    for (int q = 0; q < 72; q++) {
#pragma unroll
        for (int j = 0; j < 2; j++) {
            int u = tid + j * 256;
            *(uint4*)&As[(u >> 3) * 72 + (u & 7) * 8] = rA[j];
        }
#pragma unroll
        for (int j = 0; j < 4; j++) {
            int u = tid + j * 256;
            *(uint4*)&Bs[(u >> 4) * 128 + (u & 15) * 8] = rB[j];
        }
        __syncthreads();
        if (q < 71) { loadA(q + 1); loadB(q + 1); }
#pragma unroll
        for (int kf = 0; kf < 4; kf++) {
            wmma::fragment<wmma::matrix_a, 16, 16, 16, __half, wmma::row_major> af[2];
            wmma::fragment<wmma::matrix_b, 16, 16, 16, __half, wmma::row_major> bf[2];
#pragma unroll
            for (int i = 0; i < 2; i++)
                wmma::load_matrix_sync(af[i], &As[(wm * 32 + i * 16) * 72 + kf * 16], 72);
#pragma unroll
            for (int j = 0; j < 2; j++)
                wmma::load_matrix_sync(bf[j], &Bs[(kf * 16) * 128 + wn * 32 + j * 16], 128);
#pragma unroll
            for (int i = 0; i < 2; i++)
#pragma unroll
                for (int j = 0; j < 2; j++)
                    wmma::mma_sync(acc[i][j], af[i], bf[j], acc[i][j]);
        }
        __syncthreads();
    }
    float* eb = g_efmap + b * 65536;
#pragma unroll
    for (int i = 0; i < 2; i++)
#pragma unroll
        for (int j = 0; j < 2; j++)
            wmma::store_matrix_sync(eb + (n0 + wn * 32 + j * 16) * 256 + s0 + wm * 32 + i * 16,
                                    acc[i][j], 256, wmma::mem_col_major);
}

// ---------------- persistent recurrence (fp16 GEMM, full-A staging) ----------------
__global__ __launch_bounds__(256)
void k_steps() {
    extern __shared__ char smc[];
    __half* Ah  = (__half*)smc;                          // up to 66048 halves (132096 B)
    __half* W0s = (__half*)(smc + 132096);               // 8192 halves
    __half* W1s = (__half*)(smc + 132096 + 16384);       // 16384 halves
    float*  Cs  = (float*)(smc + 132096 + 16384 + 32768);// 2048 floats
    const int tid = threadIdx.x;
    const int bid = blockIdx.x;
    const int warp = tid >> 5;
    const int mt = warp & 3, kh = warp >> 2;
    const int n0 = bid * 16;

    // stage weight slices (half)
    for (int j = 0; j < 4; j++) {
        int u = tid + j * 256;                 // 1024 uint4
        int k = u >> 1, s = u & 1;
        *(uint4*)&W0s[k * 16 + s * 8] = *(const uint4*)(g_W0h + k * 2048 + n0 + s * 8);
    }
    for (int j = 0; j < 8; j++) {
        int u = tid + j * 256;                 // 2048 uint4
        int k = u >> 1, s = u & 1;
        *(uint4*)&W1s[k * 16 + s * 8] = *(const uint4*)(g_W1h + k * 2048 + n0 + s * 8);
    }
    __syncthreads();

    const int pb = tid >> 2, pdl = tid & 3;
    const int pr = pb & 15, pmt = pb >> 4;
    const int pd = bid * 4 + pdl;

    for (int t = 0; t < TSTEPS; t++) {
        const int tc = t & 1, tp = tc ^ 1;

        // ---- phase 1: gates0 = h0_prev @ Whh0slice (+pre) -> LSTM0 ----
        {
            const __half* Ag = g_h0h[tc];
#pragma unroll
            for (int j = 0; j < 16; j++) {     // 4096 uint4 = 64x512 halves
                int u = tid + j * 256;
                int row = u >> 6, seg = u & 63;
                *(uint4*)&Ah[row * 520 + seg * 8] =
                    __ldcg((const uint4*)(Ag + row * 512 + seg * 8));
            }
            __syncthreads();
            wmma::fragment<wmma::accumulator, 16, 16, 16, float> a0, a1;
            wmma::fill_fragment(a0, 0.0f);
            wmma::fill_fragment(a1, 0.0f);
#pragma unroll
            for (int q = 0; q < 16; q++) {     // 32 kf total, split by kh
                int kf = kh * 16 + q;
                wmma::fragment<wmma::matrix_a, 16, 16, 16, __half, wmma::row_major> af;
                wmma::fragment<wmma::matrix_b, 16, 16, 16, __half, wmma::row_major> bf;
                wmma::load_matrix_sync(af, &Ah[(mt * 16) * 520 + kf * 16], 520);
                wmma::load_matrix_sync(bf, &W0s[(kf * 16) * 16], 16);
                if (q & 1) wmma::mma_sync(a1, af, bf, a1);
                else       wmma::mma_sync(a0, af, bf, a0);
            }
#pragma unroll
            for (int i = 0; i < a0.num_elements; i++) a0.x[i] += a1.x[i];
            wmma::store_matrix_sync(&Cs[warp * 256], a0, 16, wmma::mem_row_major);
            __syncthreads();

            float4 pe = *(const float4*)&g_pre[(t * 64 + pb) * 2048 + n0 + pdl * 4];
            float4 bi = *(const float4*)&g_b0i[n0 + pdl * 4];
            int base = pmt * 256 + pr * 16 + pdl * 4;
            float gi = Cs[base + 0] + Cs[1024 + base + 0] + pe.x + bi.x;
            float gf = Cs[base + 1] + Cs[1024 + base + 1] + pe.y + bi.y;
            float gg = Cs[base + 2] + Cs[1024 + base + 2] + pe.z + bi.z;
            float go = Cs[base + 3] + Cs[1024 + base + 3] + pe.w + bi.w;
            float c = g_c0s[pb * 512 + pd];
            c = sig_acc(gf) * c + sig_acc(gi) * tanhf(gg);
            float h = sig_acc(go) * tanhf(c);
            g_c0s[pb * 512 + pd] = c;
            __half hh = __float2half(h);
            g_x1h[tc][pb * 1024 + pd] = hh;
            g_h0h[tp][pb * 512 + pd] = hh;
        }
        gsync();

        // ---- phase 2: gates1 = [h0_new|h1_prev] @ W1slice -> LSTM1 ----
        {
            const __half* Ag = g_x1h[tc];
#pragma unroll
            for (int j = 0; j < 32; j++) {     // 8192 uint4 = 64x1024 halves
                int u = tid + j * 256;
                int row = u >> 7, seg = u & 127;
                *(uint4*)&Ah[row * 1032 + seg * 8] =
                    __ldcg((const uint4*)(Ag + row * 1024 + seg * 8));
            }
            __syncthreads();
            wmma::fragment<wmma::accumulator, 16, 16, 16, float> a0, a1;
            wmma::fill_fragment(a0, 0.0f);
            wmma::fill_fragment(a1, 0.0f);
#pragma unroll
            for (int q = 0; q < 32; q++) {     // 64 kf total
                int kf = kh * 32 + q;
                wmma::fragment<wmma::matrix_a, 16, 16, 16, __half, wmma::row_major> af;
                wmma::fragment<wmma::matrix_b, 16, 16, 16, __half, wmma::row_major> bf;
                wmma::load_matrix_sync(af, &Ah[(mt * 16) * 1032 + kf * 16], 1032);
                wmma::load_matrix_sync(bf, &W1s[(kf * 16) * 16], 16);
                if (q & 1) wmma::mma_sync(a1, af, bf, a1);
                else       wmma::mma_sync(a0, af, bf, a0);
            }
#pragma unroll
            for (int i = 0; i < a0.num_elements; i++) a0.x[i] += a1.x[i];
            wmma::store_matrix_sync(&Cs[warp * 256], a0, 16, wmma::mem_row_major);
            __syncthreads();

            float4 bi = *(const float4*)&g_b1i[n0 + pdl * 4];
            int base = pmt * 256 + pr * 16 + pdl * 4;
            float gi = Cs[base + 0] + Cs[1024 + base + 0] + bi.x;
            float gf = Cs[base + 1] + Cs[1024 + base + 1] + bi.y;
            float gg = Cs[base + 2] + Cs[1024 + base + 2] + bi.z;
            float go = Cs[base + 3] + Cs[1024 + base + 3] + bi.w;
            float c = g_c1s[pb * 512 + pd];
            c = sig_acc(gf) * c + sig_acc(gi) * tanhf(gg);
            float h = sig_acc(go) * tanhf(c);
            g_c1s[pb * 512 + pd] = c;
            g_x1h[tp][pb * 1024 + 512 + pd] = __float2half(h);
            g_h1all[(t * 64 + pb) * 512 + pd] = h;
        }
        gsync();
    }
}

// ---------------- epilogue: e_h = h1all @ elwT (tf32) ----------------
__global__ __launch_bounds__(256) void k_eh() {
    __shared__ float As[64 * 36];
    __shared__ float Bs[32 * 128];
    const int tid = threadIdx.x;
    const int warp = tid >> 5;
    const int wm = warp >> 2, wn = warp & 3;
    const int n0 = blockIdx.x * 128, m0 = blockIdx.y * 64;
    wmma::fragment<wmma::accumulator, 16, 16, 8, float> acc[2][2];
#pragma unroll
    for (int i = 0; i < 2; i++)
#pragma unroll
        for (int j = 0; j < 2; j++) wmma::fill_fragment(acc[i][j], 0.0f);
    for (int kt = 0; kt < 512; kt += 32) {
        for (int i = tid; i < 2048; i += 256) {
            int m = i >> 5, k = i & 31;
            As[m * 36 + k] = g_h1all[(m0 + m) * 512 + kt + k];
        }
        for (int i = tid; i < 4096; i += 256) {
            int k = i >> 7, n = i & 127;
            Bs[i] = g_elwT[(kt + k) * 256 + n0 + n];
        }
        __syncthreads();
#pragma unroll
        for (int kf = 0; kf < 4; kf++) {
            wmma::fragment<wmma::matrix_a, 16, 16, 8, wmma::precision::tf32, wmma::row_major> af[2];
            wmma::fragment<wmma::matrix_b, 16, 16, 8, wmma::precision::tf32, wmma::row_major> bf[2];
#pragma unroll
            for (int i = 0; i < 2; i++) {
                wmma::load_matrix_sync(af[i], &As[(wm * 32 + i * 16) * 36 + kf * 8], 36);
                frag_tf32(af[i]);
            }
#pragma unroll
            for (int j = 0; j < 2; j++) {
                wmma::load_matrix_sync(bf[j], &Bs[kf * 8 * 128 + wn * 32 + j * 16], 128);
                frag_tf32(bf[j]);
            }
#pragma unroll
            for (int i = 0; i < 2; i++)
#pragma unroll
                for (int j = 0; j < 2; j++)
                    wmma::mma_sync(acc[i][j], af[i], bf[j], acc[i][j]);
        }
        __syncthreads();
    }
#pragma unroll
    for (int i = 0; i < 2; i++)
#pragma unroll
        for (int j = 0; j < 2; j++)
            wmma::store_matrix_sync(g_eh + (m0 + wm * 32 + i * 16) * 256 + n0 + wn * 32 + j * 16,
                                    acc[i][j], 256, wmma::mem_row_major);
}

// ---------------- epilogue: scores + softmax (4 timesteps per block) ----------------
__global__ __launch_bounds__(256) void k_scores(const float* __restrict__ elb,
                                                const float* __restrict__ efb,
                                                const float* __restrict__ aw,
                                                const float* __restrict__ ab,
                                                float* __restrict__ out) {
    const int tg = blockIdx.x, b = blockIdx.y;
    const int nt = (tg < 7) ? 4 : 3;
    const int tid = threadIdx.x;
    __shared__ float ehs[4 * 256], aws[256];
    __shared__ float red[8], fin;
    const float bias = elb[tid] + efb[tid];
    for (int j = 0; j < 4; j++)
        ehs[j * 256 + tid] = (j < nt) ? g_eh[((tg * 4 + j) * 64 + b) * 256 + tid] + bias : 0.0f;
    aws[tid] = aw[tid];
    __syncthreads();

    float sc[4] = {ab[0], ab[0], ab[0], ab[0]};
    const float* ef = g_efmap + b * 65536 + tid;
#pragma unroll 4
    for (int a = 0; a < 256; a++) {
        float e = ef[a * 256];
        float w = aws[a];
        sc[0] += w * tanh_fast(ehs[a] + e);
        sc[1] += w * tanh_fast(ehs[256 + a] + e);
        sc[2] += w * tanh_fast(ehs[512 + a] + e);
        sc[3] += w * tanh_fast(ehs[768 + a] + e);
    }

    const int wp = tid >> 5, lane = tid & 31;
    for (int j = 0; j < nt; j++) {
        float m = sc[j];
#pragma unroll
        for (int o = 16; o; o >>= 1) m = fmaxf(m, __shfl_xor_sync(0xffffffffu, m, o));
        if (lane == 0) red[wp] = m;
        __syncthreads();
        if (tid == 0) {
            float v = red[0];
#pragma unroll
            for (int i = 1; i < 8; i++) v = fmaxf(v, red[i]);
            fin = v;
        }
        __syncthreads();
        float e = expf(sc[j] - fin);
        float s = e;
#pragma unroll
        for (int o = 16; o; o >>= 1) s += __shfl_xor_sync(0xffffffffu, s, o);
        if (lane == 0) red[wp] = s;
        __syncthreads();
        if (tid == 0) {
            float v = 0;
#pragma unroll
            for (int i = 0; i < 8; i++) v += red[i];
            fin = v;
        }
        __syncthreads();
        out[194432 + (b * 31 + tg * 4 + j) * 256 + tid] = e / fin;
        __syncthreads();
    }
}

// ---------------- epilogue: glimpse (exact fp32) ----------------
__global__ __launch_bounds__(128) void k_glimpse(float* __restrict__ out) {
    __shared__ float ms[16 * 256];
    const int th = blockIdx.x, b = blockIdx.y;
    const int tid = threadIdx.x;
    const int nt = (th == 0) ? 16 : 15;
    for (int i = tid; i < 16 * 256; i += 128) {
        int tt = i >> 8;
        ms[i] = (tt < nt) ? out[194432 + (b * 31 + th * 16 + tt) * 256 + (i & 255)] : 0.0f;
    }
    __syncthreads();
    const int c = tid * 4;
    float4 acc[16];
#pragma unroll
    for (int tt = 0; tt < 16; tt++) acc[tt] = make_float4(0.f, 0.f, 0.f, 0.f);
    const float* fp = g_fmapT + b * 131072 + c;
#pragma unroll 4
    for (int hw = 0; hw < 256; hw++) {
        float4 f = *(const float4*)(fp + hw * 512);
#pragma unroll
        for (int tt = 0; tt < 16; tt++) {
            float m = ms[tt * 256 + hw];
            acc[tt].x += f.x * m; acc[tt].y += f.y * m;
            acc[tt].z += f.z * m; acc[tt].w += f.w * m;
        }
    }
#pragma unroll
    for (int tt = 0; tt < 16; tt++)
        if (tt < nt)
            *(float4*)&out[702336 + (b * 31 + th * 16 + tt) * 512 + c] = acc[tt];
}

// ---------------- epilogue: fc logits (tf32) ----------------
__global__ __launch_bounds__(256) void k_fc(const float* __restrict__ fcb,
                                            float* __restrict__ out) {
    __shared__ float smem[8192];
    float* As = smem;
    float* Bs = smem + 2304;
    const int t = blockIdx.x;
    const int tid = threadIdx.x;
    const int warp = tid >> 5;
    const int wm = warp >> 2, wn = warp & 3;
    wmma::fragment<wmma::accumulator, 16, 16, 8, float> acc[2][2];
#pragma unroll
    for (int i = 0; i < 2; i++)
#pragma unroll
        for (int j = 0; j < 2; j++) wmma::fill_fragment(acc[i][j], 0.0f);
    for (int kt = 0; kt < 1024; kt += 32) {
        for (int i = tid; i < 2048; i += 256) {
            int m = i >> 5, k = i & 31;
            int kk = kt + k;
            As[m * 36 + k] = (kk < 512) ? g_h1all[(t * 64 + m) * 512 + kk]
                                        : out[702336 + (m * 31 + t) * 512 + kk - 512];
        }
        for (int i = tid; i < 4096; i += 256) {
            int k = i >> 7, n = i & 127;
            Bs[i] = g_fcTp[(kt + k) * 128 + n];
        }
        __syncthreads();
#pragma unroll
        for (int kf = 0; kf < 4; kf++) {
            wmma::fragment<wmma::matrix_a, 16, 16, 8, wmma::precision::tf32, wmma::row_major> af[2];
            wmma::fragment<wmma::matrix_b, 16, 16, 8, wmma::precision::tf32, wmma::row_major> bf[2];
#pragma unroll
            for (int i = 0; i < 2; i++) {
                wmma::load_matrix_sync(af[i], &As[(wm * 32 + i * 16) * 36 + kf * 8], 36);
                frag_tf32(af[i]);
            }
#pragma unroll
            for (int j = 0; j < 2; j++) {
                wmma::load_matrix_sync(bf[j], &Bs[kf * 8 * 128 + wn * 32 + j * 16], 128);
                frag_tf32(bf[j]);
            }
#pragma unroll
            for (int i = 0; i < 2; i++)
#pragma unroll
                for (int j = 0; j < 2; j++)
                    wmma::mma_sync(acc[i][j], af[i], bf[j], acc[i][j]);
        }
        __syncthreads();
    }
    float* Cs = smem;
#pragma unroll
    for (int i = 0; i < 2; i++)
#pragma unroll
        for (int j = 0; j < 2; j++)
            wmma::store_matrix_sync(&Cs[(wm * 32 + i * 16) * 128 + wn * 32 + j * 16],
                                    acc[i][j], 128, wmma::mem_row_major);
    __syncthreads();
    for (int i = tid; i < 64 * 98; i += 256) {
        int m = i / 98, j = i % 98;
        out[(m * 31 + t) * 98 + j] = Cs[m * 128 + j] + fcb[j];
    }
}

// ---------------- launch ----------------
extern "C" void kernel_launch(void* const* d_in, const int* in_sizes, int n_in,
                              void* d_out, int out_size) {
    const float* fmap   = (const float*)d_in[0];
    const float* h0     = (const float*)d_in[1];
    const float* c0     = (const float*)d_in[2];
    const int*   target = (const int*)d_in[3];
    const float* emb    = (const float*)d_in[5];
    const float* Wih0   = (const float*)d_in[6];
    const float* Whh0   = (const float*)d_in[7];
    const float* bih0   = (const float*)d_in[8];
    const float* bhh0   = (const float*)d_in[9];
    const float* Wih1   = (const float*)d_in[10];
    const float* Whh1   = (const float*)d_in[11];
    const float* bih1   = (const float*)d_in[12];
    const float* bhh1   = (const float*)d_in[13];
    const float* elw    = (const float*)d_in[14];
    const float* elb    = (const float*)d_in[15];
    const float* efw    = (const float*)d_in[16];
    const float* efb    = (const float*)d_in[17];
    const float* aw     = (const float*)d_in[18];
    const float* ab     = (const float*)d_in[19];
    const float* fcw    = (const float*)d_in[20];
    const float* fcb    = (const float*)d_in[21];
    float* out = (float*)d_out;

    const int SMEM_STEPS = 132096 + 16384 + 32768 + 8192;   // 189440
    const int SMEM_CONV  = (4608 + 8192) * 2;               // 25600
    static int configured = 0;
    if (!configured) {
        cudaFuncSetAttribute(k_steps, cudaFuncAttributeMaxDynamicSharedMemorySize, SMEM_STEPS);
        cudaFuncSetAttribute(k_conv, cudaFuncAttributeMaxDynamicSharedMemorySize, SMEM_CONV);
        configured = 1;
    }

    k_transpose<<<dim3(512, 6), 256>>>(Wih0, Whh0, Wih1, Whh1, efw, elw, fcw, fmap,
                                       bih0, bhh0, bih1, bhh1);
    k_init2<<<(1984 * 256 + 131072 + 255) / 256, 256>>>(h0, c0, emb, target);
    k_preemb<<<dim3(16, 31), 256>>>();
    k_conv<<<dim3(2, 4, 64), 256, SMEM_CONV>>>();
    k_steps<<<GBLK, 256, SMEM_STEPS>>>();
    k_eh<<<dim3(2, 31), 256>>>();
    k_scores<<<dim3(8, 64), 256>>>(elb, efb, aw, ab, out);
    k_glimpse<<<dim3(2, 64), 128>>>(out);
    k_fc<<<31, 256>>>(fcb, out);
}

// round 7
// speedup vs baseline: 8.2923x; 1.8693x over previous
#include <cuda_runtime.h>
#include <cuda_fp16.h>
#include <mma.h>
#include <math.h>

using namespace nvcuda;

#define TSTEPS 31
#define GBLK 128

// ---------------- scratch ----------------
__device__ __half g_W0h[512 * 2048];         // [k][n] n = d*4+g interleaved (Whh0)
__device__ __half g_W1h[1024 * 2048];        // [k][n] k: [h0_new|h1_prev]
__device__ float g_Wemb[256 * 2048];         // [k][n] (Wih0) fp32/tf32
__device__ float g_b0i[2048];
__device__ float g_b1i[2048];
__device__ __half g_convWH[9 * 512 * 256];   // [tap][c][attn]
__device__ float g_elwT[512 * 256];          // [k][attn]
__device__ float g_fcTp[1024 * 128];         // [k][class padded]
__device__ float g_fmapT[64 * 256 * 512];    // [b][hw][c] fp32 (glimpse)
__device__ __half g_fmapTh[64 * 256 * 512];  // half copy (conv)
__device__ float g_efmap[64 * 256 * 256];    // [b][attn][hw] (no bias)
__device__ float g_E[1984 * 256];            // emb_seq rows (t*64+b)
__device__ float g_pre[1984 * 2048];         // emb @ Wih0^T, interleaved cols
__device__ __half g_h0h[2][64 * 512];
__device__ __half g_x1h[2][64 * 1024];       // [h0_new | h1_prev]
__device__ float g_c0s[64 * 512];
__device__ float g_c1s[64 * 512];
__device__ float g_h1all[1984 * 512];        // rows (t*64+b)
__device__ float g_eh[1984 * 256];
__device__ unsigned g_barc = 0;
__device__ volatile unsigned g_barg = 0;

__device__ __forceinline__ float tanh_fast(float x) {
    float y; asm("tanh.approx.f32 %0, %1;" : "=f"(y) : "f"(x)); return y;
}
__device__ __forceinline__ float sig_acc(float x) { return 1.0f / (1.0f + expf(-x)); }

template <class F>
__device__ __forceinline__ void frag_tf32(F& f) {
#pragma unroll
    for (int i = 0; i < f.num_elements; i++) f.x[i] = wmma::__float_to_tf32(f.x[i]);
}

__device__ __forceinline__ void gsync() {
    __syncthreads();
    if (threadIdx.x == 0) {
        __threadfence();
        unsigned gen = g_barg;
        if (atomicAdd(&g_barc, 1u) == GBLK - 1u) {
            g_barc = 0;
            __threadfence();
            g_barg = gen + 1u;
        } else {
            while (g_barg == gen) { }
            __threadfence();
        }
    }
    __syncthreads();
}

// ---------------- setup: repacks ----------------
__global__ void k_transpose(const float* __restrict__ Wih0, const float* __restrict__ Whh0,
                            const float* __restrict__ Wih1, const float* __restrict__ Whh1,
                            const float* __restrict__ efw, const float* __restrict__ elw,
                            const float* __restrict__ fcw, const float* __restrict__ fmap,
                            const float* __restrict__ bih0, const float* __restrict__ bhh0,
                            const float* __restrict__ bih1, const float* __restrict__ bhh1) {
    const int y = blockIdx.y;
    const int stride = gridDim.x * blockDim.x;
    const int i0 = blockIdx.x * blockDim.x + threadIdx.x;
    if (y == 0) {
        for (int i = i0; i < 512 * 2048; i += stride) {
            int k = i >> 11, n = i & 2047;
            int col = (n & 3) * 512 + (n >> 2);
            g_W0h[i] = __float2half(Whh0[col * 512 + k]);
        }
        for (int i = i0; i < 2048; i += stride) {
            int col = (i & 3) * 512 + (i >> 2);
            g_b0i[i] = bih0[col] + bhh0[col];
            g_b1i[i] = bih1[col] + bhh1[col];
        }
    } else if (y == 1) {
        for (int i = i0; i < 1024 * 2048; i += stride) {
            int k = i >> 11, n = i & 2047;
            int col = (n & 3) * 512 + (n >> 2);
            g_W1h[i] = __float2half((k < 512) ? Wih1[col * 512 + k] : Whh1[col * 512 + (k - 512)]);
        }
    } else if (y == 2) {
        for (int i = i0; i < 256 * 2048; i += stride) {
            int k = i >> 11, n = i & 2047;
            int col = (n & 3) * 512 + (n >> 2);
            g_Wemb[i] = Wih0[col * 256 + k];
        }
    } else if (y == 3) {
        for (int i = i0; i < 9 * 512 * 256; i += stride) {
            int tap = i >> 17, rem = i & 131071;
            int c = rem >> 8, a = rem & 255;
            g_convWH[i] = __float2half(efw[a * 4608 + c * 9 + tap]);
        }
    } else if (y == 4) {
        for (int i = i0; i < 512 * 256; i += stride) {
            int k = i >> 8, a = i & 255;
            g_elwT[i] = elw[a * 512 + k];
        }
        for (int i = i0; i < 1024 * 128; i += stride) {
            int k = i >> 7, j = i & 127;
            g_fcTp[i] = (j < 98) ? fcw[j * 1024 + k] : 0.0f;
        }
    } else {
        for (int i = i0; i < 64 * 256 * 512; i += stride) {
            int b = i >> 17, rem = i & 131071;
            int hw = rem >> 9, c = rem & 511;
            float v = fmap[b * 131072 + c * 256 + hw];
            g_fmapT[i] = v;
            g_fmapTh[i] = __float2half(v);
        }
    }
}

__global__ void k_init2(const float* __restrict__ h0, const float* __restrict__ c0,
                        const float* __restrict__ emb, const int* __restrict__ target) {
    int idx = blockIdx.x * blockDim.x + threadIdx.x;
    const int SE = 1984 * 256;
    if (idx < SE) {
        int t = idx >> 14, rem = idx & 16383;
        int b = rem >> 8, k = rem & 255;
        int lab = (t == 0) ? 0 : target[b * 30 + t - 1];
        g_E[idx] = emb[lab * 256 + k];
    } else {
        int r = idx - SE;
        if (r < 32768) {
            g_h0h[0][r] = __float2half(h0[r]);
        } else if (r < 65536) {
            int q = r - 32768; int b = q >> 9, d = q & 511;
            g_x1h[0][b * 1024 + 512 + d] = __float2half(h0[32768 + q]);
        } else if (r < 98304) {
            g_c0s[r - 65536] = c0[r - 65536];
        } else if (r < 131072) {
            g_c1s[r - 98304] = c0[32768 + (r - 98304)];
        }
    }
}

// ---------------- pre-embedding GEMM: g_pre = E @ Wemb (tf32) ----------------
__global__ __launch_bounds__(256) void k_preemb() {
    __shared__ float As[64 * 36];
    __shared__ float Bs[32 * 132];
    const int tid = threadIdx.x;
    const int warp = tid >> 5;
    const int wm = warp >> 2, wn = warp & 3;
    const int n0 = blockIdx.x * 128, m0 = blockIdx.y * 64;
    wmma::fragment<wmma::accumulator, 16, 16, 8, float> acc[2][2];
#pragma unroll
    for (int i = 0; i < 2; i++)
#pragma unroll
        for (int j = 0; j < 2; j++) wmma::fill_fragment(acc[i][j], 0.0f);
    for (int kt = 0; kt < 256; kt += 32) {
        for (int i = tid; i < 2048; i += 256) {
            int m = i >> 5, k = i & 31;
            As[m * 36 + k] = g_E[(m0 + m) * 256 + kt + k];
        }
        for (int i = tid; i < 4096; i += 256) {
            int k = i >> 7, n = i & 127;
            Bs[k * 132 + n] = g_Wemb[(kt + k) * 2048 + n0 + n];
        }
        __syncthreads();
#pragma unroll
        for (int kf = 0; kf < 4; kf++) {
            wmma::fragment<wmma::matrix_a, 16, 16, 8, wmma::precision::tf32, wmma::row_major> af[2];
            wmma::fragment<wmma::matrix_b, 16, 16, 8, wmma::precision::tf32, wmma::row_major> bf[2];
#pragma unroll
            for (int i = 0; i < 2; i++) {
                wmma::load_matrix_sync(af[i], &As[(wm * 32 + i * 16) * 36 + kf * 8], 36);
                frag_tf32(af[i]);
            }
#pragma unroll
            for (int j = 0; j < 2; j++) {
                wmma::load_matrix_sync(bf[j], &Bs[kf * 8 * 132 + wn * 32 + j * 16], 132);
                frag_tf32(bf[j]);
            }
#pragma unroll
            for (int i = 0; i < 2; i++)
#pragma unroll
                for (int j = 0; j < 2; j++)
                    wmma::mma_sync(acc[i][j], af[i], bf[j], acc[i][j]);
        }
        __syncthreads();
    }
#pragma unroll
    for (int i = 0; i < 2; i++)
#pragma unroll
        for (int j = 0; j < 2; j++)
            wmma::store_matrix_sync(g_pre + (m0 + wm * 32 + i * 16) * 2048 + n0 + wn * 32 + j * 16,
                                    acc[i][j], 2048, wmma::mem_row_major);
}

// ---------------- conv v4: fp16, padded smem (conflict-free), double-buffered ----------------
// grid (2 ntile, 4 mtile, 64 b), 256 thr. Tile M64 x N128, K=4608 in 72 chunks of 64.
#define CBUF 13312   // halves per buffer: As 64*72 (4608) + Bs 64*136 (8704)
__global__ __launch_bounds__(256) void k_conv() {
    extern __shared__ __half csm[];
    const int tid = threadIdx.x;
    const int warp = tid >> 5;
    const int wm = warp >> 2, wn = warp & 3;
    const int n0 = blockIdx.x * 128;
    const int s0 = blockIdx.y * 64;
    const int b = blockIdx.z;
    const __half* fTh = g_fmapTh + b * 131072;

    wmma::fragment<wmma::accumulator, 16, 16, 16, float> acc[2][2];
#pragma unroll
    for (int i = 0; i < 2; i++)
#pragma unroll
        for (int j = 0; j < 2; j++) wmma::fill_fragment(acc[i][j], 0.0f);

    uint4 rA[2], rB[4];
    const uint4 z4 = make_uint4(0u, 0u, 0u, 0u);

    auto loadA = [&](int q) {
        int tap = q >> 3, cch = q & 7;
        int dy = tap / 3 - 1, dx = tap % 3 - 1;
#pragma unroll
        for (int j = 0; j < 2; j++) {
            int u = tid + j * 256;
            int row = u >> 3, seg = u & 7;
            int s = s0 + row;
            int yy = (s >> 5) + dy, xx = (s & 31) + dx;
            bool ok = (yy >= 0) && (yy < 8) && (xx >= 0) && (xx < 32);
            rA[j] = ok ? *(const uint4*)(fTh + (yy * 32 + xx) * 512 + cch * 64 + seg * 8) : z4;
        }
    };
    auto loadB = [&](int q) {
        int tap = q >> 3, cch = q & 7;
        const __half* src = g_convWH + (tap * 512 + cch * 64) * 256 + n0;
#pragma unroll
        for (int j = 0; j < 4; j++) {
            int u = tid + j * 256;
            rB[j] = *(const uint4*)(src + (u >> 4) * 256 + (u & 15) * 8);
        }
    };
    auto storeAB = [&](int buf) {
        __half* A = csm + buf * CBUF;
        __half* B = A + 4608;
#pragma unroll
        for (int j = 0; j < 2; j++) {
            int u = tid + j * 256;
            *(uint4*)&A[(u >> 3) * 72 + (u & 7) * 8] = rA[j];
        }
#pragma unroll
        for (int j = 0; j < 4; j++) {
            int u = tid + j * 256;
            *(uint4*)&B[(u >> 4) * 136 + (u & 15) * 8] = rB[j];
        }
    };

    loadA(0); loadB(0);
    storeAB(0);
    __syncthreads();
#pragma unroll 1
    for (int q = 0; q < 72; q++) {
        if (q < 71) { loadA(q + 1); loadB(q + 1); }
        const __half* A = csm + (q & 1) * CBUF;
        const __half* B = A + 4608;
#pragma unroll
        for (int kf = 0; kf < 4; kf++) {
            wmma::fragment<wmma::matrix_a, 16, 16, 16, __half, wmma::row_major> af[2];
            wmma::fragment<wmma::matrix_b, 16, 16, 16, __half, wmma::row_major> bf[2];
#pragma unroll
            for (int i = 0; i < 2; i++)
                wmma::load_matrix_sync(af[i], &A[(wm * 32 + i * 16) * 72 + kf * 16], 72);
#pragma unroll
            for (int j = 0; j < 2; j++)
                wmma::load_matrix_sync(bf[j], &B[(kf * 16) * 136 + wn * 32 + j * 16], 136);
#pragma unroll
            for (int i = 0; i < 2; i++)
#pragma unroll
                for (int j = 0; j < 2; j++)
                    wmma::mma_sync(acc[i][j], af[i], bf[j], acc[i][j]);
        }
        if (q < 71) {
            storeAB((q + 1) & 1);
            __syncthreads();
        }
    }
    float* eb = g_efmap + b * 65536;
#pragma unroll
    for (int i = 0; i < 2; i++)
#pragma unroll
        for (int j = 0; j < 2; j++)
            wmma::store_matrix_sync(eb + (n0 + wn * 32 + j * 16) * 256 + s0 + wm * 32 + i * 16,
                                    acc[i][j], 256, wmma::mem_col_major);
}

// ---------------- persistent recurrence (fp16 GEMM, full-A staging, padded W) ----------------
__global__ __launch_bounds__(256)
void k_steps() {
    extern __shared__ char smc[];
    __half* Ah  = (__half*)smc;                                   // up to 66048 halves (132096 B)
    __half* W0s = (__half*)(smc + 132096);                        // 512*24 halves (24576 B)
    __half* W1s = (__half*)(smc + 132096 + 24576);                // 1024*24 halves (49152 B)
    float*  Cs  = (float*)(smc + 132096 + 24576 + 49152);         // 2048 floats (8192 B)
    const int tid = threadIdx.x;
    const int bid = blockIdx.x;
    const int warp = tid >> 5;
    const int mt = warp & 3, kh = warp >> 2;
    const int n0 = bid * 16;

    // stage weight slices (half, padded ldm 24)
    for (int j = 0; j < 4; j++) {
        int u = tid + j * 256;                 // 1024 uint4
        int k = u >> 1, s = u & 1;
        *(uint4*)&W0s[k * 24 + s * 8] = *(const uint4*)(g_W0h + k * 2048 + n0 + s * 8);
    }
    for (int j = 0; j < 8; j++) {
        int u = tid + j * 256;                 // 2048 uint4
        int k = u >> 1, s = u & 1;
        *(uint4*)&W1s[k * 24 + s * 8] = *(const uint4*)(g_W1h + k * 2048 + n0 + s * 8);
    }
    __syncthreads();

    const int pb = tid >> 2, pdl = tid & 3;
    const int pr = pb & 15, pmt = pb >> 4;
    const int pd = bid * 4 + pdl;

    for (int t = 0; t < TSTEPS; t++) {
        const int tc = t & 1, tp = tc ^ 1;

        // ---- phase 1: gates0 = h0_prev @ Whh0slice (+pre) -> LSTM0 ----
        {
            const __half* Ag = g_h0h[tc];
#pragma unroll
            for (int j = 0; j < 16; j++) {     // 4096 uint4 = 64x512 halves
                int u = tid + j * 256;
                int row = u >> 6, seg = u & 63;
                *(uint4*)&Ah[row * 520 + seg * 8] =
                    __ldcg((const uint4*)(Ag + row * 512 + seg * 8));
            }
            __syncthreads();
            wmma::fragment<wmma::accumulator, 16, 16, 16, float> a0, a1;
            wmma::fill_fragment(a0, 0.0f);
            wmma::fill_fragment(a1, 0.0f);
#pragma unroll
            for (int q = 0; q < 16; q++) {
                int kf = kh * 16 + q;
                wmma::fragment<wmma::matrix_a, 16, 16, 16, __half, wmma::row_major> af;
                wmma::fragment<wmma::matrix_b, 16, 16, 16, __half, wmma::row_major> bf;
                wmma::load_matrix_sync(af, &Ah[(mt * 16) * 520 + kf * 16], 520);
                wmma::load_matrix_sync(bf, &W0s[(kf * 16) * 24], 24);
                if (q & 1) wmma::mma_sync(a1, af, bf, a1);
                else       wmma::mma_sync(a0, af, bf, a0);
            }
#pragma unroll
            for (int i = 0; i < a0.num_elements; i++) a0.x[i] += a1.x[i];
            wmma::store_matrix_sync(&Cs[warp * 256], a0, 16, wmma::mem_row_major);
            __syncthreads();

            float4 pe = *(const float4*)&g_pre[(t * 64 + pb) * 2048 + n0 + pdl * 4];
            float4 bi = *(const float4*)&g_b0i[n0 + pdl * 4];
            int base = pmt * 256 + pr * 16 + pdl * 4;
            float gi = Cs[base + 0] + Cs[1024 + base + 0] + pe.x + bi.x;
            float gf = Cs[base + 1] + Cs[1024 + base + 1] + pe.y + bi.y;
            float gg = Cs[base + 2] + Cs[1024 + base + 2] + pe.z + bi.z;
            float go = Cs[base + 3] + Cs[1024 + base + 3] + pe.w + bi.w;
            float c = g_c0s[pb * 512 + pd];
            c = sig_acc(gf) * c + sig_acc(gi) * tanhf(gg);
            float h = sig_acc(go) * tanhf(c);
            g_c0s[pb * 512 + pd] = c;
            __half hh = __float2half(h);
            g_x1h[tc][pb * 1024 + pd] = hh;
            g_h0h[tp][pb * 512 + pd] = hh;
        }
        gsync();

        // ---- phase 2: gates1 = [h0_new|h1_prev] @ W1slice -> LSTM1 ----
        {
            const __half* Ag = g_x1h[tc];
#pragma unroll
            for (int j = 0; j < 32; j++) {     // 8192 uint4 = 64x1024 halves
                int u = tid + j * 256;
                int row = u >> 7, seg = u & 127;
                *(uint4*)&Ah[row * 1032 + seg * 8] =
                    __ldcg((const uint4*)(Ag + row * 1024 + seg * 8));
            }
            __syncthreads();
            wmma::fragment<wmma::accumulator, 16, 16, 16, float> a0, a1;
            wmma::fill_fragment(a0, 0.0f);
            wmma::fill_fragment(a1, 0.0f);
#pragma unroll
            for (int q = 0; q < 32; q++) {
                int kf = kh * 32 + q;
                wmma::fragment<wmma::matrix_a, 16, 16, 16, __half, wmma::row_major> af;
                wmma::fragment<wmma::matrix_b, 16, 16, 16, __half, wmma::row_major> bf;
                wmma::load_matrix_sync(af, &Ah[(mt * 16) * 1032 + kf * 16], 1032);
                wmma::load_matrix_sync(bf, &W1s[(kf * 16) * 24], 24);
                if (q & 1) wmma::mma_sync(a1, af, bf, a1);
                else       wmma::mma_sync(a0, af, bf, a0);
            }
#pragma unroll
            for (int i = 0; i < a0.num_elements; i++) a0.x[i] += a1.x[i];
            wmma::store_matrix_sync(&Cs[warp * 256], a0, 16, wmma::mem_row_major);
            __syncthreads();

            float4 bi = *(const float4*)&g_b1i[n0 + pdl * 4];
            int base = pmt * 256 + pr * 16 + pdl * 4;
            float gi = Cs[base + 0] + Cs[1024 + base + 0] + bi.x;
            float gf = Cs[base + 1] + Cs[1024 + base + 1] + bi.y;
            float gg = Cs[base + 2] + Cs[1024 + base + 2] + bi.z;
            float go = Cs[base + 3] + Cs[1024 + base + 3] + bi.w;
            float c = g_c1s[pb * 512 + pd];
            c = sig_acc(gf) * c + sig_acc(gi) * tanhf(gg);
            float h = sig_acc(go) * tanhf(c);
            g_c1s[pb * 512 + pd] = c;
            g_x1h[tp][pb * 1024 + 512 + pd] = __float2half(h);
            g_h1all[(t * 64 + pb) * 512 + pd] = h;
        }
        gsync();
    }
}

// ---------------- epilogue: e_h = h1all @ elwT (tf32) ----------------
__global__ __launch_bounds__(256) void k_eh() {
    __shared__ float As[64 * 36];
    __shared__ float Bs[32 * 132];
    const int tid = threadIdx.x;
    const int warp = tid >> 5;
    const int wm = warp >> 2, wn = warp & 3;
    const int n0 = blockIdx.x * 128, m0 = blockIdx.y * 64;
    wmma::fragment<wmma::accumulator, 16, 16, 8, float> acc[2][2];
#pragma unroll
    for (int i = 0; i < 2; i++)
#pragma unroll
        for (int j = 0; j < 2; j++) wmma::fill_fragment(acc[i][j], 0.0f);
    for (int kt = 0; kt < 512; kt += 32) {
        for (int i = tid; i < 2048; i += 256) {
            int m = i >> 5, k = i & 31;
            As[m * 36 + k] = g_h1all[(m0 + m) * 512 + kt + k];
        }
        for (int i = tid; i < 4096; i += 256) {
            int k = i >> 7, n = i & 127;
            Bs[k * 132 + n] = g_elwT[(kt + k) * 256 + n0 + n];
        }
        __syncthreads();
#pragma unroll
        for (int kf = 0; kf < 4; kf++) {
            wmma::fragment<wmma::matrix_a, 16, 16, 8, wmma::precision::tf32, wmma::row_major> af[2];
            wmma::fragment<wmma::matrix_b, 16, 16, 8, wmma::precision::tf32, wmma::row_major> bf[2];
#pragma unroll
            for (int i = 0; i < 2; i++) {
                wmma::load_matrix_sync(af[i], &As[(wm * 32 + i * 16) * 36 + kf * 8], 36);
                frag_tf32(af[i]);
            }
#pragma unroll
            for (int j = 0; j < 2; j++) {
                wmma::load_matrix_sync(bf[j], &Bs[kf * 8 * 132 + wn * 32 + j * 16], 132);
                frag_tf32(bf[j]);
            }
#pragma unroll
            for (int i = 0; i < 2; i++)
#pragma unroll
                for (int j = 0; j < 2; j++)
                    wmma::mma_sync(acc[i][j], af[i], bf[j], acc[i][j]);
        }
        __syncthreads();
    }
#pragma unroll
    for (int i = 0; i < 2; i++)
#pragma unroll
        for (int j = 0; j < 2; j++)
            wmma::store_matrix_sync(g_eh + (m0 + wm * 32 + i * 16) * 256 + n0 + wn * 32 + j * 16,
                                    acc[i][j], 256, wmma::mem_row_major);
}

// ---------------- epilogue: scores + softmax (4 timesteps per block) ----------------
__global__ __launch_bounds__(256) void k_scores(const float* __restrict__ elb,
                                                const float* __restrict__ efb,
                                                const float* __restrict__ aw,
                                                const float* __restrict__ ab,
                                                float* __restrict__ out) {
    const int tg = blockIdx.x, b = blockIdx.y;
    const int nt = (tg < 7) ? 4 : 3;
    const int tid = threadIdx.x;
    __shared__ float ehs[4 * 256], aws[256];
    __shared__ float red[8], fin;
    const float bias = elb[tid] + efb[tid];
    for (int j = 0; j < 4; j++)
        ehs[j * 256 + tid] = (j < nt) ? g_eh[((tg * 4 + j) * 64 + b) * 256 + tid] + bias : 0.0f;
    aws[tid] = aw[tid];
    __syncthreads();

    float sc[4] = {ab[0], ab[0], ab[0], ab[0]};
    const float* ef = g_efmap + b * 65536 + tid;
#pragma unroll 4
    for (int a = 0; a < 256; a++) {
        float e = ef[a * 256];
        float w = aws[a];
        sc[0] += w * tanh_fast(ehs[a] + e);
        sc[1] += w * tanh_fast(ehs[256 + a] + e);
        sc[2] += w * tanh_fast(ehs[512 + a] + e);
        sc[3] += w * tanh_fast(ehs[768 + a] + e);
    }

    const int wp = tid >> 5, lane = tid & 31;
    for (int j = 0; j < nt; j++) {
        float m = sc[j];
#pragma unroll
        for (int o = 16; o; o >>= 1) m = fmaxf(m, __shfl_xor_sync(0xffffffffu, m, o));
        if (lane == 0) red[wp] = m;
        __syncthreads();
        if (tid == 0) {
            float v = red[0];
#pragma unroll
            for (int i = 1; i < 8; i++) v = fmaxf(v, red[i]);
            fin = v;
        }
        __syncthreads();
        float e = expf(sc[j] - fin);
        float s = e;
#pragma unroll
        for (int o = 16; o; o >>= 1) s += __shfl_xor_sync(0xffffffffu, s, o);
        if (lane == 0) red[wp] = s;
        __syncthreads();
        if (tid == 0) {
            float v = 0;
#pragma unroll
            for (int i = 0; i < 8; i++) v += red[i];
            fin = v;
        }
        __syncthreads();
        out[194432 + (b * 31 + tg * 4 + j) * 256 + tid] = e / fin;
        __syncthreads();
    }
}

// ---------------- epilogue: glimpse (exact fp32) ----------------
__global__ __launch_bounds__(128) void k_glimpse(float* __restrict__ out) {
    __shared__ float ms[16 * 256];
    const int th = blockIdx.x, b = blockIdx.y;
    const int tid = threadIdx.x;
    const int nt = (th == 0) ? 16 : 15;
    for (int i = tid; i < 16 * 256; i += 128) {
        int tt = i >> 8;
        ms[i] = (tt < nt) ? out[194432 + (b * 31 + th * 16 + tt) * 256 + (i & 255)] : 0.0f;
    }
    __syncthreads();
    const int c = tid * 4;
    float4 acc[16];
#pragma unroll
    for (int tt = 0; tt < 16; tt++) acc[tt] = make_float4(0.f, 0.f, 0.f, 0.f);
    const float* fp = g_fmapT + b * 131072 + c;
#pragma unroll 4
    for (int hw = 0; hw < 256; hw++) {
        float4 f = *(const float4*)(fp + hw * 512);
#pragma unroll
        for (int tt = 0; tt < 16; tt++) {
            float m = ms[tt * 256 + hw];
            acc[tt].x += f.x * m; acc[tt].y += f.y * m;
            acc[tt].z += f.z * m; acc[tt].w += f.w * m;
        }
    }
#pragma unroll
    for (int tt = 0; tt < 16; tt++)
        if (tt < nt)
            *(float4*)&out[702336 + (b * 31 + th * 16 + tt) * 512 + c] = acc[tt];
}

// ---------------- epilogue: fc logits (tf32) ----------------
__global__ __launch_bounds__(256) void k_fc(const float* __restrict__ fcb,
                                            float* __restrict__ out) {
    __shared__ float smem[8192];
    float* As = smem;
    float* Bs = smem + 2304;          // 32*132 = 4224 -> total 6528 < 8192
    const int t = blockIdx.x;
    const int tid = threadIdx.x;
    const int warp = tid >> 5;
    const int wm = warp >> 2, wn = warp & 3;
    wmma::fragment<wmma::accumulator, 16, 16, 8, float> acc[2][2];
#pragma unroll
    for (int i = 0; i < 2; i++)
#pragma unroll
        for (int j = 0; j < 2; j++) wmma::fill_fragment(acc[i][j], 0.0f);
    for (int kt = 0; kt < 1024; kt += 32) {
        for (int i = tid; i < 2048; i += 256) {
            int m = i >> 5, k = i & 31;
            int kk = kt + k;
            As[m * 36 + k] = (kk < 512) ? g_h1all[(t * 64 + m) * 512 + kk]
                                        : out[702336 + (m * 31 + t) * 512 + kk - 512];
        }
        for (int i = tid; i < 4096; i += 256) {
            int k = i >> 7, n = i & 127;
            Bs[k * 132 + n] = g_fcTp[(kt + k) * 128 + n];
        }
        __syncthreads();
#pragma unroll
        for (int kf = 0; kf < 4; kf++) {
            wmma::fragment<wmma::matrix_a, 16, 16, 8, wmma::precision::tf32, wmma::row_major> af[2];
            wmma::fragment<wmma::matrix_b, 16, 16, 8, wmma::precision::tf32, wmma::row_major> bf[2];
#pragma unroll
            for (int i = 0; i < 2; i++) {
                wmma::load_matrix_sync(af[i], &As[(wm * 32 + i * 16) * 36 + kf * 8], 36);
                frag_tf32(af[i]);
            }
#pragma unroll
            for (int j = 0; j < 2; j++) {
                wmma::load_matrix_sync(bf[j], &Bs[kf * 8 * 132 + wn * 32 + j * 16], 132);
                frag_tf32(bf[j]);
            }
#pragma unroll
            for (int i = 0; i < 2; i++)
#pragma unroll
                for (int j = 0; j < 2; j++)
                    wmma::mma_sync(acc[i][j], af[i], bf[j], acc[i][j]);
        }
        __syncthreads();
    }
    float* Cs = smem;
#pragma unroll
    for (int i = 0; i < 2; i++)
#pragma unroll
        for (int j = 0; j < 2; j++)
            wmma::store_matrix_sync(&Cs[(wm * 32 + i * 16) * 128 + wn * 32 + j * 16],
                                    acc[i][j], 128, wmma::mem_row_major);
    __syncthreads();
    for (int i = tid; i < 64 * 98; i += 256) {
        int m = i / 98, j = i % 98;
        out[(m * 31 + t) * 98 + j] = Cs[m * 128 + j] + fcb[j];
    }
}

// ---------------- launch ----------------
extern "C" void kernel_launch(void* const* d_in, const int* in_sizes, int n_in,
                              void* d_out, int out_size) {
    const float* fmap   = (const float*)d_in[0];
    const float* h0     = (const float*)d_in[1];
    const float* c0     = (const float*)d_in[2];
    const int*   target = (const int*)d_in[3];
    const float* emb    = (const float*)d_in[5];
    const float* Wih0   = (const float*)d_in[6];
    const float* Whh0   = (const float*)d_in[7];
    const float* bih0   = (const float*)d_in[8];
    const float* bhh0   = (const float*)d_in[9];
    const float* Wih1   = (const float*)d_in[10];
    const float* Whh1   = (const float*)d_in[11];
    const float* bih1   = (const float*)d_in[12];
    const float* bhh1   = (const float*)d_in[13];
    const float* elw    = (const float*)d_in[14];
    const float* elb    = (const float*)d_in[15];
    const float* efw    = (const float*)d_in[16];
    const float* efb    = (const float*)d_in[17];
    const float* aw     = (const float*)d_in[18];
    const float* ab     = (const float*)d_in[19];
    const float* fcw    = (const float*)d_in[20];
    const float* fcb    = (const float*)d_in[21];
    float* out = (float*)d_out;

    const int SMEM_STEPS = 132096 + 24576 + 49152 + 8192;   // 214016
    const int SMEM_CONV  = 2 * CBUF * 2;                    // 53248
    static int configured = 0;
    if (!configured) {
        cudaFuncSetAttribute(k_steps, cudaFuncAttributeMaxDynamicSharedMemorySize, SMEM_STEPS);
        cudaFuncSetAttribute(k_conv, cudaFuncAttributeMaxDynamicSharedMemorySize, SMEM_CONV);
        configured = 1;
    }

    k_transpose<<<dim3(512, 6), 256>>>(Wih0, Whh0, Wih1, Whh1, efw, elw, fcw, fmap,
                                       bih0, bhh0, bih1, bhh1);
    k_init2<<<(1984 * 256 + 131072 + 255) / 256, 256>>>(h0, c0, emb, target);
    k_preemb<<<dim3(16, 31), 256>>>();
    k_conv<<<dim3(2, 4, 64), 256, SMEM_CONV>>>();
    k_steps<<<GBLK, 256, SMEM_STEPS>>>();
    k_eh<<<dim3(2, 31), 256>>>();
    k_scores<<<dim3(8, 64), 256>>>(elb, efb, aw, ab, out);
    k_glimpse<<<dim3(2, 64), 128>>>(out);
    k_fc<<<31, 256>>>(fcb, out);
}

// round 8
// speedup vs baseline: 8.5979x; 1.0368x over previous
#include <cuda_runtime.h>
#include <cuda_fp16.h>
#include <mma.h>
#include <math.h>

using namespace nvcuda;

#define TSTEPS 31
#define GBLK 128

// ---------------- scratch ----------------
__device__ __half g_W0h[512 * 2048];         // [k][n] n = d*4+g interleaved (Whh0)
__device__ __half g_W1h[1024 * 2048];        // [k][n] k: [h0_new|h1_prev]
__device__ float g_Wemb[256 * 2048];         // [k][n] (Wih0) fp32/tf32
__device__ float g_b0i[2048];
__device__ float g_b1i[2048];
__device__ __half g_convWH[9 * 512 * 256];   // [tap][c][attn]
__device__ float g_elwT[512 * 256];          // [k][attn]
__device__ float g_fcTp[1024 * 128];         // [k][class padded]
__device__ float g_fmapT[64 * 256 * 512];    // [b][hw][c] fp32 (glimpse)
__device__ __half g_fmapTh[64 * 256 * 512];  // half copy (conv)
__device__ float g_efmap[64 * 256 * 256];    // [b][attn][hw] (no bias)
__device__ float g_E[1984 * 256];            // emb_seq rows (t*64+b)
__device__ float g_pre[1984 * 2048];         // emb @ Wih0^T, interleaved cols
__device__ __half g_h0h[2][64 * 512];
__device__ __half g_x1h[2][64 * 1024];       // [h0_new | h1_prev]
__device__ float g_c0s[64 * 512];
__device__ float g_c1s[64 * 512];
__device__ float g_h1all[1984 * 512];        // rows (t*64+b)
__device__ float g_eh[1984 * 256];
__device__ unsigned g_barc = 0;
__device__ volatile unsigned g_barg = 0;

__device__ __forceinline__ float tanh_fast(float x) {
    float y; asm("tanh.approx.f32 %0, %1;" : "=f"(y) : "f"(x)); return y;
}
__device__ __forceinline__ float sig_acc(float x) { return 1.0f / (1.0f + expf(-x)); }

__device__ __forceinline__ void cp_async16(void* sdst, const void* gsrc, bool ok) {
    unsigned s = (unsigned)__cvta_generic_to_shared(sdst);
    int sz = ok ? 16 : 0;
    asm volatile("cp.async.cg.shared.global [%0], [%1], 16, %2;\n" :: "r"(s), "l"(gsrc), "r"(sz));
}

template <class F>
__device__ __forceinline__ void frag_tf32(F& f) {
#pragma unroll
    for (int i = 0; i < f.num_elements; i++) f.x[i] = wmma::__float_to_tf32(f.x[i]);
}

__device__ __forceinline__ void gsync() {
    __syncthreads();
    if (threadIdx.x == 0) {
        __threadfence();
        unsigned gen = g_barg;
        if (atomicAdd(&g_barc, 1u) == GBLK - 1u) {
            g_barc = 0;
            __threadfence();
            g_barg = gen + 1u;
        } else {
            while (g_barg == gen) { }
            __threadfence();
        }
    }
    __syncthreads();
}

// ---------------- setup: repacks (weights) ----------------
__global__ void k_transpose(const float* __restrict__ Wih0, const float* __restrict__ Whh0,
                            const float* __restrict__ Wih1, const float* __restrict__ Whh1,
                            const float* __restrict__ efw, const float* __restrict__ elw,
                            const float* __restrict__ fcw,
                            const float* __restrict__ bih0, const float* __restrict__ bhh0,
                            const float* __restrict__ bih1, const float* __restrict__ bhh1) {
    const int y = blockIdx.y;
    const int stride = gridDim.x * blockDim.x;
    const int i0 = blockIdx.x * blockDim.x + threadIdx.x;
    if (y == 0) {
        for (int i = i0; i < 512 * 2048; i += stride) {
            int k = i >> 11, n = i & 2047;
            int col = (n & 3) * 512 + (n >> 2);
            g_W0h[i] = __float2half(Whh0[col * 512 + k]);
        }
        for (int i = i0; i < 2048; i += stride) {
            int col = (i & 3) * 512 + (i >> 2);
            g_b0i[i] = bih0[col] + bhh0[col];
            g_b1i[i] = bih1[col] + bhh1[col];
        }
    } else if (y == 1) {
        for (int i = i0; i < 1024 * 2048; i += stride) {
            int k = i >> 11, n = i & 2047;
            int col = (n & 3) * 512 + (n >> 2);
            g_W1h[i] = __float2half((k < 512) ? Wih1[col * 512 + k] : Whh1[col * 512 + (k - 512)]);
        }
    } else if (y == 2) {
        for (int i = i0; i < 256 * 2048; i += stride) {
            int k = i >> 11, n = i & 2047;
            int col = (n & 3) * 512 + (n >> 2);
            g_Wemb[i] = Wih0[col * 256 + k];
        }
    } else if (y == 3) {
        for (int i = i0; i < 9 * 512 * 256; i += stride) {
            int tap = i >> 17, rem = i & 131071;
            int c = rem >> 8, a = rem & 255;
            g_convWH[i] = __float2half(efw[a * 4608 + c * 9 + tap]);
        }
    } else {
        for (int i = i0; i < 512 * 256; i += stride) {
            int k = i >> 8, a = i & 255;
            g_elwT[i] = elw[a * 512 + k];
        }
        for (int i = i0; i < 1024 * 128; i += stride) {
            int k = i >> 7, j = i & 127;
            g_fcTp[i] = (j < 98) ? fcw[j * 1024 + k] : 0.0f;
        }
    }
}

// ---------------- setup: tiled fmap transpose ----------------
__global__ __launch_bounds__(256) void k_fmapT(const float* __restrict__ fmap) {
    __shared__ float ts[32][33];
    const int b = blockIdx.y;
    const int tile = blockIdx.x;             // 16 c-tiles x 8 hw-tiles
    const int tc = (tile & 15) * 32;
    const int th = (tile >> 4) * 32;
    const int tx = threadIdx.x & 31, ty = threadIdx.x >> 5;
    const float* src = fmap + b * 131072;
#pragma unroll
    for (int it = 0; it < 4; it++) {
        int cl = ty + it * 8;
        ts[cl][tx] = src[(tc + cl) * 256 + th + tx];
    }
    __syncthreads();
    float* dst = g_fmapT + b * 131072;
    __half* dsth = g_fmapTh + b * 131072;
#pragma unroll
    for (int it = 0; it < 4; it++) {
        int hwl = ty + it * 8;
        float v = ts[tx][hwl];
        dst[(th + hwl) * 512 + tc + tx] = v;
        dsth[(th + hwl) * 512 + tc + tx] = __float2half(v);
    }
}

__global__ void k_init2(const float* __restrict__ h0, const float* __restrict__ c0,
                        const float* __restrict__ emb, const int* __restrict__ target) {
    int idx = blockIdx.x * blockDim.x + threadIdx.x;
    const int SE = 1984 * 256;
    if (idx < SE) {
        int t = idx >> 14, rem = idx & 16383;
        int b = rem >> 8, k = rem & 255;
        int lab = (t == 0) ? 0 : target[b * 30 + t - 1];
        g_E[idx] = emb[lab * 256 + k];
    } else {
        int r = idx - SE;
        if (r < 32768) {
            g_h0h[0][r] = __float2half(h0[r]);
        } else if (r < 65536) {
            int q = r - 32768; int b = q >> 9, d = q & 511;
            g_x1h[0][b * 1024 + 512 + d] = __float2half(h0[32768 + q]);
        } else if (r < 98304) {
            g_c0s[r - 65536] = c0[r - 65536];
        } else if (r < 131072) {
            g_c1s[r - 98304] = c0[32768 + (r - 98304)];
        }
    }
}

// ---------------- pre-embedding GEMM: g_pre = E @ Wemb (tf32) ----------------
__global__ __launch_bounds__(256) void k_preemb() {
    __shared__ float As[64 * 36];
    __shared__ float Bs[32 * 132];
    const int tid = threadIdx.x;
    const int warp = tid >> 5;
    const int wm = warp >> 2, wn = warp & 3;
    const int n0 = blockIdx.x * 128, m0 = blockIdx.y * 64;
    wmma::fragment<wmma::accumulator, 16, 16, 8, float> acc[2][2];
#pragma unroll
    for (int i = 0; i < 2; i++)
#pragma unroll
        for (int j = 0; j < 2; j++) wmma::fill_fragment(acc[i][j], 0.0f);
    for (int kt = 0; kt < 256; kt += 32) {
        for (int i = tid; i < 2048; i += 256) {
            int m = i >> 5, k = i & 31;
            As[m * 36 + k] = g_E[(m0 + m) * 256 + kt + k];
        }
        for (int i = tid; i < 4096; i += 256) {
            int k = i >> 7, n = i & 127;
            Bs[k * 132 + n] = g_Wemb[(kt + k) * 2048 + n0 + n];
        }
        __syncthreads();
#pragma unroll
        for (int kf = 0; kf < 4; kf++) {
            wmma::fragment<wmma::matrix_a, 16, 16, 8, wmma::precision::tf32, wmma::row_major> af[2];
            wmma::fragment<wmma::matrix_b, 16, 16, 8, wmma::precision::tf32, wmma::row_major> bf[2];
#pragma unroll
            for (int i = 0; i < 2; i++) {
                wmma::load_matrix_sync(af[i], &As[(wm * 32 + i * 16) * 36 + kf * 8], 36);
                frag_tf32(af[i]);
            }
#pragma unroll
            for (int j = 0; j < 2; j++) {
                wmma::load_matrix_sync(bf[j], &Bs[kf * 8 * 132 + wn * 32 + j * 16], 132);
                frag_tf32(bf[j]);
            }
#pragma unroll
            for (int i = 0; i < 2; i++)
#pragma unroll
                for (int j = 0; j < 2; j++)
                    wmma::mma_sync(acc[i][j], af[i], bf[j], acc[i][j]);
        }
        __syncthreads();
    }
#pragma unroll
    for (int i = 0; i < 2; i++)
#pragma unroll
        for (int j = 0; j < 2; j++)
            wmma::store_matrix_sync(g_pre + (m0 + wm * 32 + i * 16) * 2048 + n0 + wn * 32 + j * 16,
                                    acc[i][j], 2048, wmma::mem_row_major);
}

// ---------------- conv v5: fp16, M256xN128 tile, cp.async double-buffer ----------------
// grid (2 nhalf, 64 b), 256 thr. K=4608 in 72 chunks of 64.
#define CONV_BUF 27136   // halves/buffer: As 256*72 (18432) + Bs 64*136 (8704)
__global__ __launch_bounds__(256) void k_conv() {
    extern __shared__ __half csm[];
    const int tid = threadIdx.x;
    const int warp = tid >> 5;
    const int wm = warp >> 1, wn = warp & 1;     // warp tile M64 x N64
    const int n0 = blockIdx.x * 128;
    const int b = blockIdx.y;
    const __half* fTh = g_fmapTh + b * 131072;

    wmma::fragment<wmma::accumulator, 16, 16, 16, float> acc[4][4];
#pragma unroll
    for (int i = 0; i < 4; i++)
#pragma unroll
        for (int j = 0; j < 4; j++) wmma::fill_fragment(acc[i][j], 0.0f);

    auto issue = [&](int q) {
        int tap = q >> 3, cch = q & 7;
        int dy = tap / 3 - 1, dx = tap % 3 - 1;
        __half* A = csm + (q & 1) * CONV_BUF;
        __half* B = A + 18432;
#pragma unroll
        for (int j = 0; j < 8; j++) {          // A: 2048 16B lines (256 rows x 64 halves)
            int u = tid + j * 256;
            int row = u >> 3, seg = u & 7;
            int yy = (row >> 5) + dy, xx = (row & 31) + dx;
            bool ok = (yy >= 0) && (yy < 8) && (xx >= 0) && (xx < 32);
            const __half* src = ok ? (fTh + (yy * 32 + xx) * 512 + cch * 64 + seg * 8) : fTh;
            cp_async16(A + row * 72 + seg * 8, src, ok);
        }
        const __half* bsrc = g_convWH + (tap * 512 + cch * 64) * 256 + n0;
#pragma unroll
        for (int j = 0; j < 4; j++) {          // B: 1024 16B lines (64 rows x 128 halves)
            int u = tid + j * 256;
            int row = u >> 4, c16 = u & 15;
            cp_async16(B + row * 136 + c16 * 8, bsrc + row * 256 + c16 * 8, true);
        }
        asm volatile("cp.async.commit_group;\n" ::: "memory");
    };

    issue(0);
#pragma unroll 1
    for (int q = 0; q < 72; q++) {
        if (q < 71) {
            issue(q + 1);
            asm volatile("cp.async.wait_group 1;\n" ::: "memory");
        } else {
            asm volatile("cp.async.wait_group 0;\n" ::: "memory");
        }
        __syncthreads();
        const __half* A = csm + (q & 1) * CONV_BUF;
        const __half* B = A + 18432;
#pragma unroll
        for (int kf = 0; kf < 4; kf++) {
            wmma::fragment<wmma::matrix_a, 16, 16, 16, __half, wmma::row_major> af[4];
#pragma unroll
            for (int i = 0; i < 4; i++)
                wmma::load_matrix_sync(af[i], &A[(wm * 64 + i * 16) * 72 + kf * 16], 72);
#pragma unroll
            for (int j = 0; j < 4; j++) {
                wmma::fragment<wmma::matrix_b, 16, 16, 16, __half, wmma::row_major> bf;
                wmma::load_matrix_sync(bf, &B[(kf * 16) * 136 + wn * 64 + j * 16], 136);
#pragma unroll
                for (int i = 0; i < 4; i++)
                    wmma::mma_sync(acc[i][j], af[i], bf, acc[i][j]);
            }
        }
        __syncthreads();
    }
    float* eb = g_efmap + b * 65536;
#pragma unroll
    for (int i = 0; i < 4; i++)
#pragma unroll
        for (int j = 0; j < 4; j++)
            wmma::store_matrix_sync(eb + (n0 + wn * 64 + j * 16) * 256 + wm * 64 + i * 16,
                                    acc[i][j], 256, wmma::mem_col_major);
}

// ---------------- persistent recurrence (fp16 GEMM, full-A staging, padded W) ----------------
__global__ __launch_bounds__(256)
void k_steps() {
    extern __shared__ char smc[];
    __half* Ah  = (__half*)smc;                                   // up to 66048 halves (132096 B)
    __half* W0s = (__half*)(smc + 132096);                        // 512*24 halves (24576 B)
    __half* W1s = (__half*)(smc + 132096 + 24576);                // 1024*24 halves (49152 B)
    float*  Cs  = (float*)(smc + 132096 + 24576 + 49152);         // 2048 floats (8192 B)
    const int tid = threadIdx.x;
    const int bid = blockIdx.x;
    const int warp = tid >> 5;
    const int mt = warp & 3, kh = warp >> 2;
    const int n0 = bid * 16;

    for (int j = 0; j < 4; j++) {
        int u = tid + j * 256;
        int k = u >> 1, s = u & 1;
        *(uint4*)&W0s[k * 24 + s * 8] = *(const uint4*)(g_W0h + k * 2048 + n0 + s * 8);
    }
    for (int j = 0; j < 8; j++) {
        int u = tid + j * 256;
        int k = u >> 1, s = u & 1;
        *(uint4*)&W1s[k * 24 + s * 8] = *(const uint4*)(g_W1h + k * 2048 + n0 + s * 8);
    }
    __syncthreads();

    const int pb = tid >> 2, pdl = tid & 3;
    const int pr = pb & 15, pmt = pb >> 4;
    const int pd = bid * 4 + pdl;

    for (int t = 0; t < TSTEPS; t++) {
        const int tc = t & 1, tp = tc ^ 1;

        // ---- phase 1: gates0 = h0_prev @ Whh0slice (+pre) -> LSTM0 ----
        {
            const __half* Ag = g_h0h[tc];
#pragma unroll
            for (int j = 0; j < 16; j++) {
                int u = tid + j * 256;
                int row = u >> 6, seg = u & 63;
                *(uint4*)&Ah[row * 520 + seg * 8] =
                    __ldcg((const uint4*)(Ag + row * 512 + seg * 8));
            }
            __syncthreads();
            wmma::fragment<wmma::accumulator, 16, 16, 16, float> a0, a1;
            wmma::fill_fragment(a0, 0.0f);
            wmma::fill_fragment(a1, 0.0f);
#pragma unroll
            for (int q = 0; q < 16; q++) {
                int kf = kh * 16 + q;
                wmma::fragment<wmma::matrix_a, 16, 16, 16, __half, wmma::row_major> af;
                wmma::fragment<wmma::matrix_b, 16, 16, 16, __half, wmma::row_major> bf;
                wmma::load_matrix_sync(af, &Ah[(mt * 16) * 520 + kf * 16], 520);
                wmma::load_matrix_sync(bf, &W0s[(kf * 16) * 24], 24);
                if (q & 1) wmma::mma_sync(a1, af, bf, a1);
                else       wmma::mma_sync(a0, af, bf, a0);
            }
#pragma unroll
            for (int i = 0; i < a0.num_elements; i++) a0.x[i] += a1.x[i];
            wmma::store_matrix_sync(&Cs[warp * 256], a0, 16, wmma::mem_row_major);
            __syncthreads();

            float4 pe = *(const float4*)&g_pre[(t * 64 + pb) * 2048 + n0 + pdl * 4];
            float4 bi = *(const float4*)&g_b0i[n0 + pdl * 4];
            int base = pmt * 256 + pr * 16 + pdl * 4;
            float gi = Cs[base + 0] + Cs[1024 + base + 0] + pe.x + bi.x;
            float gf = Cs[base + 1] + Cs[1024 + base + 1] + pe.y + bi.y;
            float gg = Cs[base + 2] + Cs[1024 + base + 2] + pe.z + bi.z;
            float go = Cs[base + 3] + Cs[1024 + base + 3] + pe.w + bi.w;
            float c = g_c0s[pb * 512 + pd];
            c = sig_acc(gf) * c + sig_acc(gi) * tanhf(gg);
            float h = sig_acc(go) * tanhf(c);
            g_c0s[pb * 512 + pd] = c;
            __half hh = __float2half(h);
            g_x1h[tc][pb * 1024 + pd] = hh;
            g_h0h[tp][pb * 512 + pd] = hh;
        }
        gsync();

        // ---- phase 2: gates1 = [h0_new|h1_prev] @ W1slice -> LSTM1 ----
        {
            const __half* Ag = g_x1h[tc];
#pragma unroll
            for (int j = 0; j < 32; j++) {
                int u = tid + j * 256;
                int row = u >> 7, seg = u & 127;
                *(uint4*)&Ah[row * 1032 + seg * 8] =
                    __ldcg((const uint4*)(Ag + row * 1024 + seg * 8));
            }
            __syncthreads();
            wmma::fragment<wmma::accumulator, 16, 16, 16, float> a0, a1;
            wmma::fill_fragment(a0, 0.0f);
            wmma::fill_fragment(a1, 0.0f);
#pragma unroll
            for (int q = 0; q < 32; q++) {
                int kf = kh * 32 + q;
                wmma::fragment<wmma::matrix_a, 16, 16, 16, __half, wmma::row_major> af;
                wmma::fragment<wmma::matrix_b, 16, 16, 16, __half, wmma::row_major> bf;
                wmma::load_matrix_sync(af, &Ah[(mt * 16) * 1032 + kf * 16], 1032);
                wmma::load_matrix_sync(bf, &W1s[(kf * 16) * 24], 24);
                if (q & 1) wmma::mma_sync(a1, af, bf, a1);
                else       wmma::mma_sync(a0, af, bf, a0);
            }
#pragma unroll
            for (int i = 0; i < a0.num_elements; i++) a0.x[i] += a1.x[i];
            wmma::store_matrix_sync(&Cs[warp * 256], a0, 16, wmma::mem_row_major);
            __syncthreads();

            float4 bi = *(const float4*)&g_b1i[n0 + pdl * 4];
            int base = pmt * 256 + pr * 16 + pdl * 4;
            float gi = Cs[base + 0] + Cs[1024 + base + 0] + bi.x;
            float gf = Cs[base + 1] + Cs[1024 + base + 1] + bi.y;
            float gg = Cs[base + 2] + Cs[1024 + base + 2] + bi.z;
            float go = Cs[base + 3] + Cs[1024 + base + 3] + bi.w;
            float c = g_c1s[pb * 512 + pd];
            c = sig_acc(gf) * c + sig_acc(gi) * tanhf(gg);
            float h = sig_acc(go) * tanhf(c);
            g_c1s[pb * 512 + pd] = c;
            g_x1h[tp][pb * 1024 + 512 + pd] = __float2half(h);
            g_h1all[(t * 64 + pb) * 512 + pd] = h;
        }
        gsync();
    }
}

// ---------------- epilogue: e_h = h1all @ elwT (tf32) ----------------
__global__ __launch_bounds__(256) void k_eh() {
    __shared__ float As[64 * 36];
    __shared__ float Bs[32 * 132];
    const int tid = threadIdx.x;
    const int warp = tid >> 5;
    const int wm = warp >> 2, wn = warp & 3;
    const int n0 = blockIdx.x * 128, m0 = blockIdx.y * 64;
    wmma::fragment<wmma::accumulator, 16, 16, 8, float> acc[2][2];
#pragma unroll
    for (int i = 0; i < 2; i++)
#pragma unroll
        for (int j = 0; j < 2; j++) wmma::fill_fragment(acc[i][j], 0.0f);
    for (int kt = 0; kt < 512; kt += 32) {
        for (int i = tid; i < 2048; i += 256) {
            int m = i >> 5, k = i & 31;
            As[m * 36 + k] = g_h1all[(m0 + m) * 512 + kt + k];
        }
        for (int i = tid; i < 4096; i += 256) {
            int k = i >> 7, n = i & 127;
            Bs[k * 132 + n] = g_elwT[(kt + k) * 256 + n0 + n];
        }
        __syncthreads();
#pragma unroll
        for (int kf = 0; kf < 4; kf++) {
            wmma::fragment<wmma::matrix_a, 16, 16, 8, wmma::precision::tf32, wmma::row_major> af[2];
            wmma::fragment<wmma::matrix_b, 16, 16, 8, wmma::precision::tf32, wmma::row_major> bf[2];
#pragma unroll
            for (int i = 0; i < 2; i++) {
                wmma::load_matrix_sync(af[i], &As[(wm * 32 + i * 16) * 36 + kf * 8], 36);
                frag_tf32(af[i]);
            }
#pragma unroll
            for (int j = 0; j < 2; j++) {
                wmma::load_matrix_sync(bf[j], &Bs[kf * 8 * 132 + wn * 32 + j * 16], 132);
                frag_tf32(bf[j]);
            }
#pragma unroll
            for (int i = 0; i < 2; i++)
#pragma unroll
                for (int j = 0; j < 2; j++)
                    wmma::mma_sync(acc[i][j], af[i], bf[j], acc[i][j]);
        }
        __syncthreads();
    }
#pragma unroll
    for (int i = 0; i < 2; i++)
#pragma unroll
        for (int j = 0; j < 2; j++)
            wmma::store_matrix_sync(g_eh + (m0 + wm * 32 + i * 16) * 256 + n0 + wn * 32 + j * 16,
                                    acc[i][j], 256, wmma::mem_row_major);
}

// ---------------- epilogue: scores + softmax (8 timesteps per block) ----------------
__global__ __launch_bounds__(256) void k_scores(const float* __restrict__ elb,
                                                const float* __restrict__ efb,
                                                const float* __restrict__ aw,
                                                const float* __restrict__ ab,
                                                float* __restrict__ out) {
    const int tg = blockIdx.x, b = blockIdx.y;
    const int nt = (tg < 3) ? 8 : 7;
    const int tid = threadIdx.x;
    __shared__ float ehs[8 * 256], aws[256];
    __shared__ float red[8], fin;
    const float bias = elb[tid] + efb[tid];
    for (int j = 0; j < 8; j++)
        ehs[j * 256 + tid] = (j < nt) ? g_eh[((tg * 8 + j) * 64 + b) * 256 + tid] + bias : 0.0f;
    aws[tid] = aw[tid];
    __syncthreads();

    float sc[8];
#pragma unroll
    for (int j = 0; j < 8; j++) sc[j] = ab[0];
    const float* ef = g_efmap + b * 65536 + tid;
#pragma unroll 2
    for (int a = 0; a < 256; a++) {
        float e = ef[a * 256];
        float w = aws[a];
#pragma unroll
        for (int j = 0; j < 8; j++)
            sc[j] += w * tanh_fast(ehs[j * 256 + a] + e);
    }

    const int wp = tid >> 5, lane = tid & 31;
    for (int j = 0; j < nt; j++) {
        float m = sc[j];
#pragma unroll
        for (int o = 16; o; o >>= 1) m = fmaxf(m, __shfl_xor_sync(0xffffffffu, m, o));
        if (lane == 0) red[wp] = m;
        __syncthreads();
        if (tid == 0) {
            float v = red[0];
#pragma unroll
            for (int i = 1; i < 8; i++) v = fmaxf(v, red[i]);
            fin = v;
        }
        __syncthreads();
        float e = expf(sc[j] - fin);
        float s = e;
#pragma unroll
        for (int o = 16; o; o >>= 1) s += __shfl_xor_sync(0xffffffffu, s, o);
        if (lane == 0) red[wp] = s;
        __syncthreads();
        if (tid == 0) {
            float v = 0;
#pragma unroll
            for (int i = 0; i < 8; i++) v += red[i];
            fin = v;
        }
        __syncthreads();
        out[194432 + (b * 31 + tg * 8 + j) * 256 + tid] = e / fin;
        __syncthreads();
    }
}

// ---------------- epilogue: glimpse (exact fp32) ----------------
__global__ __launch_bounds__(128) void k_glimpse(float* __restrict__ out) {
    __shared__ float ms[16 * 256];
    const int th = blockIdx.x, b = blockIdx.y;
    const int tid = threadIdx.x;
    const int nt = (th == 0) ? 16 : 15;
    for (int i = tid; i < 16 * 256; i += 128) {
        int tt = i >> 8;
        ms[i] = (tt < nt) ? out[194432 + (b * 31 + th * 16 + tt) * 256 + (i & 255)] : 0.0f;
    }
    __syncthreads();
    const int c = tid * 4;
    float4 acc[16];
#pragma unroll
    for (int tt = 0; tt < 16; tt++) acc[tt] = make_float4(0.f, 0.f, 0.f, 0.f);
    const float* fp = g_fmapT + b * 131072 + c;
#pragma unroll 4
    for (int hw = 0; hw < 256; hw++) {
        float4 f = *(const float4*)(fp + hw * 512);
#pragma unroll
        for (int tt = 0; tt < 16; tt++) {
            float m = ms[tt * 256 + hw];
            acc[tt].x += f.x * m; acc[tt].y += f.y * m;
            acc[tt].z += f.z * m; acc[tt].w += f.w * m;
        }
    }
#pragma unroll
    for (int tt = 0; tt < 16; tt++)
        if (tt < nt)
            *(float4*)&out[702336 + (b * 31 + th * 16 + tt) * 512 + c] = acc[tt];
}

// ---------------- epilogue: fc logits (tf32) ----------------
__global__ __launch_bounds__(256) void k_fc(const float* __restrict__ fcb,
                                            float* __restrict__ out) {
    __shared__ float smem[8192];
    float* As = smem;
    float* Bs = smem + 2304;
    const int t = blockIdx.x;
    const int tid = threadIdx.x;
    const int warp = tid >> 5;
    const int wm = warp >> 2, wn = warp & 3;
    wmma::fragment<wmma::accumulator, 16, 16, 8, float> acc[2][2];
#pragma unroll
    for (int i = 0; i < 2; i++)
#pragma unroll
        for (int j = 0; j < 2; j++) wmma::fill_fragment(acc[i][j], 0.0f);
    for (int kt = 0; kt < 1024; kt += 32) {
        for (int i = tid; i < 2048; i += 256) {
            int m = i >> 5, k = i & 31;
            int kk = kt + k;
            As[m * 36 + k] = (kk < 512) ? g_h1all[(t * 64 + m) * 512 + kk]
                                        : out[702336 + (m * 31 + t) * 512 + kk - 512];
        }
        for (int i = tid; i < 4096; i += 256) {
            int k = i >> 7, n = i & 127;
            Bs[k * 132 + n] = g_fcTp[(kt + k) * 128 + n];
        }
        __syncthreads();
#pragma unroll
        for (int kf = 0; kf < 4; kf++) {
            wmma::fragment<wmma::matrix_a, 16, 16, 8, wmma::precision::tf32, wmma::row_major> af[2];
            wmma::fragment<wmma::matrix_b, 16, 16, 8, wmma::precision::tf32, wmma::row_major> bf[2];
#pragma unroll
            for (int i = 0; i < 2; i++) {
                wmma::load_matrix_sync(af[i], &As[(wm * 32 + i * 16) * 36 + kf * 8], 36);
                frag_tf32(af[i]);
            }
#pragma unroll
            for (int j = 0; j < 2; j++) {
                wmma::load_matrix_sync(bf[j], &Bs[kf * 8 * 132 + wn * 32 + j * 16], 132);
                frag_tf32(bf[j]);
            }
#pragma unroll
            for (int i = 0; i < 2; i++)
#pragma unroll
                for (int j = 0; j < 2; j++)
                    wmma::mma_sync(acc[i][j], af[i], bf[j], acc[i][j]);
        }
        __syncthreads();
    }
    float* Cs = smem;
#pragma unroll
    for (int i = 0; i < 2; i++)
#pragma unroll
        for (int j = 0; j < 2; j++)
            wmma::store_matrix_sync(&Cs[(wm * 32 + i * 16) * 128 + wn * 32 + j * 16],
                                    acc[i][j], 128, wmma::mem_row_major);
    __syncthreads();
    for (int i = tid; i < 64 * 98; i += 256) {
        int m = i / 98, j = i % 98;
        out[(m * 31 + t) * 98 + j] = Cs[m * 128 + j] + fcb[j];
    }
}

// ---------------- launch ----------------
extern "C" void kernel_launch(void* const* d_in, const int* in_sizes, int n_in,
                              void* d_out, int out_size) {
    const float* fmap   = (const float*)d_in[0];
    const float* h0     = (const float*)d_in[1];
    const float* c0     = (const float*)d_in[2];
    const int*   target = (const int*)d_in[3];
    const float* emb    = (const float*)d_in[5];
    const float* Wih0   = (const float*)d_in[6];
    const float* Whh0   = (const float*)d_in[7];
    const float* bih0   = (const float*)d_in[8];
    const float* bhh0   = (const float*)d_in[9];
    const float* Wih1   = (const float*)d_in[10];
    const float* Whh1   = (const float*)d_in[11];
    const float* bih1   = (const float*)d_in[12];
    const float* bhh1   = (const float*)d_in[13];
    const float* elw    = (const float*)d_in[14];
    const float* elb    = (const float*)d_in[15];
    const float* efw    = (const float*)d_in[16];
    const float* efb    = (const float*)d_in[17];
    const float* aw     = (const float*)d_in[18];
    const float* ab     = (const float*)d_in[19];
    const float* fcw    = (const float*)d_in[20];
    const float* fcb    = (const float*)d_in[21];
    float* out = (float*)d_out;

    const int SMEM_STEPS = 132096 + 24576 + 49152 + 8192;   // 214016
    const int SMEM_CONV  = 2 * CONV_BUF * 2;                // 108544
    static int configured = 0;
    if (!configured) {
        cudaFuncSetAttribute(k_steps, cudaFuncAttributeMaxDynamicSharedMemorySize, SMEM_STEPS);
        cudaFuncSetAttribute(k_conv, cudaFuncAttributeMaxDynamicSharedMemorySize, SMEM_CONV);
        configured = 1;
    }

    k_transpose<<<dim3(512, 5), 256>>>(Wih0, Whh0, Wih1, Whh1, efw, elw, fcw,
                                       bih0, bhh0, bih1, bhh1);
    k_fmapT<<<dim3(128, 64), 256>>>(fmap);
    k_init2<<<(1984 * 256 + 131072 + 255) / 256, 256>>>(h0, c0, emb, target);
    k_preemb<<<dim3(16, 31), 256>>>();
    k_conv<<<dim3(2, 64), 256, SMEM_CONV>>>();
    k_steps<<<GBLK, 256, SMEM_STEPS>>>();
    k_eh<<<dim3(2, 31), 256>>>();
    k_scores<<<dim3(4, 64), 256>>>(elb, efb, aw, ab, out);
    k_glimpse<<<dim3(2, 64), 128>>>(out);
    k_fc<<<31, 256>>>(fcb, out);
}

// round 9
// speedup vs baseline: 11.2860x; 1.3127x over previous
#include <cuda_runtime.h>
#include <cuda_fp16.h>
#include <mma.h>
#include <math.h>

using namespace nvcuda;

#define TSTEPS 31
#define GBLK 128

// ---------------- scratch ----------------
__device__ __half g_W0h[512 * 2048];         // [k][n] n = d*4+g interleaved (Whh0)
__device__ __half g_W1h[1024 * 2048];        // [k][n] k: [h0_new|h1_prev]
__device__ __half g_Wembh[256 * 2048];       // [k][n] (Wih0)
__device__ float g_b0i[2048];
__device__ float g_b1i[2048];
__device__ __half g_convWH[9 * 512 * 256];   // [tap][c][attn]
__device__ __half g_elwTh[512 * 256];        // [k][attn]
__device__ __half g_fcTph[1024 * 128];       // [k][class padded]
__device__ float g_fmapT[64 * 256 * 512];    // [b][hw][c] fp32 (glimpse)
__device__ __half g_fmapTh[64 * 256 * 512];  // half copy (conv)
__device__ float g_efmap[64 * 256 * 256];    // [b][attn][hw] (no bias)
__device__ __half g_Eh[1984 * 256];          // emb_seq rows (t*64+b)
__device__ float g_pre[1984 * 2048];         // emb @ Wih0^T, interleaved cols
__device__ __half g_h0h[2][64 * 512];
__device__ __half g_x1h[2][64 * 1024];       // [h0_new | h1_prev]
__device__ float g_c0s[64 * 512];
__device__ float g_c1s[64 * 512];
__device__ __half g_h1allh[1984 * 512];      // rows (t*64+b), half
__device__ __half g_gh[1984 * 512];          // glimpse half, rows (b*31+t)
__device__ float g_eh[1984 * 256];
__device__ unsigned g_barc = 0;
__device__ volatile unsigned g_barg = 0;

__device__ __forceinline__ float tanh_fast(float x) {
    float y; asm("tanh.approx.f32 %0, %1;" : "=f"(y) : "f"(x)); return y;
}
__device__ __forceinline__ float sig_acc(float x) { return 1.0f / (1.0f + expf(-x)); }

__device__ __forceinline__ void cp_async16(void* sdst, const void* gsrc, bool ok) {
    unsigned s = (unsigned)__cvta_generic_to_shared(sdst);
    int sz = ok ? 16 : 0;
    asm volatile("cp.async.cg.shared.global [%0], [%1], 16, %2;\n" :: "r"(s), "l"(gsrc), "r"(sz));
}

__device__ __forceinline__ void gsync() {
    __syncthreads();
    if (threadIdx.x == 0) {
        __threadfence();
        unsigned gen = g_barg;
        if (atomicAdd(&g_barc, 1u) == GBLK - 1u) {
            g_barc = 0;
            __threadfence();
            g_barg = gen + 1u;
        } else {
            while (g_barg == gen) { }
            __threadfence();
        }
    }
    __syncthreads();
}

// ---------------- setup: repacks (weights) ----------------
__global__ void k_transpose(const float* __restrict__ Wih0, const float* __restrict__ Whh0,
                            const float* __restrict__ Wih1, const float* __restrict__ Whh1,
                            const float* __restrict__ efw, const float* __restrict__ elw,
                            const float* __restrict__ fcw,
                            const float* __restrict__ bih0, const float* __restrict__ bhh0,
                            const float* __restrict__ bih1, const float* __restrict__ bhh1) {
    const int y = blockIdx.y;
    const int stride = gridDim.x * blockDim.x;
    const int i0 = blockIdx.x * blockDim.x + threadIdx.x;
    if (y == 0) {
        for (int i = i0; i < 512 * 2048; i += stride) {
            int k = i >> 11, n = i & 2047;
            int col = (n & 3) * 512 + (n >> 2);
            g_W0h[i] = __float2half(Whh0[col * 512 + k]);
        }
        for (int i = i0; i < 2048; i += stride) {
            int col = (i & 3) * 512 + (i >> 2);
            g_b0i[i] = bih0[col] + bhh0[col];
            g_b1i[i] = bih1[col] + bhh1[col];
        }
    } else if (y == 1) {
        for (int i = i0; i < 1024 * 2048; i += stride) {
            int k = i >> 11, n = i & 2047;
            int col = (n & 3) * 512 + (n >> 2);
            g_W1h[i] = __float2half((k < 512) ? Wih1[col * 512 + k] : Whh1[col * 512 + (k - 512)]);
        }
    } else if (y == 2) {
        for (int i = i0; i < 256 * 2048; i += stride) {
            int k = i >> 11, n = i & 2047;
            int col = (n & 3) * 512 + (n >> 2);
            g_Wembh[i] = __float2half(Wih0[col * 256 + k]);
        }
    } else if (y == 3) {
        for (int i = i0; i < 9 * 512 * 256; i += stride) {
            int tap = i >> 17, rem = i & 131071;
            int c = rem >> 8, a = rem & 255;
            g_convWH[i] = __float2half(efw[a * 4608 + c * 9 + tap]);
        }
    } else {
        for (int i = i0; i < 512 * 256; i += stride) {
            int k = i >> 8, a = i & 255;
            g_elwTh[i] = __float2half(elw[a * 512 + k]);
        }
        for (int i = i0; i < 1024 * 128; i += stride) {
            int k = i >> 7, j = i & 127;
            g_fcTph[i] = __float2half((j < 98) ? fcw[j * 1024 + k] : 0.0f);
        }
    }
}

// ---------------- setup: tiled fmap transpose ----------------
__global__ __launch_bounds__(256) void k_fmapT(const float* __restrict__ fmap) {
    __shared__ float ts[32][33];
    const int b = blockIdx.y;
    const int tile = blockIdx.x;
    const int tc = (tile & 15) * 32;
    const int th = (tile >> 4) * 32;
    const int tx = threadIdx.x & 31, ty = threadIdx.x >> 5;
    const float* src = fmap + b * 131072;
#pragma unroll
    for (int it = 0; it < 4; it++) {
        int cl = ty + it * 8;
        ts[cl][tx] = src[(tc + cl) * 256 + th + tx];
    }
    __syncthreads();
    float* dst = g_fmapT + b * 131072;
    __half* dsth = g_fmapTh + b * 131072;
#pragma unroll
    for (int it = 0; it < 4; it++) {
        int hwl = ty + it * 8;
        float v = ts[tx][hwl];
        dst[(th + hwl) * 512 + tc + tx] = v;
        dsth[(th + hwl) * 512 + tc + tx] = __float2half(v);
    }
}

__global__ void k_init2(const float* __restrict__ h0, const float* __restrict__ c0,
                        const float* __restrict__ emb, const int* __restrict__ target) {
    int idx = blockIdx.x * blockDim.x + threadIdx.x;
    const int SE = 1984 * 256;
    if (idx < SE) {
        int t = idx >> 14, rem = idx & 16383;
        int b = rem >> 8, k = rem & 255;
        int lab = (t == 0) ? 0 : target[b * 30 + t - 1];
        g_Eh[idx] = __float2half(emb[lab * 256 + k]);
    } else {
        int r = idx - SE;
        if (r < 32768) {
            g_h0h[0][r] = __float2half(h0[r]);
        } else if (r < 65536) {
            int q = r - 32768; int b = q >> 9, d = q & 511;
            g_x1h[0][b * 1024 + 512 + d] = __float2half(h0[32768 + q]);
        } else if (r < 98304) {
            g_c0s[r - 65536] = c0[r - 65536];
        } else if (r < 131072) {
            g_c1s[r - 98304] = c0[32768 + (r - 98304)];
        }
    }
}

// ---------------- generic fp16 epilogue GEMM body (M64 x N128 tile) ----------------
// As[64][72] Bs[64][136]; 8 warps: wm = warp>>2 (2 Mtiles of 32), wn = warp&3 (4 Ntiles of 32)

// pre-embedding: g_pre = E @ Wemb. grid (16 n, 31 m)
__global__ __launch_bounds__(256) void k_preemb() {
    __shared__ __half As[64 * 72];
    __shared__ __half Bs[64 * 136];
    const int tid = threadIdx.x;
    const int warp = tid >> 5;
    const int wm = warp >> 2, wn = warp & 3;
    const int n0 = blockIdx.x * 128, m0 = blockIdx.y * 64;
    wmma::fragment<wmma::accumulator, 16, 16, 16, float> acc[2][2];
#pragma unroll
    for (int i = 0; i < 2; i++)
#pragma unroll
        for (int j = 0; j < 2; j++) wmma::fill_fragment(acc[i][j], 0.0f);
    for (int kt = 0; kt < 256; kt += 64) {
#pragma unroll
        for (int j = 0; j < 2; j++) {
            int u = tid + j * 256;
            int row = u >> 3, seg = u & 7;
            *(uint4*)&As[row * 72 + seg * 8] =
                *(const uint4*)(g_Eh + (m0 + row) * 256 + kt + seg * 8);
        }
#pragma unroll
        for (int j = 0; j < 4; j++) {
            int u = tid + j * 256;
            int row = u >> 4, seg = u & 15;
            *(uint4*)&Bs[row * 136 + seg * 8] =
                *(const uint4*)(g_Wembh + (kt + row) * 2048 + n0 + seg * 8);
        }
        __syncthreads();
#pragma unroll
        for (int kf = 0; kf < 4; kf++) {
            wmma::fragment<wmma::matrix_a, 16, 16, 16, __half, wmma::row_major> af[2];
            wmma::fragment<wmma::matrix_b, 16, 16, 16, __half, wmma::row_major> bf[2];
#pragma unroll
            for (int i = 0; i < 2; i++)
                wmma::load_matrix_sync(af[i], &As[(wm * 32 + i * 16) * 72 + kf * 16], 72);
#pragma unroll
            for (int j = 0; j < 2; j++)
                wmma::load_matrix_sync(bf[j], &Bs[(kf * 16) * 136 + wn * 32 + j * 16], 136);
#pragma unroll
            for (int i = 0; i < 2; i++)
#pragma unroll
                for (int j = 0; j < 2; j++)
                    wmma::mma_sync(acc[i][j], af[i], bf[j], acc[i][j]);
        }
        __syncthreads();
    }
#pragma unroll
    for (int i = 0; i < 2; i++)
#pragma unroll
        for (int j = 0; j < 2; j++)
            wmma::store_matrix_sync(g_pre + (m0 + wm * 32 + i * 16) * 2048 + n0 + wn * 32 + j * 16,
                                    acc[i][j], 2048, wmma::mem_row_major);
}

// ---------------- conv v5: fp16, M256xN128 tile, cp.async double-buffer ----------------
#define CONV_BUF 27136   // halves/buffer: As 256*72 (18432) + Bs 64*136 (8704)
__global__ __launch_bounds__(256) void k_conv() {
    extern __shared__ __half csm[];
    const int tid = threadIdx.x;
    const int warp = tid >> 5;
    const int wm = warp >> 1, wn = warp & 1;
    const int n0 = blockIdx.x * 128;
    const int b = blockIdx.y;
    const __half* fTh = g_fmapTh + b * 131072;

    wmma::fragment<wmma::accumulator, 16, 16, 16, float> acc[4][4];
#pragma unroll
    for (int i = 0; i < 4; i++)
#pragma unroll
        for (int j = 0; j < 4; j++) wmma::fill_fragment(acc[i][j], 0.0f);

    auto issue = [&](int q) {
        int tap = q >> 3, cch = q & 7;
        int dy = tap / 3 - 1, dx = tap % 3 - 1;
        __half* A = csm + (q & 1) * CONV_BUF;
        __half* B = A + 18432;
#pragma unroll
        for (int j = 0; j < 8; j++) {
            int u = tid + j * 256;
            int row = u >> 3, seg = u & 7;
            int yy = (row >> 5) + dy, xx = (row & 31) + dx;
            bool ok = (yy >= 0) && (yy < 8) && (xx >= 0) && (xx < 32);
            const __half* src = ok ? (fTh + (yy * 32 + xx) * 512 + cch * 64 + seg * 8) : fTh;
            cp_async16(A + row * 72 + seg * 8, src, ok);
        }
        const __half* bsrc = g_convWH + (tap * 512 + cch * 64) * 256 + n0;
#pragma unroll
        for (int j = 0; j < 4; j++) {
            int u = tid + j * 256;
            int row = u >> 4, c16 = u & 15;
            cp_async16(B + row * 136 + c16 * 8, bsrc + row * 256 + c16 * 8, true);
        }
        asm volatile("cp.async.commit_group;\n" ::: "memory");
    };

    issue(0);
#pragma unroll 1
    for (int q = 0; q < 72; q++) {
        if (q < 71) {
            issue(q + 1);
            asm volatile("cp.async.wait_group 1;\n" ::: "memory");
        } else {
            asm volatile("cp.async.wait_group 0;\n" ::: "memory");
        }
        __syncthreads();
        const __half* A = csm + (q & 1) * CONV_BUF;
        const __half* B = A + 18432;
#pragma unroll
        for (int kf = 0; kf < 4; kf++) {
            wmma::fragment<wmma::matrix_a, 16, 16, 16, __half, wmma::row_major> af[4];
#pragma unroll
            for (int i = 0; i < 4; i++)
                wmma::load_matrix_sync(af[i], &A[(wm * 64 + i * 16) * 72 + kf * 16], 72);
#pragma unroll
            for (int j = 0; j < 4; j++) {
                wmma::fragment<wmma::matrix_b, 16, 16, 16, __half, wmma::row_major> bf;
                wmma::load_matrix_sync(bf, &B[(kf * 16) * 136 + wn * 64 + j * 16], 136);
#pragma unroll
                for (int i = 0; i < 4; i++)
                    wmma::mma_sync(acc[i][j], af[i], bf, acc[i][j]);
            }
        }
        __syncthreads();
    }
    float* eb = g_efmap + b * 65536;
#pragma unroll
    for (int i = 0; i < 4; i++)
#pragma unroll
        for (int j = 0; j < 4; j++)
            wmma::store_matrix_sync(eb + (n0 + wn * 64 + j * 16) * 256 + wm * 64 + i * 16,
                                    acc[i][j], 256, wmma::mem_col_major);
}

// ---------------- persistent recurrence (fp16 GEMM, full-A staging, padded W) ----------------
__global__ __launch_bounds__(256)
void k_steps() {
    extern __shared__ char smc[];
    __half* Ah  = (__half*)smc;                                   // up to 66048 halves
    __half* W0s = (__half*)(smc + 132096);                        // 512*24 halves
    __half* W1s = (__half*)(smc + 132096 + 24576);                // 1024*24 halves
    float*  Cs  = (float*)(smc + 132096 + 24576 + 49152);         // 2048 floats
    const int tid = threadIdx.x;
    const int bid = blockIdx.x;
    const int warp = tid >> 5;
    const int mt = warp & 3, kh = warp >> 2;
    const int n0 = bid * 16;

    for (int j = 0; j < 4; j++) {
        int u = tid + j * 256;
        int k = u >> 1, s = u & 1;
        *(uint4*)&W0s[k * 24 + s * 8] = *(const uint4*)(g_W0h + k * 2048 + n0 + s * 8);
    }
    for (int j = 0; j < 8; j++) {
        int u = tid + j * 256;
        int k = u >> 1, s = u & 1;
        *(uint4*)&W1s[k * 24 + s * 8] = *(const uint4*)(g_W1h + k * 2048 + n0 + s * 8);
    }
    __syncthreads();

    const int pb = tid >> 2, pdl = tid & 3;
    const int pr = pb & 15, pmt = pb >> 4;
    const int pd = bid * 4 + pdl;

    for (int t = 0; t < TSTEPS; t++) {
        const int tc = t & 1, tp = tc ^ 1;

        // ---- phase 1 ----
        {
            const __half* Ag = g_h0h[tc];
#pragma unroll
            for (int j = 0; j < 16; j++) {
                int u = tid + j * 256;
                int row = u >> 6, seg = u & 63;
                *(uint4*)&Ah[row * 520 + seg * 8] =
                    __ldcg((const uint4*)(Ag + row * 512 + seg * 8));
            }
            __syncthreads();
            wmma::fragment<wmma::accumulator, 16, 16, 16, float> a0, a1;
            wmma::fill_fragment(a0, 0.0f);
            wmma::fill_fragment(a1, 0.0f);
#pragma unroll
            for (int q = 0; q < 16; q++) {
                int kf = kh * 16 + q;
                wmma::fragment<wmma::matrix_a, 16, 16, 16, __half, wmma::row_major> af;
                wmma::fragment<wmma::matrix_b, 16, 16, 16, __half, wmma::row_major> bf;
                wmma::load_matrix_sync(af, &Ah[(mt * 16) * 520 + kf * 16], 520);
                wmma::load_matrix_sync(bf, &W0s[(kf * 16) * 24], 24);
                if (q & 1) wmma::mma_sync(a1, af, bf, a1);
                else       wmma::mma_sync(a0, af, bf, a0);
            }
#pragma unroll
            for (int i = 0; i < a0.num_elements; i++) a0.x[i] += a1.x[i];
            wmma::store_matrix_sync(&Cs[warp * 256], a0, 16, wmma::mem_row_major);
            __syncthreads();

            float4 pe = *(const float4*)&g_pre[(t * 64 + pb) * 2048 + n0 + pdl * 4];
            float4 bi = *(const float4*)&g_b0i[n0 + pdl * 4];
            int base = pmt * 256 + pr * 16 + pdl * 4;
            float gi = Cs[base + 0] + Cs[1024 + base + 0] + pe.x + bi.x;
            float gf = Cs[base + 1] + Cs[1024 + base + 1] + pe.y + bi.y;
            float gg = Cs[base + 2] + Cs[1024 + base + 2] + pe.z + bi.z;
            float go = Cs[base + 3] + Cs[1024 + base + 3] + pe.w + bi.w;
            float c = g_c0s[pb * 512 + pd];
            c = sig_acc(gf) * c + sig_acc(gi) * tanhf(gg);
            float h = sig_acc(go) * tanhf(c);
            g_c0s[pb * 512 + pd] = c;
            __half hh = __float2half(h);
            g_x1h[tc][pb * 1024 + pd] = hh;
            g_h0h[tp][pb * 512 + pd] = hh;
        }
        gsync();

        // ---- phase 2 ----
        {
            const __half* Ag = g_x1h[tc];
#pragma unroll
            for (int j = 0; j < 32; j++) {
                int u = tid + j * 256;
                int row = u >> 7, seg = u & 127;
                *(uint4*)&Ah[row * 1032 + seg * 8] =
                    __ldcg((const uint4*)(Ag + row * 1024 + seg * 8));
            }
            __syncthreads();
            wmma::fragment<wmma::accumulator, 16, 16, 16, float> a0, a1;
            wmma::fill_fragment(a0, 0.0f);
            wmma::fill_fragment(a1, 0.0f);
#pragma unroll
            for (int q = 0; q < 32; q++) {
                int kf = kh * 32 + q;
                wmma::fragment<wmma::matrix_a, 16, 16, 16, __half, wmma::row_major> af;
                wmma::fragment<wmma::matrix_b, 16, 16, 16, __half, wmma::row_major> bf;
                wmma::load_matrix_sync(af, &Ah[(mt * 16) * 1032 + kf * 16], 1032);
                wmma::load_matrix_sync(bf, &W1s[(kf * 16) * 24], 24);
                if (q & 1) wmma::mma_sync(a1, af, bf, a1);
                else       wmma::mma_sync(a0, af, bf, a0);
            }
#pragma unroll
            for (int i = 0; i < a0.num_elements; i++) a0.x[i] += a1.x[i];
            wmma::store_matrix_sync(&Cs[warp * 256], a0, 16, wmma::mem_row_major);
            __syncthreads();

            float4 bi = *(const float4*)&g_b1i[n0 + pdl * 4];
            int base = pmt * 256 + pr * 16 + pdl * 4;
            float gi = Cs[base + 0] + Cs[1024 + base + 0] + bi.x;
            float gf = Cs[base + 1] + Cs[1024 + base + 1] + bi.y;
            float gg = Cs[base + 2] + Cs[1024 + base + 2] + bi.z;
            float go = Cs[base + 3] + Cs[1024 + base + 3] + bi.w;
            float c = g_c1s[pb * 512 + pd];
            c = sig_acc(gf) * c + sig_acc(gi) * tanhf(gg);
            float h = sig_acc(go) * tanhf(c);
            g_c1s[pb * 512 + pd] = c;
            __half hh = __float2half(h);
            g_x1h[tp][pb * 1024 + 512 + pd] = hh;
            g_h1allh[(t * 64 + pb) * 512 + pd] = hh;
        }
        gsync();
    }
}

// ---------------- epilogue: e_h = h1all @ elwT (fp16). grid (2 n, 31 m) ----------------
__global__ __launch_bounds__(256) void k_eh() {
    __shared__ __half As[64 * 72];
    __shared__ __half Bs[64 * 136];
    const int tid = threadIdx.x;
    const int warp = tid >> 5;
    const int wm = warp >> 2, wn = warp & 3;
    const int n0 = blockIdx.x * 128, m0 = blockIdx.y * 64;
    wmma::fragment<wmma::accumulator, 16, 16, 16, float> acc[2][2];
#pragma unroll
    for (int i = 0; i < 2; i++)
#pragma unroll
        for (int j = 0; j < 2; j++) wmma::fill_fragment(acc[i][j], 0.0f);
    for (int kt = 0; kt < 512; kt += 64) {
#pragma unroll
        for (int j = 0; j < 2; j++) {
            int u = tid + j * 256;
            int row = u >> 3, seg = u & 7;
            *(uint4*)&As[row * 72 + seg * 8] =
                *(const uint4*)(g_h1allh + (m0 + row) * 512 + kt + seg * 8);
        }
#pragma unroll
        for (int j = 0; j < 4; j++) {
            int u = tid + j * 256;
            int row = u >> 4, seg = u & 15;
            *(uint4*)&Bs[row * 136 + seg * 8] =
                *(const uint4*)(g_elwTh + (kt + row) * 256 + n0 + seg * 8);
        }
        __syncthreads();
#pragma unroll
        for (int kf = 0; kf < 4; kf++) {
            wmma::fragment<wmma::matrix_a, 16, 16, 16, __half, wmma::row_major> af[2];
            wmma::fragment<wmma::matrix_b, 16, 16, 16, __half, wmma::row_major> bf[2];
#pragma unroll
            for (int i = 0; i < 2; i++)
                wmma::load_matrix_sync(af[i], &As[(wm * 32 + i * 16) * 72 + kf * 16], 72);
#pragma unroll
            for (int j = 0; j < 2; j++)
                wmma::load_matrix_sync(bf[j], &Bs[(kf * 16) * 136 + wn * 32 + j * 16], 136);
#pragma unroll
            for (int i = 0; i < 2; i++)
#pragma unroll
                for (int j = 0; j < 2; j++)
                    wmma::mma_sync(acc[i][j], af[i], bf[j], acc[i][j]);
        }
        __syncthreads();
    }
#pragma unroll
    for (int i = 0; i < 2; i++)
#pragma unroll
        for (int j = 0; j < 2; j++)
            wmma::store_matrix_sync(g_eh + (m0 + wm * 32 + i * 16) * 256 + n0 + wn * 32 + j * 16,
                                    acc[i][j], 256, wmma::mem_row_major);
}

// ---------------- epilogue: scores + softmax (8 timesteps per block) ----------------
__global__ __launch_bounds__(256) void k_scores(const float* __restrict__ elb,
                                                const float* __restrict__ efb,
                                                const float* __restrict__ aw,
                                                const float* __restrict__ ab,
                                                float* __restrict__ out) {
    const int tg = blockIdx.x, b = blockIdx.y;
    const int nt = (tg < 3) ? 8 : 7;
    const int tid = threadIdx.x;
    __shared__ float ehs[8 * 256], aws[256];
    __shared__ float red[8], fin;
    const float bias = elb[tid] + efb[tid];
    for (int j = 0; j < 8; j++)
        ehs[j * 256 + tid] = (j < nt) ? g_eh[((tg * 8 + j) * 64 + b) * 256 + tid] + bias : 0.0f;
    aws[tid] = aw[tid];
    __syncthreads();

    float sc[8];
#pragma unroll
    for (int j = 0; j < 8; j++) sc[j] = ab[0];
    const float* ef = g_efmap + b * 65536 + tid;
#pragma unroll 2
    for (int a = 0; a < 256; a++) {
        float e = ef[a * 256];
        float w = aws[a];
#pragma unroll
        for (int j = 0; j < 8; j++)
            sc[j] += w * tanh_fast(ehs[j * 256 + a] + e);
    }

    const int wp = tid >> 5, lane = tid & 31;
    for (int j = 0; j < nt; j++) {
        float m = sc[j];
#pragma unroll
        for (int o = 16; o; o >>= 1) m = fmaxf(m, __shfl_xor_sync(0xffffffffu, m, o));
        if (lane == 0) red[wp] = m;
        __syncthreads();
        if (tid == 0) {
            float v = red[0];
#pragma unroll
            for (int i = 1; i < 8; i++) v = fmaxf(v, red[i]);
            fin = v;
        }
        __syncthreads();
        float e = expf(sc[j] - fin);
        float s = e;
#pragma unroll
        for (int o = 16; o; o >>= 1) s += __shfl_xor_sync(0xffffffffu, s, o);
        if (lane == 0) red[wp] = s;
        __syncthreads();
        if (tid == 0) {
            float v = 0;
#pragma unroll
            for (int i = 0; i < 8; i++) v += red[i];
            fin = v;
        }
        __syncthreads();
        out[194432 + (b * 31 + tg * 8 + j) * 256 + tid] = e / fin;
        __syncthreads();
    }
}

// ---------------- epilogue: glimpse (exact fp32 out + half copy for fc) ----------------
__global__ __launch_bounds__(128) void k_glimpse(float* __restrict__ out) {
    __shared__ float ms[16 * 256];
    const int th = blockIdx.x, b = blockIdx.y;
    const int tid = threadIdx.x;
    const int nt = (th == 0) ? 16 : 15;
    for (int i = tid; i < 16 * 256; i += 128) {
        int tt = i >> 8;
        ms[i] = (tt < nt) ? out[194432 + (b * 31 + th * 16 + tt) * 256 + (i & 255)] : 0.0f;
    }
    __syncthreads();
    const int c = tid * 4;
    float4 acc[16];
#pragma unroll
    for (int tt = 0; tt < 16; tt++) acc[tt] = make_float4(0.f, 0.f, 0.f, 0.f);
    const float* fp = g_fmapT + b * 131072 + c;
#pragma unroll 4
    for (int hw = 0; hw < 256; hw++) {
        float4 f = *(const float4*)(fp + hw * 512);
#pragma unroll
        for (int tt = 0; tt < 16; tt++) {
            float m = ms[tt * 256 + hw];
            acc[tt].x += f.x * m; acc[tt].y += f.y * m;
            acc[tt].z += f.z * m; acc[tt].w += f.w * m;
        }
    }
#pragma unroll
    for (int tt = 0; tt < 16; tt++)
        if (tt < nt) {
            int row = b * 31 + th * 16 + tt;
            *(float4*)&out[702336 + row * 512 + c] = acc[tt];
            __half2* gh = (__half2*)&g_gh[row * 512 + c];
            gh[0] = __floats2half2_rn(acc[tt].x, acc[tt].y);
            gh[1] = __floats2half2_rn(acc[tt].z, acc[tt].w);
        }
}

// ---------------- epilogue: fc logits (fp16). grid 31 (per t) ----------------
__global__ __launch_bounds__(256) void k_fc(const float* __restrict__ fcb,
                                            float* __restrict__ out) {
    __shared__ __half As[64 * 72];
    __shared__ __half Bs[64 * 136];
    __shared__ float Cs[64 * 128];
    const int t = blockIdx.x;
    const int tid = threadIdx.x;
    const int warp = tid >> 5;
    const int wm = warp >> 2, wn = warp & 3;
    wmma::fragment<wmma::accumulator, 16, 16, 16, float> acc[2][2];
#pragma unroll
    for (int i = 0; i < 2; i++)
#pragma unroll
        for (int j = 0; j < 2; j++) wmma::fill_fragment(acc[i][j], 0.0f);
    for (int kt = 0; kt < 1024; kt += 64) {
#pragma unroll
        for (int j = 0; j < 2; j++) {
            int u = tid + j * 256;
            int row = u >> 3, seg = u & 7;
            const __half* src = (kt < 512)
                ? (g_h1allh + (t * 64 + row) * 512 + kt + seg * 8)
                : (g_gh + (row * 31 + t) * 512 + (kt - 512) + seg * 8);
            *(uint4*)&As[row * 72 + seg * 8] = *(const uint4*)src;
        }
#pragma unroll
        for (int j = 0; j < 4; j++) {
            int u = tid + j * 256;
            int row = u >> 4, seg = u & 15;
            *(uint4*)&Bs[row * 136 + seg * 8] =
                *(const uint4*)(g_fcTph + (kt + row) * 128 + seg * 8);
        }
        __syncthreads();
#pragma unroll
        for (int kf = 0; kf < 4; kf++) {
            wmma::fragment<wmma::matrix_a, 16, 16, 16, __half, wmma::row_major> af[2];
            wmma::fragment<wmma::matrix_b, 16, 16, 16, __half, wmma::row_major> bf[2];
#pragma unroll
            for (int i = 0; i < 2; i++)
                wmma::load_matrix_sync(af[i], &As[(wm * 32 + i * 16) * 72 + kf * 16], 72);
#pragma unroll
            for (int j = 0; j < 2; j++)
                wmma::load_matrix_sync(bf[j], &Bs[(kf * 16) * 136 + wn * 32 + j * 16], 136);
#pragma unroll
            for (int i = 0; i < 2; i++)
#pragma unroll
                for (int j = 0; j < 2; j++)
                    wmma::mma_sync(acc[i][j], af[i], bf[j], acc[i][j]);
        }
        __syncthreads();
    }
#pragma unroll
    for (int i = 0; i < 2; i++)
#pragma unroll
        for (int j = 0; j < 2; j++)
            wmma::store_matrix_sync(&Cs[(wm * 32 + i * 16) * 128 + wn * 32 + j * 16],
                                    acc[i][j], 128, wmma::mem_row_major);
    __syncthreads();
    for (int i = tid; i < 64 * 98; i += 256) {
        int m = i / 98, j = i % 98;
        out[(m * 31 + t) * 98 + j] = Cs[m * 128 + j] + fcb[j];
    }
}

// ---------------- launch ----------------
extern "C" void kernel_launch(void* const* d_in, const int* in_sizes, int n_in,
                              void* d_out, int out_size) {
    const float* fmap   = (const float*)d_in[0];
    const float* h0     = (const float*)d_in[1];
    const float* c0     = (const float*)d_in[2];
    const int*   target = (const int*)d_in[3];
    const float* emb    = (const float*)d_in[5];
    const float* Wih0   = (const float*)d_in[6];
    const float* Whh0   = (const float*)d_in[7];
    const float* bih0   = (const float*)d_in[8];
    const float* bhh0   = (const float*)d_in[9];
    const float* Wih1   = (const float*)d_in[10];
    const float* Whh1   = (const float*)d_in[11];
    const float* bih1   = (const float*)d_in[12];
    const float* bhh1   = (const float*)d_in[13];
    const float* elw    = (const float*)d_in[14];
    const float* elb    = (const float*)d_in[15];
    const float* efw    = (const float*)d_in[16];
    const float* efb    = (const float*)d_in[17];
    const float* aw     = (const float*)d_in[18];
    const float* ab     = (const float*)d_in[19];
    const float* fcw    = (const float*)d_in[20];
    const float* fcb    = (const float*)d_in[21];
    float* out = (float*)d_out;

    const int SMEM_STEPS = 132096 + 24576 + 49152 + 8192;   // 214016
    const int SMEM_CONV  = 2 * CONV_BUF * 2;                // 108544
    static int configured = 0;
    if (!configured) {
        cudaFuncSetAttribute(k_steps, cudaFuncAttributeMaxDynamicSharedMemorySize, SMEM_STEPS);
        cudaFuncSetAttribute(k_conv, cudaFuncAttributeMaxDynamicSharedMemorySize, SMEM_CONV);
        configured = 1;
    }

    k_transpose<<<dim3(512, 5), 256>>>(Wih0, Whh0, Wih1, Whh1, efw, elw, fcw,
                                       bih0, bhh0, bih1, bhh1);
    k_fmapT<<<dim3(128, 64), 256>>>(fmap);
    k_init2<<<(1984 * 256 + 131072 + 255) / 256, 256>>>(h0, c0, emb, target);
    k_preemb<<<dim3(16, 31), 256>>>();
    k_conv<<<dim3(2, 64), 256, SMEM_CONV>>>();
    k_steps<<<GBLK, 256, SMEM_STEPS>>>();
    k_eh<<<dim3(2, 31), 256>>>();
    k_scores<<<dim3(4, 64), 256>>>(elb, efb, aw, ab, out);
    k_glimpse<<<dim3(2, 64), 128>>>(out);
    k_fc<<<31, 256>>>(fcb, out);
}

// round 10
// speedup vs baseline: 12.4182x; 1.1003x over previous
#include <cuda_runtime.h>
#include <cuda_fp16.h>
#include <mma.h>
#include <math.h>

using namespace nvcuda;

#define TSTEPS 31
#define GBLK 128

// ---------------- scratch ----------------
__device__ __half g_W0h[512 * 2048];         // [k][n] n = d*4+g interleaved (Whh0)
__device__ __half g_W1h[1024 * 2048];        // [k][n] k: [h0_new|h1_prev]
__device__ __half g_Wembh[256 * 2048];       // [k][n] (Wih0)
__device__ float g_b0i[2048];
__device__ float g_b1i[2048];
__device__ __half g_convWH[9 * 512 * 256];   // [tap][c][attn]
__device__ __half g_elwTh[512 * 256];        // [k][attn]
__device__ __half g_fcTph[1024 * 128];       // [k][class padded]
__device__ float g_fmapT[64 * 256 * 512];    // [b][hw][c] fp32 (glimpse)
__device__ __half g_fmapTh[64 * 256 * 512];  // half copy (conv)
__device__ float g_efmap[64 * 256 * 256];    // [b][attn][hw] (no bias)
__device__ __half g_Eh[1984 * 256];          // emb_seq rows (t*64+b)
__device__ float g_pre[1984 * 2048];         // emb @ Wih0^T, interleaved cols
__device__ __half g_xh[2][64 * 1024];        // [b][h0 | h1] recurrence buffer
__device__ float g_c0s[64 * 512];
__device__ float g_c1s[64 * 512];
__device__ __half g_h1allh[1984 * 512];      // rows (t*64+b), half
__device__ __half g_gh[1984 * 512];          // glimpse half, rows (b*31+t)
__device__ float g_eh[1984 * 256];
__device__ unsigned g_barc = 0;
__device__ volatile unsigned g_barg = 0;

__device__ __forceinline__ float tanh_fast(float x) {
    float y; asm("tanh.approx.f32 %0, %1;" : "=f"(y) : "f"(x)); return y;
}
__device__ __forceinline__ float sig_acc(float x) { return 1.0f / (1.0f + expf(-x)); }

__device__ __forceinline__ void cp_async16(void* sdst, const void* gsrc, bool ok) {
    unsigned s = (unsigned)__cvta_generic_to_shared(sdst);
    int sz = ok ? 16 : 0;
    asm volatile("cp.async.cg.shared.global [%0], [%1], 16, %2;\n" :: "r"(s), "l"(gsrc), "r"(sz));
}

__device__ __forceinline__ void gsync() {
    __syncthreads();
    if (threadIdx.x == 0) {
        __threadfence();
        unsigned gen = g_barg;
        if (atomicAdd(&g_barc, 1u) == GBLK - 1u) {
            g_barc = 0;
            __threadfence();
            g_barg = gen + 1u;
        } else {
            while (g_barg == gen) { }
            __threadfence();
        }
    }
    __syncthreads();
}

// ---------------- setup: tiled weight transposes (coalesced) ----------------
// y=0: W0h (K=512 from Whh0), y=1: W1h (K=1024 from Wih1|Whh1), y=2: Wembh (K=256 from Wih0)
__global__ __launch_bounds__(256) void k_wtrans(const float* __restrict__ Whh0,
                                                const float* __restrict__ Wih1,
                                                const float* __restrict__ Whh1,
                                                const float* __restrict__ Wih0) {
    __shared__ float ts[32][33];
    const int y = blockIdx.y;
    const int tile = blockIdx.x;
    const int tn = tile & 63, tk = tile >> 6;
    const int kmax = (y == 0) ? 16 : (y == 1) ? 32 : 8;
    if (tk >= kmax) return;
    const int n0 = tn * 32, k0 = tk * 32;
    const int tx = threadIdx.x & 31, ty = threadIdx.x >> 5;
#pragma unroll
    for (int i = 0; i < 4; i++) {
        int nl = ty + i * 8;
        int n = n0 + nl;
        int col = (n & 3) * 512 + (n >> 2);
        int k = k0 + tx;
        float v;
        if (y == 0)      v = Whh0[col * 512 + k];
        else if (y == 1) v = (k < 512) ? Wih1[col * 512 + k] : Whh1[col * 512 + (k - 512)];
        else             v = Wih0[col * 256 + k];
        ts[nl][tx] = v;
    }
    __syncthreads();
    __half* dst = (y == 0) ? g_W0h : (y == 1) ? g_W1h : g_Wembh;
#pragma unroll
    for (int i = 0; i < 4; i++) {
        int kl = ty + i * 8;
        dst[(k0 + kl) * 2048 + n0 + tx] = __float2half(ts[tx][kl]);
    }
}

// conv weight repack: efw[a][c*9+tap] -> g_convWH[tap][c][a]; tiles 32a x 32c, all taps
__global__ __launch_bounds__(256) void k_ctrans(const float* __restrict__ efw) {
    __shared__ float ts[32 * 289];
    const int a0 = blockIdx.x * 32, c0 = blockIdx.y * 32;
    const int tid = threadIdx.x;
    for (int u = tid; u < 32 * 288; u += 256) {
        int al = u / 288, x = u - al * 288;
        ts[al * 289 + x] = efw[(a0 + al) * 4608 + c0 * 9 + x];
    }
    __syncthreads();
    for (int u = tid; u < 9216; u += 256) {
        int al = u & 31, rest = u >> 5;
        int cl = rest & 31, tap = rest >> 5;
        g_convWH[tap * 131072 + (c0 + cl) * 256 + a0 + al] =
            __float2half(ts[al * 289 + cl * 9 + tap]);
    }
}

// small repacks: biases, elw, fc
__global__ void k_small(const float* __restrict__ elw, const float* __restrict__ fcw,
                        const float* __restrict__ bih0, const float* __restrict__ bhh0,
                        const float* __restrict__ bih1, const float* __restrict__ bhh1) {
    const int stride = gridDim.x * blockDim.x;
    const int i0 = blockIdx.x * blockDim.x + threadIdx.x;
    for (int i = i0; i < 2048; i += stride) {
        int col = (i & 3) * 512 + (i >> 2);
        g_b0i[i] = bih0[col] + bhh0[col];
        g_b1i[i] = bih1[col] + bhh1[col];
    }
    for (int i = i0; i < 512 * 256; i += stride) {
        int k = i >> 8, a = i & 255;
        g_elwTh[i] = __float2half(elw[a * 512 + k]);
    }
    for (int i = i0; i < 1024 * 128; i += stride) {
        int k = i >> 7, j = i & 127;
        g_fcTph[i] = __float2half((j < 98) ? fcw[j * 1024 + k] : 0.0f);
    }
}

// ---------------- setup: tiled fmap transpose ----------------
__global__ __launch_bounds__(256) void k_fmapT(const float* __restrict__ fmap) {
    __shared__ float ts[32][33];
    const int b = blockIdx.y;
    const int tile = blockIdx.x;
    const int tc = (tile & 15) * 32;
    const int th = (tile >> 4) * 32;
    const int tx = threadIdx.x & 31, ty = threadIdx.x >> 5;
    const float* src = fmap + b * 131072;
#pragma unroll
    for (int it = 0; it < 4; it++) {
        int cl = ty + it * 8;
        ts[cl][tx] = src[(tc + cl) * 256 + th + tx];
    }
    __syncthreads();
    float* dst = g_fmapT + b * 131072;
    __half* dsth = g_fmapTh + b * 131072;
#pragma unroll
    for (int it = 0; it < 4; it++) {
        int hwl = ty + it * 8;
        float v = ts[tx][hwl];
        dst[(th + hwl) * 512 + tc + tx] = v;
        dsth[(th + hwl) * 512 + tc + tx] = __float2half(v);
    }
}

__global__ void k_init2(const float* __restrict__ h0, const float* __restrict__ c0,
                        const float* __restrict__ emb, const int* __restrict__ target) {
    int idx = blockIdx.x * blockDim.x + threadIdx.x;
    const int SE = 1984 * 256;
    if (idx < SE) {
        int t = idx >> 14, rem = idx & 16383;
        int b = rem >> 8, k = rem & 255;
        int lab = (t == 0) ? 0 : target[b * 30 + t - 1];
        g_Eh[idx] = __float2half(emb[lab * 256 + k]);
    } else {
        int r = idx - SE;
        if (r < 32768) {
            int b = r >> 9, d = r & 511;
            g_xh[1][b * 1024 + d] = __float2half(h0[r]);            // h0 layer0 init
        } else if (r < 65536) {
            int q = r - 32768; int b = q >> 9, d = q & 511;
            g_xh[0][b * 1024 + 512 + d] = __float2half(h0[32768 + q]);  // h1 init
        } else if (r < 98304) {
            g_c0s[r - 65536] = c0[r - 65536];
        } else if (r < 131072) {
            g_c1s[r - 98304] = c0[32768 + (r - 98304)];
        }
    }
}

// ---------------- pre-embedding GEMM: g_pre = E @ Wemb (fp16) ----------------
__global__ __launch_bounds__(256) void k_preemb() {
    __shared__ __half As[64 * 72];
    __shared__ __half Bs[64 * 136];
    const int tid = threadIdx.x;
    const int warp = tid >> 5;
    const int wm = warp >> 2, wn = warp & 3;
    const int n0 = blockIdx.x * 128, m0 = blockIdx.y * 64;
    wmma::fragment<wmma::accumulator, 16, 16, 16, float> acc[2][2];
#pragma unroll
    for (int i = 0; i < 2; i++)
#pragma unroll
        for (int j = 0; j < 2; j++) wmma::fill_fragment(acc[i][j], 0.0f);
    for (int kt = 0; kt < 256; kt += 64) {
#pragma unroll
        for (int j = 0; j < 2; j++) {
            int u = tid + j * 256;
            int row = u >> 3, seg = u & 7;
            *(uint4*)&As[row * 72 + seg * 8] =
                *(const uint4*)(g_Eh + (m0 + row) * 256 + kt + seg * 8);
        }
#pragma unroll
        for (int j = 0; j < 4; j++) {
            int u = tid + j * 256;
            int row = u >> 4, seg = u & 15;
            *(uint4*)&Bs[row * 136 + seg * 8] =
                *(const uint4*)(g_Wembh + (kt + row) * 2048 + n0 + seg * 8);
        }
        __syncthreads();
#pragma unroll
        for (int kf = 0; kf < 4; kf++) {
            wmma::fragment<wmma::matrix_a, 16, 16, 16, __half, wmma::row_major> af[2];
            wmma::fragment<wmma::matrix_b, 16, 16, 16, __half, wmma::row_major> bf[2];
#pragma unroll
            for (int i = 0; i < 2; i++)
                wmma::load_matrix_sync(af[i], &As[(wm * 32 + i * 16) * 72 + kf * 16], 72);
#pragma unroll
            for (int j = 0; j < 2; j++)
                wmma::load_matrix_sync(bf[j], &Bs[(kf * 16) * 136 + wn * 32 + j * 16], 136);
#pragma unroll
            for (int i = 0; i < 2; i++)
#pragma unroll
                for (int j = 0; j < 2; j++)
                    wmma::mma_sync(acc[i][j], af[i], bf[j], acc[i][j]);
        }
        __syncthreads();
    }
#pragma unroll
    for (int i = 0; i < 2; i++)
#pragma unroll
        for (int j = 0; j < 2; j++)
            wmma::store_matrix_sync(g_pre + (m0 + wm * 32 + i * 16) * 2048 + n0 + wn * 32 + j * 16,
                                    acc[i][j], 2048, wmma::mem_row_major);
}

// ---------------- conv v5: fp16, M256xN128 tile, cp.async double-buffer ----------------
#define CONV_BUF 27136   // halves/buffer: As 256*72 (18432) + Bs 64*136 (8704)
__global__ __launch_bounds__(256) void k_conv() {
    extern __shared__ __half csm[];
    const int tid = threadIdx.x;
    const int warp = tid >> 5;
    const int wm = warp >> 1, wn = warp & 1;
    const int n0 = blockIdx.x * 128;
    const int b = blockIdx.y;
    const __half* fTh = g_fmapTh + b * 131072;

    wmma::fragment<wmma::accumulator, 16, 16, 16, float> acc[4][4];
#pragma unroll
    for (int i = 0; i < 4; i++)
#pragma unroll
        for (int j = 0; j < 4; j++) wmma::fill_fragment(acc[i][j], 0.0f);

    auto issue = [&](int q) {
        int tap = q >> 3, cch = q & 7;
        int dy = tap / 3 - 1, dx = tap % 3 - 1;
        __half* A = csm + (q & 1) * CONV_BUF;
        __half* B = A + 18432;
#pragma unroll
        for (int j = 0; j < 8; j++) {
            int u = tid + j * 256;
            int row = u >> 3, seg = u & 7;
            int yy = (row >> 5) + dy, xx = (row & 31) + dx;
            bool ok = (yy >= 0) && (yy < 8) && (xx >= 0) && (xx < 32);
            const __half* src = ok ? (fTh + (yy * 32 + xx) * 512 + cch * 64 + seg * 8) : fTh;
            cp_async16(A + row * 72 + seg * 8, src, ok);
        }
        const __half* bsrc = g_convWH + (tap * 512 + cch * 64) * 256 + n0;
#pragma unroll
        for (int j = 0; j < 4; j++) {
            int u = tid + j * 256;
            int row = u >> 4, c16 = u & 15;
            cp_async16(B + row * 136 + c16 * 8, bsrc + row * 256 + c16 * 8, true);
        }
        asm volatile("cp.async.commit_group;\n" ::: "memory");
    };

    issue(0);
#pragma unroll 1
    for (int q = 0; q < 72; q++) {
        if (q < 71) {
            issue(q + 1);
            asm volatile("cp.async.wait_group 1;\n" ::: "memory");
        } else {
            asm volatile("cp.async.wait_group 0;\n" ::: "memory");
        }
        __syncthreads();
        const __half* A = csm + (q & 1) * CONV_BUF;
        const __half* B = A + 18432;
#pragma unroll
        for (int kf = 0; kf < 4; kf++) {
            wmma::fragment<wmma::matrix_a, 16, 16, 16, __half, wmma::row_major> af[4];
#pragma unroll
            for (int i = 0; i < 4; i++)
                wmma::load_matrix_sync(af[i], &A[(wm * 64 + i * 16) * 72 + kf * 16], 72);
#pragma unroll
            for (int j = 0; j < 4; j++) {
                wmma::fragment<wmma::matrix_b, 16, 16, 16, __half, wmma::row_major> bf;
                wmma::load_matrix_sync(bf, &B[(kf * 16) * 136 + wn * 64 + j * 16], 136);
#pragma unroll
                for (int i = 0; i < 4; i++)
                    wmma::mma_sync(acc[i][j], af[i], bf, acc[i][j]);
            }
        }
        __syncthreads();
    }
    float* eb = g_efmap + b * 65536;
#pragma unroll
    for (int i = 0; i < 4; i++)
#pragma unroll
        for (int j = 0; j < 4; j++)
            wmma::store_matrix_sync(eb + (n0 + wn * 64 + j * 16) * 256 + wm * 64 + i * 16,
                                    acc[i][j], 256, wmma::mem_col_major);
}

// ---------------- persistent recurrence: pipelined (phase1(k) + phase2(k-1)) ----------------
// 32 intervals, 31 gsyncs. Block bid owns 16 interleaved gate-cols for BOTH layers.
__global__ __launch_bounds__(256)
void k_steps() {
    extern __shared__ char smc[];
    __half* Ah  = (__half*)smc;                                   // 64*1032 halves = 132096 B
    __half* W0s = (__half*)(smc + 132096);                        // 512*24 halves = 24576 B
    __half* W1s = (__half*)(smc + 132096 + 24576);                // 1024*24 halves = 49152 B
    float*  Cs  = (float*)(smc + 132096 + 24576 + 49152);         // 4096 floats = 16384 B
    const int tid = threadIdx.x;
    const int bid = blockIdx.x;
    const int warp = tid >> 5;
    const int mt = warp & 3, kh = warp >> 2;
    const int n0 = bid * 16;

    for (int j = 0; j < 4; j++) {
        int u = tid + j * 256;
        int k = u >> 1, s = u & 1;
        *(uint4*)&W0s[k * 24 + s * 8] = *(const uint4*)(g_W0h + k * 2048 + n0 + s * 8);
    }
    for (int j = 0; j < 8; j++) {
        int u = tid + j * 256;
        int k = u >> 1, s = u & 1;
        *(uint4*)&W1s[k * 24 + s * 8] = *(const uint4*)(g_W1h + k * 2048 + n0 + s * 8);
    }
    __syncthreads();

    const int pb = tid >> 2, pdl = tid & 3;
    const int pr = pb & 15, pmt = pb >> 4;
    const int pd = bid * 4 + pdl;

#pragma unroll 1
    for (int k = 0; k <= TSTEPS; k++) {
        const int rb = (k + 1) & 1, wb = k & 1;

        // stage A = [h0_{k-1} | h1_{k-2}] (64 x 1024 halves)
        {
            const __half* Ag = g_xh[rb];
#pragma unroll
            for (int j = 0; j < 32; j++) {
                int u = tid + j * 256;
                int row = u >> 7, seg = u & 127;
                *(uint4*)&Ah[row * 1032 + seg * 8] =
                    __ldcg((const uint4*)(Ag + row * 1024 + seg * 8));
            }
        }
        __syncthreads();

        // GEMM0 (layer-0 gates, t=k) over K=512 (h0 region)
        if (k < TSTEPS) {
            wmma::fragment<wmma::accumulator, 16, 16, 16, float> a0, a1;
            wmma::fill_fragment(a0, 0.0f);
            wmma::fill_fragment(a1, 0.0f);
#pragma unroll
            for (int q = 0; q < 16; q++) {
                int kf = kh * 16 + q;
                wmma::fragment<wmma::matrix_a, 16, 16, 16, __half, wmma::row_major> af;
                wmma::fragment<wmma::matrix_b, 16, 16, 16, __half, wmma::row_major> bf;
                wmma::load_matrix_sync(af, &Ah[(mt * 16) * 1032 + kf * 16], 1032);
                wmma::load_matrix_sync(bf, &W0s[(kf * 16) * 24], 24);
                if (q & 1) wmma::mma_sync(a1, af, bf, a1);
                else       wmma::mma_sync(a0, af, bf, a0);
            }
#pragma unroll
            for (int i = 0; i < a0.num_elements; i++) a0.x[i] += a1.x[i];
            wmma::store_matrix_sync(&Cs[warp * 256], a0, 16, wmma::mem_row_major);
        }
        // GEMM1 (layer-1 gates, t=k-1) over K=1024
        if (k > 0) {
            wmma::fragment<wmma::accumulator, 16, 16, 16, float> a0, a1;
            wmma::fill_fragment(a0, 0.0f);
            wmma::fill_fragment(a1, 0.0f);
#pragma unroll
            for (int q = 0; q < 32; q++) {
                int kf = kh * 32 + q;
                wmma::fragment<wmma::matrix_a, 16, 16, 16, __half, wmma::row_major> af;
                wmma::fragment<wmma::matrix_b, 16, 16, 16, __half, wmma::row_major> bf;
                wmma::load_matrix_sync(af, &Ah[(mt * 16) * 1032 + kf * 16], 1032);
                wmma::load_matrix_sync(bf, &W1s[(kf * 16) * 24], 24);
                if (q & 1) wmma::mma_sync(a1, af, bf, a1);
                else       wmma::mma_sync(a0, af, bf, a0);
            }
#pragma unroll
            for (int i = 0; i < a0.num_elements; i++) a0.x[i] += a1.x[i];
            wmma::store_matrix_sync(&Cs[2048 + warp * 256], a0, 16, wmma::mem_row_major);
        }
        __syncthreads();

        // pointwise LSTM0 (t=k)
        if (k < TSTEPS) {
            float4 pe = *(const float4*)&g_pre[(k * 64 + pb) * 2048 + n0 + pdl * 4];
            float4 bi = *(const float4*)&g_b0i[n0 + pdl * 4];
            int base = pmt * 256 + pr * 16 + pdl * 4;
            float gi = Cs[base + 0] + Cs[1024 + base + 0] + pe.x + bi.x;
            float gf = Cs[base + 1] + Cs[1024 + base + 1] + pe.y + bi.y;
            float gg = Cs[base + 2] + Cs[1024 + base + 2] + pe.z + bi.z;
            float go = Cs[base + 3] + Cs[1024 + base + 3] + pe.w + bi.w;
            float c = g_c0s[pb * 512 + pd];
            c = sig_acc(gf) * c + sig_acc(gi) * tanhf(gg);
            float h = sig_acc(go) * tanhf(c);
            g_c0s[pb * 512 + pd] = c;
            g_xh[wb][pb * 1024 + pd] = __float2half(h);
        }
        // pointwise LSTM1 (t=k-1)
        if (k > 0) {
            float4 bi = *(const float4*)&g_b1i[n0 + pdl * 4];
            int base = 2048 + pmt * 256 + pr * 16 + pdl * 4;
            float gi = Cs[base + 0] + Cs[1024 + base + 0] + bi.x;
            float gf = Cs[base + 1] + Cs[1024 + base + 1] + bi.y;
            float gg = Cs[base + 2] + Cs[1024 + base + 2] + bi.z;
            float go = Cs[base + 3] + Cs[1024 + base + 3] + bi.w;
            float c = g_c1s[pb * 512 + pd];
            c = sig_acc(gf) * c + sig_acc(gi) * tanhf(gg);
            float h = sig_acc(go) * tanhf(c);
            g_c1s[pb * 512 + pd] = c;
            __half hh = __float2half(h);
            g_xh[wb][pb * 1024 + 512 + pd] = hh;
            g_h1allh[((k - 1) * 64 + pb) * 512 + pd] = hh;
        }
        if (k < TSTEPS) gsync();
    }
}

// ---------------- epilogue: e_h = h1all @ elwT (fp16). grid (2 n, 31 m) ----------------
__global__ __launch_bounds__(256) void k_eh() {
    __shared__ __half As[64 * 72];
    __shared__ __half Bs[64 * 136];
    const int tid = threadIdx.x;
    const int warp = tid >> 5;
    const int wm = warp >> 2, wn = warp & 3;
    const int n0 = blockIdx.x * 128, m0 = blockIdx.y * 64;
    wmma::fragment<wmma::accumulator, 16, 16, 16, float> acc[2][2];
#pragma unroll
    for (int i = 0; i < 2; i++)
#pragma unroll
        for (int j = 0; j < 2; j++) wmma::fill_fragment(acc[i][j], 0.0f);
    for (int kt = 0; kt < 512; kt += 64) {
#pragma unroll
        for (int j = 0; j < 2; j++) {
            int u = tid + j * 256;
            int row = u >> 3, seg = u & 7;
            *(uint4*)&As[row * 72 + seg * 8] =
                *(const uint4*)(g_h1allh + (m0 + row) * 512 + kt + seg * 8);
        }
#pragma unroll
        for (int j = 0; j < 4; j++) {
            int u = tid + j * 256;
            int row = u >> 4, seg = u & 15;
            *(uint4*)&Bs[row * 136 + seg * 8] =
                *(const uint4*)(g_elwTh + (kt + row) * 256 + n0 + seg * 8);
        }
        __syncthreads();
#pragma unroll
        for (int kf = 0; kf < 4; kf++) {
            wmma::fragment<wmma::matrix_a, 16, 16, 16, __half, wmma::row_major> af[2];
            wmma::fragment<wmma::matrix_b, 16, 16, 16, __half, wmma::row_major> bf[2];
#pragma unroll
            for (int i = 0; i < 2; i++)
                wmma::load_matrix_sync(af[i], &As[(wm * 32 + i * 16) * 72 + kf * 16], 72);
#pragma unroll
            for (int j = 0; j < 2; j++)
                wmma::load_matrix_sync(bf[j], &Bs[(kf * 16) * 136 + wn * 32 + j * 16], 136);
#pragma unroll
            for (int i = 0; i < 2; i++)
#pragma unroll
                for (int j = 0; j < 2; j++)
                    wmma::mma_sync(acc[i][j], af[i], bf[j], acc[i][j]);
        }
        __syncthreads();
    }
#pragma unroll
    for (int i = 0; i < 2; i++)
#pragma unroll
        for (int j = 0; j < 2; j++)
            wmma::store_matrix_sync(g_eh + (m0 + wm * 32 + i * 16) * 256 + n0 + wn * 32 + j * 16,
                                    acc[i][j], 256, wmma::mem_row_major);
}

// ---------------- epilogue: scores + softmax (8 timesteps per block) ----------------
__global__ __launch_bounds__(256) void k_scores(const float* __restrict__ elb,
                                                const float* __restrict__ efb,
                                                const float* __restrict__ aw,
                                                const float* __restrict__ ab,
                                                float* __restrict__ out) {
    const int tg = blockIdx.x, b = blockIdx.y;
    const int nt = (tg < 3) ? 8 : 7;
    const int tid = threadIdx.x;
    __shared__ float ehs[8 * 256], aws[256];
    __shared__ float red[8], fin;
    const float bias = elb[tid] + efb[tid];
    for (int j = 0; j < 8; j++)
        ehs[j * 256 + tid] = (j < nt) ? g_eh[((tg * 8 + j) * 64 + b) * 256 + tid] + bias : 0.0f;
    aws[tid] = aw[tid];
    __syncthreads();

    float sc[8];
#pragma unroll
    for (int j = 0; j < 8; j++) sc[j] = ab[0];
    const float* ef = g_efmap + b * 65536 + tid;
#pragma unroll 2
    for (int a = 0; a < 256; a++) {
        float e = ef[a * 256];
        float w = aws[a];
#pragma unroll
        for (int j = 0; j < 8; j++)
            sc[j] += w * tanh_fast(ehs[j * 256 + a] + e);
    }

    const int wp = tid >> 5, lane = tid & 31;
    for (int j = 0; j < nt; j++) {
        float m = sc[j];
#pragma unroll
        for (int o = 16; o; o >>= 1) m = fmaxf(m, __shfl_xor_sync(0xffffffffu, m, o));
        if (lane == 0) red[wp] = m;
        __syncthreads();
        if (tid == 0) {
            float v = red[0];
#pragma unroll
            for (int i = 1; i < 8; i++) v = fmaxf(v, red[i]);
            fin = v;
        }
        __syncthreads();
        float e = expf(sc[j] - fin);
        float s = e;
#pragma unroll
        for (int o = 16; o; o >>= 1) s += __shfl_xor_sync(0xffffffffu, s, o);
        if (lane == 0) red[wp] = s;
        __syncthreads();
        if (tid == 0) {
            float v = 0;
#pragma unroll
            for (int i = 0; i < 8; i++) v += red[i];
            fin = v;
        }
        __syncthreads();
        out[194432 + (b * 31 + tg * 8 + j) * 256 + tid] = e / fin;
        __syncthreads();
    }
}

// ---------------- epilogue: glimpse (exact fp32 out + half copy for fc) ----------------
__global__ __launch_bounds__(128) void k_glimpse(float* __restrict__ out) {
    __shared__ float ms[16 * 256];
    const int th = blockIdx.x, b = blockIdx.y;
    const int tid = threadIdx.x;
    const int nt = (th == 0) ? 16 : 15;
    for (int i = tid; i < 16 * 256; i += 128) {
        int tt = i >> 8;
        ms[i] = (tt < nt) ? out[194432 + (b * 31 + th * 16 + tt) * 256 + (i & 255)] : 0.0f;
    }
    __syncthreads();
    const int c = tid * 4;
    float4 acc[16];
#pragma unroll
    for (int tt = 0; tt < 16; tt++) acc[tt] = make_float4(0.f, 0.f, 0.f, 0.f);
    const float* fp = g_fmapT + b * 131072 + c;
#pragma unroll 4
    for (int hw = 0; hw < 256; hw++) {
        float4 f = *(const float4*)(fp + hw * 512);
#pragma unroll
        for (int tt = 0; tt < 16; tt++) {
            float m = ms[tt * 256 + hw];
            acc[tt].x += f.x * m; acc[tt].y += f.y * m;
            acc[tt].z += f.z * m; acc[tt].w += f.w * m;
        }
    }
#pragma unroll
    for (int tt = 0; tt < 16; tt++)
        if (tt < nt) {
            int row = b * 31 + th * 16 + tt;
            *(float4*)&out[702336 + row * 512 + c] = acc[tt];
            __half2* gh = (__half2*)&g_gh[row * 512 + c];
            gh[0] = __floats2half2_rn(acc[tt].x, acc[tt].y);
            gh[1] = __floats2half2_rn(acc[tt].z, acc[tt].w);
        }
}

// ---------------- epilogue: fc logits (fp16). grid 31 (per t) ----------------
__global__ __launch_bounds__(256) void k_fc(const float* __restrict__ fcb,
                                            float* __restrict__ out) {
    __shared__ __half As[64 * 72];
    __shared__ __half Bs[64 * 136];
    __shared__ float Cs[64 * 128];
    const int t = blockIdx.x;
    const int tid = threadIdx.x;
    const int warp = tid >> 5;
    const int wm = warp >> 2, wn = warp & 3;
    wmma::fragment<wmma::accumulator, 16, 16, 16, float> acc[2][2];
#pragma unroll
    for (int i = 0; i < 2; i++)
#pragma unroll
        for (int j = 0; j < 2; j++) wmma::fill_fragment(acc[i][j], 0.0f);
    for (int kt = 0; kt < 1024; kt += 64) {
#pragma unroll
        for (int j = 0; j < 2; j++) {
            int u = tid + j * 256;
            int row = u >> 3, seg = u & 7;
            const __half* src = (kt < 512)
                ? (g_h1allh + (t * 64 + row) * 512 + kt + seg * 8)
                : (g_gh + (row * 31 + t) * 512 + (kt - 512) + seg * 8);
            *(uint4*)&As[row * 72 + seg * 8] = *(const uint4*)src;
        }
#pragma unroll
        for (int j = 0; j < 4; j++) {
            int u = tid + j * 256;
            int row = u >> 4, seg = u & 15;
            *(uint4*)&Bs[row * 136 + seg * 8] =
                *(const uint4*)(g_fcTph + (kt + row) * 128 + seg * 8);
        }
        __syncthreads();
#pragma unroll
        for (int kf = 0; kf < 4; kf++) {
            wmma::fragment<wmma::matrix_a, 16, 16, 16, __half, wmma::row_major> af[2];
            wmma::fragment<wmma::matrix_b, 16, 16, 16, __half, wmma::row_major> bf[2];
#pragma unroll
            for (int i = 0; i < 2; i++)
                wmma::load_matrix_sync(af[i], &As[(wm * 32 + i * 16) * 72 + kf * 16], 72);
#pragma unroll
            for (int j = 0; j < 2; j++)
                wmma::load_matrix_sync(bf[j], &Bs[(kf * 16) * 136 + wn * 32 + j * 16], 136);
#pragma unroll
            for (int i = 0; i < 2; i++)
#pragma unroll
                for (int j = 0; j < 2; j++)
                    wmma::mma_sync(acc[i][j], af[i], bf[j], acc[i][j]);
        }
        __syncthreads();
    }
#pragma unroll
    for (int i = 0; i < 2; i++)
#pragma unroll
        for (int j = 0; j < 2; j++)
            wmma::store_matrix_sync(&Cs[(wm * 32 + i * 16) * 128 + wn * 32 + j * 16],
                                    acc[i][j], 128, wmma::mem_row_major);
    __syncthreads();
    for (int i = tid; i < 64 * 98; i += 256) {
        int m = i / 98, j = i % 98;
        out[(m * 31 + t) * 98 + j] = Cs[m * 128 + j] + fcb[j];
    }
}

// ---------------- launch ----------------
extern "C" void kernel_launch(void* const* d_in, const int* in_sizes, int n_in,
                              void* d_out, int out_size) {
    const float* fmap   = (const float*)d_in[0];
    const float* h0     = (const float*)d_in[1];
    const float* c0     = (const float*)d_in[2];
    const int*   target = (const int*)d_in[3];
    const float* emb    = (const float*)d_in[5];
    const float* Wih0   = (const float*)d_in[6];
    const float* Whh0   = (const float*)d_in[7];
    const float* bih0   = (const float*)d_in[8];
    const float* bhh0   = (const float*)d_in[9];
    const float* Wih1   = (const float*)d_in[10];
    const float* Whh1   = (const float*)d_in[11];
    const float* bih1   = (const float*)d_in[12];
    const float* bhh1   = (const float*)d_in[13];
    const float* elw    = (const float*)d_in[14];
    const float* elb    = (const float*)d_in[15];
    const float* efw    = (const float*)d_in[16];
    const float* efb    = (const float*)d_in[17];
    const float* aw     = (const float*)d_in[18];
    const float* ab     = (const float*)d_in[19];
    const float* fcw    = (const float*)d_in[20];
    const float* fcb    = (const float*)d_in[21];
    float* out = (float*)d_out;

    const int SMEM_STEPS = 132096 + 24576 + 49152 + 16384;  // 222208
    const int SMEM_CONV  = 2 * CONV_BUF * 2;                // 108544
    static int configured = 0;
    if (!configured) {
        cudaFuncSetAttribute(k_steps, cudaFuncAttributeMaxDynamicSharedMemorySize, SMEM_STEPS);
        cudaFuncSetAttribute(k_conv, cudaFuncAttributeMaxDynamicSharedMemorySize, SMEM_CONV);
        configured = 1;
    }

    k_wtrans<<<dim3(2048, 3), 256>>>(Whh0, Wih1, Whh1, Wih0);
    k_ctrans<<<dim3(8, 16), 256>>>(efw);
    k_small<<<128, 256>>>(elw, fcw, bih0, bhh0, bih1, bhh1);
    k_fmapT<<<dim3(128, 64), 256>>>(fmap);
    k_init2<<<(1984 * 256 + 131072 + 255) / 256, 256>>>(h0, c0, emb, target);
    k_preemb<<<dim3(16, 31), 256>>>();
    k_conv<<<dim3(2, 64), 256, SMEM_CONV>>>();
    k_steps<<<GBLK, 256, SMEM_STEPS>>>();
    k_eh<<<dim3(2, 31), 256>>>();
    k_scores<<<dim3(4, 64), 256>>>(elb, efb, aw, ab, out);
    k_glimpse<<<dim3(2, 64), 128>>>(out);
    k_fc<<<31, 256>>>(fcb, out);
}